// round 1
// baseline (speedup 1.0000x reference)
#include <cuda_runtime.h>
#include <math.h>

#define BB   4
#define CC   256
#define LL   2048
#define HH   8
#define DD   64
#define HID  512
#define MQKV 1536

// Scratch (allocation-free rule: __device__ globals)
__device__ float g_qkv[(size_t)BB * MQKV * LL];   // 48 MB: rows 0..511 = q*scale, 512..1023 = k, 1024..1535 = v
__device__ float g_att[(size_t)BB * HID * LL];    // 16 MB: attention output, [b, (h d), l]

// ---------------------------------------------------------------------------
// Generic batched GEMM: Y[b] = W (M x K) * X[b] (K x N)  (+ optional bias,
// optional 0.125 scale applied to rows < scaleRows).
// Tiles: 64x64x16, block 16x16 threads, 4x4 register micro-tile per thread.
// M % 64 == 0, N % 64 == 0, K % 16 == 0 required (true for all our shapes).
// ---------------------------------------------------------------------------
__global__ void gemm_kernel(const float* __restrict__ W,
                            const float* __restrict__ X,
                            float*       __restrict__ Y,
                            const float* __restrict__ bias,
                            int M, int K, int N, int scaleRows)
{
    __shared__ float As[64][17];
    __shared__ float Bs[16][65];

    const int b  = blockIdx.z;
    const int m0 = blockIdx.y * 64;
    const int n0 = blockIdx.x * 64;
    const float* Xb = X + (size_t)b * K * N;
    float*       Yb = Y + (size_t)b * M * N;

    const int tx = threadIdx.x, ty = threadIdx.y;
    const int tid = ty * 16 + tx;

    float acc[4][4] = {};

    for (int k0 = 0; k0 < K; k0 += 16) {
        #pragma unroll
        for (int e = 0; e < 4; e++) {
            int idx = tid + e * 256;
            int m = idx >> 4, k = idx & 15;
            As[m][k] = W[(size_t)(m0 + m) * K + k0 + k];
        }
        #pragma unroll
        for (int e = 0; e < 4; e++) {
            int idx = tid + e * 256;
            int k = idx >> 6, n = idx & 63;
            Bs[k][n] = Xb[(size_t)(k0 + k) * N + n0 + n];
        }
        __syncthreads();

        #pragma unroll
        for (int kk = 0; kk < 16; kk++) {
            float ra[4], rb[4];
            #pragma unroll
            for (int i = 0; i < 4; i++) ra[i] = As[ty * 4 + i][kk];
            #pragma unroll
            for (int j = 0; j < 4; j++) rb[j] = Bs[kk][tx * 4 + j];
            #pragma unroll
            for (int i = 0; i < 4; i++)
                #pragma unroll
                for (int j = 0; j < 4; j++)
                    acc[i][j] = fmaf(ra[i], rb[j], acc[i][j]);
        }
        __syncthreads();
    }

    #pragma unroll
    for (int i = 0; i < 4; i++) {
        int m = m0 + ty * 4 + i;
        float sc = (m < scaleRows) ? 0.125f : 1.0f;
        float bv = bias ? bias[m] : 0.0f;
        #pragma unroll
        for (int j = 0; j < 4; j++)
            Yb[(size_t)m * N + n0 + tx * 4 + j] = acc[i][j] * sc + bv;
    }
}

// ---------------------------------------------------------------------------
// Flash attention: per CTA one (b,h) and one 64-query tile.
// Q/K/V live in g_qkv as [b, row, l] with row = {h*64+d | 512+h*64+d | 1024+h*64+d}.
// Online softmax over 32 key tiles of 64. Output written to g_att[b, h*64+d, l].
// Dynamic smem: Qs(64x65) Ks(64x65) Vs(64x65) Ps(64x65) = 66560 B.
// ---------------------------------------------------------------------------
__global__ void attn_kernel()
{
    extern __shared__ float sm[];
    float (*Qs)[65] = (float(*)[65])(sm);                // [i][d]
    float (*Ks)[65] = (float(*)[65])(sm + 64 * 65);      // [d][j]
    float (*Vs)[65] = (float(*)[65])(sm + 2 * 64 * 65);  // [j][d]
    float (*Ps)[65] = (float(*)[65])(sm + 3 * 64 * 65);  // [i][j]

    const int bh = blockIdx.y;
    const int b = bh >> 3, h = bh & 7;
    const int i0 = blockIdx.x * 64;

    const float* qb = g_qkv + ((size_t)b * MQKV +            h * DD) * LL;
    const float* kb = g_qkv + ((size_t)b * MQKV + HID      + h * DD) * LL;
    const float* vb = g_qkv + ((size_t)b * MQKV + 2 * HID  + h * DD) * LL;

    const int tx = threadIdx.x, ty = threadIdx.y;
    const int tid = ty * 16 + tx;

    // Load Q tile transposed: Qs[i][d]  (global read coalesced along i)
    #pragma unroll
    for (int e = 0; e < 16; e++) {
        int idx = tid + e * 256;
        int d = idx >> 6, i = idx & 63;
        Qs[i][d] = qb[(size_t)d * LL + i0 + i];
    }

    float m_i[4], l_i[4], O[4][4] = {};
    #pragma unroll
    for (int i = 0; i < 4; i++) { m_i[i] = -INFINITY; l_i[i] = 0.f; }

    for (int j0 = 0; j0 < LL; j0 += 64) {
        // Load K tile as [d][j], V tile transposed to [j][d]
        #pragma unroll
        for (int e = 0; e < 16; e++) {
            int idx = tid + e * 256;
            int d = idx >> 6, j = idx & 63;
            Ks[d][j] = kb[(size_t)d * LL + j0 + j];
            Vs[j][d] = vb[(size_t)d * LL + j0 + j];
        }
        __syncthreads();

        // S = Q^T K  (per-thread 4x4 of the 64x64 tile)
        float s[4][4] = {};
        #pragma unroll
        for (int d = 0; d < 64; d++) {
            float ra[4], rb[4];
            #pragma unroll
            for (int i = 0; i < 4; i++) ra[i] = Qs[ty * 4 + i][d];
            #pragma unroll
            for (int j = 0; j < 4; j++) rb[j] = Ks[d][tx * 4 + j];
            #pragma unroll
            for (int i = 0; i < 4; i++)
                #pragma unroll
                for (int j = 0; j < 4; j++)
                    s[i][j] = fmaf(ra[i], rb[j], s[i][j]);
        }

        // Online softmax update. Row i is shared by the 16 lanes with equal ty
        // (lanes k..k+15 within the warp), so xor-shuffles 1..8 stay in-group.
        #pragma unroll
        for (int i = 0; i < 4; i++) {
            float mx = s[i][0];
            #pragma unroll
            for (int j = 1; j < 4; j++) mx = fmaxf(mx, s[i][j]);
            #pragma unroll
            for (int off = 8; off >= 1; off >>= 1)
                mx = fmaxf(mx, __shfl_xor_sync(0xffffffffu, mx, off));

            float m_new = fmaxf(m_i[i], mx);
            float alpha = __expf(m_i[i] - m_new);
            float rs = 0.f;
            #pragma unroll
            for (int j = 0; j < 4; j++) {
                float p = __expf(s[i][j] - m_new);
                s[i][j] = p;
                rs += p;
            }
            #pragma unroll
            for (int off = 8; off >= 1; off >>= 1)
                rs += __shfl_xor_sync(0xffffffffu, rs, off);

            l_i[i] = l_i[i] * alpha + rs;
            m_i[i] = m_new;
            #pragma unroll
            for (int j = 0; j < 4; j++) O[i][j] *= alpha;
        }

        // Stage P to shared for the PV matmul (column ownership changes)
        #pragma unroll
        for (int i = 0; i < 4; i++)
            #pragma unroll
            for (int j = 0; j < 4; j++)
                Ps[ty * 4 + i][tx * 4 + j] = s[i][j];
        __syncthreads();

        // O[i][d] += sum_j P[i][j] * V[j][d]
        #pragma unroll
        for (int j = 0; j < 64; j++) {
            float pa[4], vv[4];
            #pragma unroll
            for (int i = 0; i < 4; i++) pa[i] = Ps[ty * 4 + i][j];
            #pragma unroll
            for (int d = 0; d < 4; d++) vv[d] = Vs[j][tx * 4 + d];
            #pragma unroll
            for (int i = 0; i < 4; i++)
                #pragma unroll
                for (int d = 0; d < 4; d++)
                    O[i][d] = fmaf(pa[i], vv[d], O[i][d]);
        }
        __syncthreads();  // protect Ks/Vs/Ps before next tile
    }

    // Normalize and write out transposed: g_att[b, h*64+d, i0+i]
    float* ob = g_att + ((size_t)b * HID + h * DD) * LL;
    #pragma unroll
    for (int i = 0; i < 4; i++) {
        float inv = 1.0f / l_i[i];
        #pragma unroll
        for (int d = 0; d < 4; d++)
            ob[(size_t)(tx * 4 + d) * LL + i0 + ty * 4 + i] = O[i][d] * inv;
    }
}

// ---------------------------------------------------------------------------
extern "C" void kernel_launch(void* const* d_in, const int* in_sizes, int n_in,
                              void* d_out, int out_size)
{
    const float* x     = (const float*)d_in[0];  // [4,256,2048]
    const float* w_qkv = (const float*)d_in[1];  // [1536,256]
    const float* w_out = (const float*)d_in[2];  // [256,512]
    const float* b_out = (const float*)d_in[3];  // [256]
    float* out = (float*)d_out;                  // [4,256,2048]

    float* qkv_ptr = nullptr;
    float* att_ptr = nullptr;
    cudaGetSymbolAddress((void**)&qkv_ptr, g_qkv);
    cudaGetSymbolAddress((void**)&att_ptr, g_att);

    const int ATTN_SMEM = 4 * 64 * 65 * (int)sizeof(float);  // 66560 B
    cudaFuncSetAttribute(attn_kernel, cudaFuncAttributeMaxDynamicSharedMemorySize, ATTN_SMEM);

    dim3 blk(16, 16);

    // 1) QKV projection: [1536,256] x [4][256,2048], q rows scaled by 0.125
    gemm_kernel<<<dim3(LL / 64, MQKV / 64, BB), blk>>>(
        w_qkv, x, qkv_ptr, nullptr, MQKV, CC, LL, HID);

    // 2) Flash attention: grid = (query tiles, b*h)
    attn_kernel<<<dim3(LL / 64, BB * HH), blk, ATTN_SMEM>>>();

    // 3) Output projection + bias: [256,512] x [4][512,2048]
    gemm_kernel<<<dim3(LL / 64, CC / 64, BB), blk>>>(
        w_out, att_ptr, out, b_out, CC, HID, LL, 0);
}

// round 2
// speedup vs baseline: 1.2737x; 1.2737x over previous
#include <cuda_runtime.h>
#include <math.h>

#define BB   4
#define CC   256
#define LL   2048
#define HH   8
#define DD   64
#define HID  512
#define MQKV 1536
#define PAD  68   // smem row pitch (floats): 68*4=272B, 16B-aligned rows

// Scratch (allocation-free rule: __device__ globals)
__device__ float g_qkv[(size_t)BB * MQKV * LL];   // [b, row, l]; rows 0..511=q*0.125, 512..1023=k, 1024..1535=v
__device__ float g_att[(size_t)BB * LL * HID];    // attention out, [b, l, (h d)]  (i-major for coalesced writes)

// ---------------------------------------------------------------------------
// Batched GEMM: Y[b] = W (M x K) * X[b] (K x N) (+bias, +0.125 on rows<scaleRows)
// TRANSB=false: X is [K][N] row-major. TRANSB=true: X is [N][K] row-major.
// Tiles 64x128x16, 256 threads, 4x8 micro-tile, all-LDS.128 inner loop.
// Requires M%64==0, N%128==0, K%16==0.
// ---------------------------------------------------------------------------
template<bool TRANSB>
__global__ void gemm_kernel(const float* __restrict__ W,
                            const float* __restrict__ X,
                            float*       __restrict__ Y,
                            const float* __restrict__ bias,
                            int M, int K, int N, int scaleRows)
{
    __shared__ float As[16][PAD];   // [k][m]
    __shared__ float Bs[16][132];   // [k][n], pitch 132 (16B-aligned rows)

    const int b  = blockIdx.z;
    const int m0 = blockIdx.y * 64;
    const int n0 = blockIdx.x * 128;
    const float* Xb = X + (size_t)b * K * N;
    float*       Yb = Y + (size_t)b * M * N;

    const int tid = threadIdx.x;
    const int tx = tid & 15, ty = tid >> 4;

    float acc[4][8] = {};

    for (int k0 = 0; k0 < K; k0 += 16) {
        // Fill As[k][m] (transposed): each thread one float4 along k
        {
            int m = tid >> 2, kq = (tid & 3) * 4;
            float4 w4 = *(const float4*)(W + (size_t)(m0 + m) * K + k0 + kq);
            As[kq + 0][m] = w4.x; As[kq + 1][m] = w4.y;
            As[kq + 2][m] = w4.z; As[kq + 3][m] = w4.w;
        }
        // Fill Bs[k][n]
        if (!TRANSB) {
            #pragma unroll
            for (int e = 0; e < 2; e++) {
                int f = tid + e * 256;
                int k = f >> 5, nq = (f & 31) * 4;
                *(float4*)(&Bs[k][nq]) =
                    *(const float4*)(Xb + (size_t)(k0 + k) * N + n0 + nq);
            }
        } else {
            int nb = tid >> 2, kq = (tid & 3) * 4;
            #pragma unroll
            for (int e = 0; e < 2; e++) {
                int nn = nb + e * 64;
                float4 x4 = *(const float4*)(Xb + (size_t)(n0 + nn) * K + k0 + kq);
                Bs[kq + 0][nn] = x4.x; Bs[kq + 1][nn] = x4.y;
                Bs[kq + 2][nn] = x4.z; Bs[kq + 3][nn] = x4.w;
            }
        }
        __syncthreads();

        #pragma unroll
        for (int kk = 0; kk < 16; kk++) {
            float4 ra  = *(float4*)(&As[kk][ty * 4]);
            float4 rb0 = *(float4*)(&Bs[kk][tx * 4]);
            float4 rb1 = *(float4*)(&Bs[kk][64 + tx * 4]);
            float a[4] = {ra.x, ra.y, ra.z, ra.w};
            float b0[4] = {rb0.x, rb0.y, rb0.z, rb0.w};
            float b1[4] = {rb1.x, rb1.y, rb1.z, rb1.w};
            #pragma unroll
            for (int i = 0; i < 4; i++) {
                #pragma unroll
                for (int j = 0; j < 4; j++) {
                    acc[i][j]     = fmaf(a[i], b0[j], acc[i][j]);
                    acc[i][4 + j] = fmaf(a[i], b1[j], acc[i][4 + j]);
                }
            }
        }
        __syncthreads();
    }

    #pragma unroll
    for (int i = 0; i < 4; i++) {
        int m = m0 + ty * 4 + i;
        float sc = (m < scaleRows) ? 0.125f : 1.0f;
        float bv = bias ? bias[m] : 0.0f;
        float4 o0, o1;
        o0.x = acc[i][0] * sc + bv; o0.y = acc[i][1] * sc + bv;
        o0.z = acc[i][2] * sc + bv; o0.w = acc[i][3] * sc + bv;
        o1.x = acc[i][4] * sc + bv; o1.y = acc[i][5] * sc + bv;
        o1.z = acc[i][6] * sc + bv; o1.w = acc[i][7] * sc + bv;
        *(float4*)(Yb + (size_t)m * N + n0 + tx * 4)      = o0;
        *(float4*)(Yb + (size_t)m * N + n0 + 64 + tx * 4) = o1;
    }
}

// ---------------------------------------------------------------------------
// Flash attention, fp32, all-vectorized smem traffic.
// CTA: one (b,h), one 64-query tile; loops 32 key tiles of 64.
// Layouts: Qs/Ks/Vd stored [d][·] (as global), Ps [i][j]. PV is dot-product
// over contiguous j so V never needs transposing.
// Smem: 4 * 64 * 68 * 4 = 69632 B.
// ---------------------------------------------------------------------------
__global__ void attn_kernel()
{
    extern __shared__ float sm[];
    float* Qs = sm;                 // [d][i]
    float* Ks = sm + 64 * PAD;      // [d][j]
    float* Vd = sm + 2 * 64 * PAD;  // [d][j]
    float* Ps = sm + 3 * 64 * PAD;  // [i][j]

    const int bh = blockIdx.y;
    const int b = bh >> 3, h = bh & 7;
    const int i0 = blockIdx.x * 64;

    const float* qb = g_qkv + ((size_t)b * MQKV +           h * DD) * LL;
    const float* kb = g_qkv + ((size_t)b * MQKV + HID     + h * DD) * LL;
    const float* vb = g_qkv + ((size_t)b * MQKV + 2 * HID + h * DD) * LL;

    const int tid = threadIdx.x;
    const int tx = tid & 15, ty = tid >> 4;

    // Load Q tile: Qs[d][i], straight from global (coalesced float4)
    #pragma unroll
    for (int e = 0; e < 4; e++) {
        int f = tid + e * 256;
        int d = f >> 4, iq = (f & 15) * 4;
        *(float4*)(Qs + d * PAD + iq) =
            *(const float4*)(qb + (size_t)d * LL + i0 + iq);
    }

    float m_i[4], l_i[4], O[4][4] = {};
    #pragma unroll
    for (int i = 0; i < 4; i++) { m_i[i] = -INFINITY; l_i[i] = 0.f; }

    for (int j0 = 0; j0 < LL; j0 += 64) {
        // Load K and V tiles as [d][j]
        #pragma unroll
        for (int e = 0; e < 4; e++) {
            int f = tid + e * 256;
            int d = f >> 4, jq = (f & 15) * 4;
            *(float4*)(Ks + d * PAD + jq) =
                *(const float4*)(kb + (size_t)d * LL + j0 + jq);
            *(float4*)(Vd + d * PAD + jq) =
                *(const float4*)(vb + (size_t)d * LL + j0 + jq);
        }
        __syncthreads();

        // S = Q^T K : thread owns i=ty*4.., j=tx*4..   (2 LDS.128 / 16 FMA)
        float s[4][4] = {};
        #pragma unroll
        for (int d = 0; d < 64; d++) {
            float4 ra = *(float4*)(Qs + d * PAD + ty * 4);
            float4 rb = *(float4*)(Ks + d * PAD + tx * 4);
            float a[4] = {ra.x, ra.y, ra.z, ra.w};
            float bq[4] = {rb.x, rb.y, rb.z, rb.w};
            #pragma unroll
            for (int i = 0; i < 4; i++)
                #pragma unroll
                for (int j = 0; j < 4; j++)
                    s[i][j] = fmaf(a[i], bq[j], s[i][j]);
        }

        // Online softmax (rows shared by 16-lane half-warps: xor 1..8)
        #pragma unroll
        for (int i = 0; i < 4; i++) {
            float mx = s[i][0];
            #pragma unroll
            for (int j = 1; j < 4; j++) mx = fmaxf(mx, s[i][j]);
            #pragma unroll
            for (int off = 8; off >= 1; off >>= 1)
                mx = fmaxf(mx, __shfl_xor_sync(0xffffffffu, mx, off));

            float m_new = fmaxf(m_i[i], mx);
            float alpha = __expf(m_i[i] - m_new);
            float rs = 0.f;
            #pragma unroll
            for (int j = 0; j < 4; j++) {
                float p = __expf(s[i][j] - m_new);
                s[i][j] = p;
                rs += p;
            }
            #pragma unroll
            for (int off = 8; off >= 1; off >>= 1)
                rs += __shfl_xor_sync(0xffffffffu, rs, off);

            l_i[i] = l_i[i] * alpha + rs;
            m_i[i] = m_new;
            #pragma unroll
            for (int j = 0; j < 4; j++) O[i][j] *= alpha;
        }

        // Stage P (vectorized store, thread owns contiguous j)
        #pragma unroll
        for (int i = 0; i < 4; i++) {
            float4 p4;
            p4.x = s[i][0]; p4.y = s[i][1]; p4.z = s[i][2]; p4.w = s[i][3];
            *(float4*)(Ps + (ty * 4 + i) * PAD + tx * 4) = p4;
        }
        __syncthreads();

        // O[i][d] += sum_j P[i][j] * V[d][j]   — dot products over contig j.
        // Thread owns d = tx + 16*k (strided).  8 LDS.128 / 64 FMA per chunk.
        #pragma unroll
        for (int jc = 0; jc < 64; jc += 4) {
            float4 pa[4], vv[4];
            #pragma unroll
            for (int i = 0; i < 4; i++)
                pa[i] = *(float4*)(Ps + (ty * 4 + i) * PAD + jc);
            #pragma unroll
            for (int k = 0; k < 4; k++)
                vv[k] = *(float4*)(Vd + (tx + 16 * k) * PAD + jc);
            #pragma unroll
            for (int i = 0; i < 4; i++) {
                #pragma unroll
                for (int k = 0; k < 4; k++) {
                    O[i][k] = fmaf(pa[i].x, vv[k].x, O[i][k]);
                    O[i][k] = fmaf(pa[i].y, vv[k].y, O[i][k]);
                    O[i][k] = fmaf(pa[i].z, vv[k].z, O[i][k]);
                    O[i][k] = fmaf(pa[i].w, vv[k].w, O[i][k]);
                }
            }
        }
        __syncthreads();  // protect Ks/Vd/Ps before next tile
    }

    // Normalize, write g_att[b, l, hid] (coalesced)
    float* ob = g_att + ((size_t)b * LL + i0) * HID + h * DD;
    #pragma unroll
    for (int i = 0; i < 4; i++) {
        float inv = 1.0f / l_i[i];
        #pragma unroll
        for (int k = 0; k < 4; k++)
            ob[(size_t)(ty * 4 + i) * HID + tx + 16 * k] = O[i][k] * inv;
    }
}

// ---------------------------------------------------------------------------
extern "C" void kernel_launch(void* const* d_in, const int* in_sizes, int n_in,
                              void* d_out, int out_size)
{
    const float* x     = (const float*)d_in[0];  // [4,256,2048]
    const float* w_qkv = (const float*)d_in[1];  // [1536,256]
    const float* w_out = (const float*)d_in[2];  // [256,512]
    const float* b_out = (const float*)d_in[3];  // [256]
    float* out = (float*)d_out;                  // [4,256,2048]

    float* qkv_ptr = nullptr;
    float* att_ptr = nullptr;
    cudaGetSymbolAddress((void**)&qkv_ptr, g_qkv);
    cudaGetSymbolAddress((void**)&att_ptr, g_att);

    const int ATTN_SMEM = 4 * 64 * PAD * (int)sizeof(float);  // 69632 B
    cudaFuncSetAttribute(attn_kernel, cudaFuncAttributeMaxDynamicSharedMemorySize, ATTN_SMEM);

    // 1) QKV projection: [1536,256] x [4][256,2048]; q rows scaled by 0.125
    gemm_kernel<false><<<dim3(LL / 128, MQKV / 64, BB), 256>>>(
        w_qkv, x, qkv_ptr, nullptr, MQKV, CC, LL, HID);

    // 2) Flash attention
    attn_kernel<<<dim3(LL / 64, BB * HH), 256, ATTN_SMEM>>>();

    // 3) Output projection + bias: [256,512] x att^T ([4][2048,512] stored i-major)
    gemm_kernel<true><<<dim3(LL / 128, CC / 64, BB), 256>>>(
        w_out, att_ptr, out, b_out, CC, HID, LL, 0);
}

// round 4
// speedup vs baseline: 2.6989x; 2.1190x over previous
#include <cuda_runtime.h>
#include <cuda_bf16.h>
#include <math.h>
#include <stdint.h>

#define BB   4
#define CC   256
#define LL   2048
#define HH   8
#define DD   64
#define HID  512
#define MQKV 1536

// ---------------- scratch (allocation-free rule: __device__ globals) -------
__device__ __align__(16) __nv_bfloat16 g_q_hi[(size_t)BB * LL * HID];  // [b][l][512]
__device__ __align__(16) __nv_bfloat16 g_q_lo[(size_t)BB * LL * HID];
__device__ __align__(16) __nv_bfloat16 g_k_hi[(size_t)BB * LL * HID];
__device__ __align__(16) __nv_bfloat16 g_k_lo[(size_t)BB * LL * HID];
__device__ __align__(16) __nv_bfloat16 g_v_hi[(size_t)BB * HID * LL]; // [b][512][l]
__device__ __align__(16) __nv_bfloat16 g_v_lo[(size_t)BB * HID * LL];
__device__ __align__(16) float         g_att[(size_t)BB * LL * HID];  // [b][l][512]

#define SWZ(x) ((x) ^ (((x) >> 3) & 0x70))

// ---------------- warp-MMA helpers (baseline sm_80+ features) --------------
__device__ __forceinline__ uint32_t smem_u32(const void* p) {
    uint32_t a;
    asm("{ .reg .u64 t; cvta.to.shared.u64 t, %1; cvt.u32.u64 %0, t; }"
        : "=r"(a) : "l"(p));
    return a;
}
__device__ __forceinline__ void ldsm4(uint32_t& r0, uint32_t& r1, uint32_t& r2,
                                      uint32_t& r3, uint32_t a) {
    asm volatile("ldmatrix.sync.aligned.m8n8.x4.shared.b16 {%0,%1,%2,%3}, [%4];"
                 : "=r"(r0), "=r"(r1), "=r"(r2), "=r"(r3) : "r"(a));
}
__device__ __forceinline__ void mma16816(float* c, const uint32_t* a,
                                         uint32_t b0, uint32_t b1) {
    asm volatile("mma.sync.aligned.m16n8k16.row.col.f32.bf16.bf16.f32 "
                 "{%0,%1,%2,%3}, {%4,%5,%6,%7}, {%8,%9}, {%0,%1,%2,%3};"
                 : "+f"(c[0]), "+f"(c[1]), "+f"(c[2]), "+f"(c[3])
                 : "r"(a[0]), "r"(a[1]), "r"(a[2]), "r"(a[3]), "r"(b0), "r"(b1));
}
// pack two floats -> bf16x2 (p0 -> low half, p1 -> high half)
__device__ __forceinline__ uint32_t cvt2bf(float p0, float p1) {
    uint32_t r;
    asm("cvt.rn.bf16x2.f32 %0, %1, %2;" : "=r"(r) : "f"(p1), "f"(p0));
    return r;
}
// split pair into hi (bf16x2) + residual lo (bf16x2)
__device__ __forceinline__ void pack_pair(float p0, float p1,
                                          uint32_t& hi, uint32_t& lo) {
    hi = cvt2bf(p0, p1);
    float f0 = __uint_as_float(hi << 16);
    float f1 = __uint_as_float(hi & 0xffff0000u);
    lo = cvt2bf(p0 - f0, p1 - f1);
}
__device__ __forceinline__ void split_bf16(float x, __nv_bfloat16& h, __nv_bfloat16& l) {
    h = __float2bfloat16(x);
    l = __float2bfloat16(x - __bfloat162float(h));
}

// ---------------------------------------------------------------------------
// QKV GEMM: qkv = w_qkv (1536x256) * x[b] (256x2048); epilogue emits bf16
// hi/lo. q (rows 0..511, x0.125) / k (512..1023) -> [b][l][512]; v -> [b][512][l].
// ---------------------------------------------------------------------------
__global__ void qkv_gemm(const float* __restrict__ W, const float* __restrict__ X)
{
    __shared__ float As[16][68];
    __shared__ float Bs[16][132];

    const int b  = blockIdx.z;
    const int m0 = blockIdx.y * 64;
    const int n0 = blockIdx.x * 128;
    const float* Xb = X + (size_t)b * CC * LL;

    const int tid = threadIdx.x;
    const int tx = tid & 15, ty = tid >> 4;

    float acc[4][8] = {};

    for (int k0 = 0; k0 < CC; k0 += 16) {
        {
            int m = tid >> 2, kq = (tid & 3) * 4;
            float4 w4 = *(const float4*)(W + (size_t)(m0 + m) * CC + k0 + kq);
            As[kq + 0][m] = w4.x; As[kq + 1][m] = w4.y;
            As[kq + 2][m] = w4.z; As[kq + 3][m] = w4.w;
        }
        #pragma unroll
        for (int e = 0; e < 2; e++) {
            int f = tid + e * 256;
            int k = f >> 5, nq = (f & 31) * 4;
            *(float4*)(&Bs[k][nq]) = *(const float4*)(Xb + (size_t)(k0 + k) * LL + n0 + nq);
        }
        __syncthreads();

        #pragma unroll
        for (int kk = 0; kk < 16; kk++) {
            float4 ra  = *(float4*)(&As[kk][ty * 4]);
            float4 rb0 = *(float4*)(&Bs[kk][tx * 4]);
            float4 rb1 = *(float4*)(&Bs[kk][64 + tx * 4]);
            float a[4] = {ra.x, ra.y, ra.z, ra.w};
            float b0[4] = {rb0.x, rb0.y, rb0.z, rb0.w};
            float b1[4] = {rb1.x, rb1.y, rb1.z, rb1.w};
            #pragma unroll
            for (int i = 0; i < 4; i++)
                #pragma unroll
                for (int j = 0; j < 4; j++) {
                    acc[i][j]     = fmaf(a[i], b0[j], acc[i][j]);
                    acc[i][4 + j] = fmaf(a[i], b1[j], acc[i][4 + j]);
                }
        }
        __syncthreads();
    }

    const int seg = m0 >> 9;  // 0=q 1=k 2=v
    if (seg < 2) {
        __nv_bfloat16* ghi = seg == 0 ? g_q_hi : g_k_hi;
        __nv_bfloat16* glo = seg == 0 ? g_q_lo : g_k_lo;
        const float sc = seg == 0 ? 0.125f : 1.0f;
        const int chb = (m0 & 511) + ty * 4;
        #pragma unroll
        for (int jj = 0; jj < 8; jj++) {
            int n = n0 + (jj < 4 ? tx * 4 + jj : 64 + tx * 4 + (jj - 4));
            uint32_t h01 = 0, h23 = 0, l01 = 0, l23 = 0;
            #pragma unroll
            for (int i = 0; i < 4; i++) {
                __nv_bfloat16 h, l;
                split_bf16(acc[i][jj] * sc, h, l);
                uint32_t hb = __bfloat16_as_ushort(h), lb = __bfloat16_as_ushort(l);
                if (i < 2) { h01 |= hb << (16 * i); l01 |= lb << (16 * i); }
                else       { h23 |= hb << (16 * (i - 2)); l23 |= lb << (16 * (i - 2)); }
            }
            size_t base = ((size_t)b * LL + n) * HID + chb;
            *(uint2*)(ghi + base) = make_uint2(h01, h23);
            *(uint2*)(glo + base) = make_uint2(l01, l23);
        }
    } else {
        #pragma unroll
        for (int i = 0; i < 4; i++) {
            int row = (m0 - 1024) + ty * 4 + i;
            size_t base = ((size_t)b * HID + row) * LL;
            #pragma unroll
            for (int half = 0; half < 2; half++) {
                int n = n0 + half * 64 + tx * 4;
                uint32_t h01 = 0, h23 = 0, l01 = 0, l23 = 0;
                #pragma unroll
                for (int j = 0; j < 4; j++) {
                    __nv_bfloat16 h, l;
                    split_bf16(acc[i][half * 4 + j], h, l);
                    uint32_t hb = __bfloat16_as_ushort(h), lb = __bfloat16_as_ushort(l);
                    if (j < 2) { h01 |= hb << (16 * j); l01 |= lb << (16 * j); }
                    else       { h23 |= hb << (16 * (j - 2)); l23 |= lb << (16 * (j - 2)); }
                }
                *(uint2*)(g_v_hi + base + n) = make_uint2(h01, h23);
                *(uint2*)(g_v_lo + base + n) = make_uint2(l01, l23);
            }
        }
    }
}

// ---------------------------------------------------------------------------
// Flash attention on mma.sync (bf16, 3-pass hi/lo). CTA = one (b,h) x 128
// queries, 8 warps x 16 rows. 64-key tiles, K/V double-buffered via cp.async.
// smem: 2 bufs x (Khi|Klo|Vhi|Vlo, 8KB each) = 64KB. Q staged in buf1 once.
// ---------------------------------------------------------------------------
__global__ void __launch_bounds__(256, 1) attn_kernel()
{
    extern __shared__ __align__(1024) char smem[];
    const uint32_t sb = smem_u32(smem);
    const int tid = threadIdx.x;
    const int lane = tid & 31, w = tid >> 5;
    const int bh = blockIdx.y;
    const int b = bh >> 3, h = bh & 7;
    const int i0 = blockIdx.x * 128;

    const __nv_bfloat16* qh = g_q_hi + ((size_t)b * LL + i0) * HID + h * DD;
    const __nv_bfloat16* ql = g_q_lo + ((size_t)b * LL + i0) * HID + h * DD;
    const __nv_bfloat16* kh = g_k_hi + (size_t)b * LL * HID + h * DD;
    const __nv_bfloat16* kl = g_k_lo + (size_t)b * LL * HID + h * DD;
    const __nv_bfloat16* vh = g_v_hi + ((size_t)b * HID + h * DD) * LL;
    const __nv_bfloat16* vl = g_v_lo + ((size_t)b * HID + h * DD) * LL;

    // lane-constant swizzled ldmatrix offsets
    const int g = lane >> 3;
    const int rowB = ((g & 2) ? 8 : 0) + (lane & 7);
    const int bytB = (g & 1) * 16;
    const int rowA = lane & 15;
    const int bytA = (lane >> 4) * 16;
    uint32_t swzB[4], swzA[4];
    #pragma unroll
    for (int kk = 0; kk < 4; kk++) {
        swzB[kk] = SWZ((uint32_t)(rowB * 128 + bytB + kk * 32));
        swzA[kk] = SWZ((uint32_t)(rowA * 128 + bytA + kk * 32));
    }

    // cp.async one 64-key tile (4 x 8KB) into buffer (jt & 1)
    auto issue_tile = [&](int jt) {
        const int j0 = jt * 64;
        const uint32_t base = sb + ((jt & 1) ? 32768u : 0u);
        #pragma unroll
        for (int e = 0; e < 8; e++) {
            const int bufsel = e >> 1;
            const int wi = tid + (e & 1) * 256;     // 0..511
            const int row = wi >> 3, c = wi & 7;
            const uint32_t dst = base + bufsel * 8192 + SWZ((uint32_t)(row * 128 + c * 16));
            const __nv_bfloat16* src;
            if (bufsel == 0)      src = kh + (size_t)(j0 + row) * HID + c * 8;
            else if (bufsel == 1) src = kl + (size_t)(j0 + row) * HID + c * 8;
            else if (bufsel == 2) src = vh + (size_t)row * LL + j0 + c * 8;
            else                  src = vl + (size_t)row * LL + j0 + c * 8;
            asm volatile("cp.async.cg.shared.global [%0], [%1], 16;"
                         :: "r"(dst), "l"(src));
        }
        asm volatile("cp.async.commit_group;" ::: "memory");
    };

    issue_tile(0);   // prefetch tile 0 into buf0 (offset 0..32K)

    // ---- stage Q (hi @32K, lo @48K), extract register fragments ----
    #pragma unroll
    for (int e = 0; e < 4; e++) {
        int idx = tid + e * 256;           // 0..1023
        int row = idx >> 3, c = idx & 7;
        uint32_t sw = SWZ((uint32_t)(row * 128 + c * 16));
        *(uint4*)(smem + 32768 + sw) = *(const uint4*)(qh + (size_t)row * HID + c * 8);
        *(uint4*)(smem + 49152 + sw) = *(const uint4*)(ql + (size_t)row * HID + c * 8);
    }
    __syncthreads();
    uint32_t qfh[4][4], qfl[4][4];
    #pragma unroll
    for (int kk = 0; kk < 4; kk++) {
        ldsm4(qfh[kk][0], qfh[kk][1], qfh[kk][2], qfh[kk][3],
              sb + 32768u + ((uint32_t)w << 11) + swzA[kk]);
        ldsm4(qfl[kk][0], qfl[kk][1], qfl[kk][2], qfl[kk][3],
              sb + 49152u + ((uint32_t)w << 11) + swzA[kk]);
    }
    __syncthreads();   // Q smem free (becomes buf1)

    const float LOG2E = 1.4426950408889634f;
    float m0 = -INFINITY, m1 = -INFINITY, l0 = 0.f, l1 = 0.f;
    float O[8][4] = {};

    for (int t = 0; t < 32; t++) {
        asm volatile("cp.async.wait_group 0;" ::: "memory");
        __syncthreads();
        if (t + 1 < 32) issue_tile(t + 1);

        const uint32_t base = sb + ((t & 1) ? 32768u : 0u);
        const uint32_t kbh = base, kbl = base + 8192u;
        const uint32_t vbh = base + 16384u, vbl = base + 24576u;

        // ---- S = Q K^T (per warp: m16 x n64, 3-pass split) ----
        float s[8][4] = {};
        #pragma unroll
        for (int kk = 0; kk < 4; kk++) {
            #pragma unroll
            for (int jnp = 0; jnp < 4; jnp++) {
                uint32_t b0, b1, b2, b3, c0, c1, c2, c3;
                ldsm4(b0, b1, b2, b3, kbh + ((uint32_t)jnp << 11) + swzB[kk]);
                ldsm4(c0, c1, c2, c3, kbl + ((uint32_t)jnp << 11) + swzB[kk]);
                mma16816(s[2 * jnp],     qfh[kk], b0, b1);
                mma16816(s[2 * jnp],     qfl[kk], b0, b1);
                mma16816(s[2 * jnp],     qfh[kk], c0, c1);
                mma16816(s[2 * jnp + 1], qfh[kk], b2, b3);
                mma16816(s[2 * jnp + 1], qfl[kk], b2, b3);
                mma16816(s[2 * jnp + 1], qfh[kk], c2, c3);
            }
        }

        // ---- online softmax (2 rows per thread; quad = lanes sharing row) --
        float mx0 = -INFINITY, mx1 = -INFINITY;
        #pragma unroll
        for (int tt = 0; tt < 8; tt++) {
            mx0 = fmaxf(mx0, fmaxf(s[tt][0], s[tt][1]));
            mx1 = fmaxf(mx1, fmaxf(s[tt][2], s[tt][3]));
        }
        mx0 = fmaxf(mx0, __shfl_xor_sync(0xffffffffu, mx0, 1));
        mx0 = fmaxf(mx0, __shfl_xor_sync(0xffffffffu, mx0, 2));
        mx1 = fmaxf(mx1, __shfl_xor_sync(0xffffffffu, mx1, 1));
        mx1 = fmaxf(mx1, __shfl_xor_sync(0xffffffffu, mx1, 2));

        float mn0 = fmaxf(m0, mx0), mn1 = fmaxf(m1, mx1);
        float a0 = exp2f((m0 - mn0) * LOG2E), a1 = exp2f((m1 - mn1) * LOG2E);
        float rs0 = 0.f, rs1 = 0.f;
        #pragma unroll
        for (int tt = 0; tt < 8; tt++) {
            s[tt][0] = exp2f((s[tt][0] - mn0) * LOG2E);
            s[tt][1] = exp2f((s[tt][1] - mn0) * LOG2E);
            s[tt][2] = exp2f((s[tt][2] - mn1) * LOG2E);
            s[tt][3] = exp2f((s[tt][3] - mn1) * LOG2E);
            rs0 += s[tt][0] + s[tt][1];
            rs1 += s[tt][2] + s[tt][3];
        }
        rs0 += __shfl_xor_sync(0xffffffffu, rs0, 1);
        rs0 += __shfl_xor_sync(0xffffffffu, rs0, 2);
        rs1 += __shfl_xor_sync(0xffffffffu, rs1, 1);
        rs1 += __shfl_xor_sync(0xffffffffu, rs1, 2);
        l0 = l0 * a0 + rs0; l1 = l1 * a1 + rs1;
        m0 = mn0; m1 = mn1;
        #pragma unroll
        for (int tt = 0; tt < 8; tt++) {
            O[tt][0] *= a0; O[tt][1] *= a0;
            O[tt][2] *= a1; O[tt][3] *= a1;
        }

        // ---- P (C-frag) -> A-frags, hi/lo split, in registers ----
        uint32_t ph[4][4], pl[4][4];
        #pragma unroll
        for (int kk = 0; kk < 4; kk++) {
            pack_pair(s[2 * kk][0],     s[2 * kk][1],     ph[kk][0], pl[kk][0]);
            pack_pair(s[2 * kk][2],     s[2 * kk][3],     ph[kk][1], pl[kk][1]);
            pack_pair(s[2 * kk + 1][0], s[2 * kk + 1][1], ph[kk][2], pl[kk][2]);
            pack_pair(s[2 * kk + 1][2], s[2 * kk + 1][3], ph[kk][3], pl[kk][3]);
        }

        // ---- O += P V^T (per warp: m16 x n64(d), 3-pass split) ----
        #pragma unroll
        for (int kk = 0; kk < 4; kk++) {
            #pragma unroll
            for (int dnp = 0; dnp < 4; dnp++) {
                uint32_t b0, b1, b2, b3, c0, c1, c2, c3;
                ldsm4(b0, b1, b2, b3, vbh + ((uint32_t)dnp << 11) + swzB[kk]);
                ldsm4(c0, c1, c2, c3, vbl + ((uint32_t)dnp << 11) + swzB[kk]);
                mma16816(O[2 * dnp],     ph[kk], b0, b1);
                mma16816(O[2 * dnp],     pl[kk], b0, b1);
                mma16816(O[2 * dnp],     ph[kk], c0, c1);
                mma16816(O[2 * dnp + 1], ph[kk], b2, b3);
                mma16816(O[2 * dnp + 1], pl[kk], b2, b3);
                mma16816(O[2 * dnp + 1], ph[kk], c2, c3);
            }
        }
        // (top-of-loop wait+sync protects buffer reuse)
    }

    // ---- normalize + write g_att[b][l][h*64+d] (coalesced float2) ----
    const float inv0 = 1.0f / l0, inv1 = 1.0f / l1;
    const int r0 = i0 + 16 * w + (lane >> 2);
    float* ob0 = g_att + ((size_t)b * LL + r0) * HID + h * DD + 2 * (lane & 3);
    float* ob1 = ob0 + (size_t)8 * HID;
    #pragma unroll
    for (int tt = 0; tt < 8; tt++) {
        float2 v0, v1;
        v0.x = O[tt][0] * inv0; v0.y = O[tt][1] * inv0;
        v1.x = O[tt][2] * inv1; v1.y = O[tt][3] * inv1;
        *(float2*)(ob0 + 8 * tt) = v0;
        *(float2*)(ob1 + 8 * tt) = v1;
    }
}

// ---------------------------------------------------------------------------
// Output projection: out = w_out (256x512) * att[b]^T (+bias), att [b][l][512].
// ---------------------------------------------------------------------------
__global__ void out_gemm(const float* __restrict__ W, float* __restrict__ Y,
                         const float* __restrict__ bias)
{
    __shared__ float As[16][68];
    __shared__ float Bs[16][132];

    const int b  = blockIdx.z;
    const int m0 = blockIdx.y * 64;
    const int n0 = blockIdx.x * 128;
    const float* Xb = g_att + (size_t)b * LL * HID;
    float*       Yb = Y + (size_t)b * CC * LL;

    const int tid = threadIdx.x;
    const int tx = tid & 15, ty = tid >> 4;

    float acc[4][8] = {};

    for (int k0 = 0; k0 < HID; k0 += 16) {
        {
            int m = tid >> 2, kq = (tid & 3) * 4;
            float4 w4 = *(const float4*)(W + (size_t)(m0 + m) * HID + k0 + kq);
            As[kq + 0][m] = w4.x; As[kq + 1][m] = w4.y;
            As[kq + 2][m] = w4.z; As[kq + 3][m] = w4.w;
        }
        {
            int nb = tid >> 2, kq = (tid & 3) * 4;
            #pragma unroll
            for (int e = 0; e < 2; e++) {
                int nn = nb + e * 64;
                float4 x4 = *(const float4*)(Xb + (size_t)(n0 + nn) * HID + k0 + kq);
                Bs[kq + 0][nn] = x4.x; Bs[kq + 1][nn] = x4.y;
                Bs[kq + 2][nn] = x4.z; Bs[kq + 3][nn] = x4.w;
            }
        }
        __syncthreads();

        #pragma unroll
        for (int kk = 0; kk < 16; kk++) {
            float4 ra  = *(float4*)(&As[kk][ty * 4]);
            float4 rb0 = *(float4*)(&Bs[kk][tx * 4]);
            float4 rb1 = *(float4*)(&Bs[kk][64 + tx * 4]);
            float a[4] = {ra.x, ra.y, ra.z, ra.w};
            float b0[4] = {rb0.x, rb0.y, rb0.z, rb0.w};
            float b1[4] = {rb1.x, rb1.y, rb1.z, rb1.w};
            #pragma unroll
            for (int i = 0; i < 4; i++)
                #pragma unroll
                for (int j = 0; j < 4; j++) {
                    acc[i][j]     = fmaf(a[i], b0[j], acc[i][j]);
                    acc[i][4 + j] = fmaf(a[i], b1[j], acc[i][4 + j]);
                }
        }
        __syncthreads();
    }

    #pragma unroll
    for (int i = 0; i < 4; i++) {
        int m = m0 + ty * 4 + i;
        float bv = bias[m];
        float4 o0, o1;
        o0.x = acc[i][0] + bv; o0.y = acc[i][1] + bv;
        o0.z = acc[i][2] + bv; o0.w = acc[i][3] + bv;
        o1.x = acc[i][4] + bv; o1.y = acc[i][5] + bv;
        o1.z = acc[i][6] + bv; o1.w = acc[i][7] + bv;
        *(float4*)(Yb + (size_t)m * LL + n0 + tx * 4)      = o0;
        *(float4*)(Yb + (size_t)m * LL + n0 + 64 + tx * 4) = o1;
    }
}

// ---------------------------------------------------------------------------
extern "C" void kernel_launch(void* const* d_in, const int* in_sizes, int n_in,
                              void* d_out, int out_size)
{
    const float* x     = (const float*)d_in[0];
    const float* w_qkv = (const float*)d_in[1];
    const float* w_out = (const float*)d_in[2];
    const float* b_out = (const float*)d_in[3];
    float* out = (float*)d_out;

    const int ATTN_SMEM = 65536;
    cudaFuncSetAttribute(attn_kernel, cudaFuncAttributeMaxDynamicSharedMemorySize, ATTN_SMEM);

    qkv_gemm<<<dim3(LL / 128, MQKV / 64, BB), 256>>>(w_qkv, x);
    attn_kernel<<<dim3(LL / 128, BB * HH), 256, ATTN_SMEM>>>();
    out_gemm<<<dim3(LL / 128, CC / 64, BB), 256>>>(w_out, out, b_out);
}

// round 5
// speedup vs baseline: 3.6741x; 1.3613x over previous
#include <cuda_runtime.h>
#include <cuda_bf16.h>
#include <math.h>
#include <stdint.h>

#define BB   4
#define CC   256
#define LL   2048
#define HH   8
#define DD   64
#define HID  512
#define MQKV 1536
#define QKS  1024   // fused q|k channel stride

// ---------------- scratch (allocation-free rule: __device__ globals) -------
__device__ __align__(16) __nv_bfloat16 g_wq_hi[MQKV * CC];             // w_qkv split (q rows pre-scaled)
__device__ __align__(16) __nv_bfloat16 g_wq_lo[MQKV * CC];
__device__ __align__(16) __nv_bfloat16 g_wo_hi[CC * HID];              // w_out split
__device__ __align__(16) __nv_bfloat16 g_wo_lo[CC * HID];
__device__ __align__(16) __nv_bfloat16 g_xT_hi[(size_t)BB * LL * CC];  // x^T [b][l][256]
__device__ __align__(16) __nv_bfloat16 g_xT_lo[(size_t)BB * LL * CC];
__device__ __align__(16) __nv_bfloat16 g_qk_hi[(size_t)BB * LL * QKS]; // [b][l][q0..511|k0..511]
__device__ __align__(16) __nv_bfloat16 g_qk_lo[(size_t)BB * LL * QKS];
__device__ __align__(16) __nv_bfloat16 g_v_hi[(size_t)BB * HID * LL];  // [b][512][l]
__device__ __align__(16) __nv_bfloat16 g_v_lo[(size_t)BB * HID * LL];
__device__ __align__(16) __nv_bfloat16 g_att_hi[(size_t)BB * LL * HID]; // [b][l][512]
__device__ __align__(16) __nv_bfloat16 g_att_lo[(size_t)BB * LL * HID];

#define SWZ(x) ((x) ^ (((x) >> 3) & 0x70))

// ---------------- warp-MMA helpers -----------------------------------------
__device__ __forceinline__ uint32_t smem_u32(const void* p) {
    uint32_t a;
    asm("{ .reg .u64 t; cvta.to.shared.u64 t, %1; cvt.u32.u64 %0, t; }"
        : "=r"(a) : "l"(p));
    return a;
}
__device__ __forceinline__ void ldsm4(uint32_t& r0, uint32_t& r1, uint32_t& r2,
                                      uint32_t& r3, uint32_t a) {
    asm volatile("ldmatrix.sync.aligned.m8n8.x4.shared.b16 {%0,%1,%2,%3}, [%4];"
                 : "=r"(r0), "=r"(r1), "=r"(r2), "=r"(r3) : "r"(a));
}
__device__ __forceinline__ void mma16816(float* c, const uint32_t* a,
                                         uint32_t b0, uint32_t b1) {
    asm volatile("mma.sync.aligned.m16n8k16.row.col.f32.bf16.bf16.f32 "
                 "{%0,%1,%2,%3}, {%4,%5,%6,%7}, {%8,%9}, {%0,%1,%2,%3};"
                 : "+f"(c[0]), "+f"(c[1]), "+f"(c[2]), "+f"(c[3])
                 : "r"(a[0]), "r"(a[1]), "r"(a[2]), "r"(a[3]), "r"(b0), "r"(b1));
}
__device__ __forceinline__ uint32_t cvt2bf(float p0, float p1) {
    uint32_t r;
    asm("cvt.rn.bf16x2.f32 %0, %1, %2;" : "=r"(r) : "f"(p1), "f"(p0));
    return r;
}
__device__ __forceinline__ void pack_pair(float p0, float p1,
                                          uint32_t& hi, uint32_t& lo) {
    hi = cvt2bf(p0, p1);
    float f0 = __uint_as_float(hi << 16);
    float f1 = __uint_as_float(hi & 0xffff0000u);
    lo = cvt2bf(p0 - f0, p1 - f1);
}
__device__ __forceinline__ void split_bf16(float x, __nv_bfloat16& h, __nv_bfloat16& l) {
    h = __float2bfloat16(x);
    l = __float2bfloat16(x - __bfloat162float(h));
}

// ---------------------------------------------------------------------------
// conv_w: split both weight matrices to bf16 hi/lo; q rows (<512) x0.125.
// ---------------------------------------------------------------------------
__global__ void conv_w(const float* __restrict__ wq, const float* __restrict__ wo)
{
    const int NQ = MQKV * CC;
    int idx = blockIdx.x * 256 + threadIdx.x;
    if (idx < NQ) {
        float v = wq[idx];
        if (idx < 512 * CC) v *= 0.125f;
        __nv_bfloat16 h, l;
        split_bf16(v, h, l);
        g_wq_hi[idx] = h; g_wq_lo[idx] = l;
    } else {
        int j = idx - NQ;
        if (j < CC * HID) {
            __nv_bfloat16 h, l;
            split_bf16(wo[j], h, l);
            g_wo_hi[j] = h; g_wo_lo[j] = l;
        }
    }
}

// ---------------------------------------------------------------------------
// conv_x: transpose + split x [b][256][2048] -> xT hi/lo [b][2048][256].
// ---------------------------------------------------------------------------
__global__ void conv_x(const float* __restrict__ x)
{
    __shared__ float t[32][33];
    const int b = blockIdx.z;
    const int c0 = blockIdx.y * 32, l0 = blockIdx.x * 32;
    const int tx = threadIdx.x, ty = threadIdx.y;  // (32,8)
    const float* xb = x + ((size_t)b * CC + c0) * LL + l0;
    #pragma unroll
    for (int i = 0; i < 4; i++)
        t[ty + 8 * i][tx] = xb[(size_t)(ty + 8 * i) * LL + tx];
    __syncthreads();
    #pragma unroll
    for (int i = 0; i < 4; i++) {
        int row = ty + 8 * i;                     // l offset
        float v = t[tx][row];                     // = x[c0+tx][l0+row]
        __nv_bfloat16 h, l2;
        split_bf16(v, h, l2);
        size_t o = ((size_t)b * LL + l0 + row) * CC + c0 + tx;
        g_xT_hi[o] = h; g_xT_lo[o] = l2;
    }
}

// ---------------------------------------------------------------------------
// Generic bf16-split MMA GEMM: C[m][n] = sum_k A[m][k] * B[n][k], 3-pass
// (Ah*Bh + Al*Bh + Ah*Bl). CTA 128(M) x 64(N), 8 warps x m16n64, K-chunks of
// 64, cp.async double-buffered (2 x 48KB smem).
// MODE 0: pack hi/lo bf16 -> Yh/Yl. MODE 1: fp32 + bias[m] -> Yf.
// ---------------------------------------------------------------------------
template<int MODE>
__global__ void __launch_bounds__(256, 1) mma_gemm(
    const __nv_bfloat16* __restrict__ Ah, const __nv_bfloat16* __restrict__ Al, size_t sA,
    const __nv_bfloat16* __restrict__ Bh, const __nv_bfloat16* __restrict__ Bl, size_t sB,
    __nv_bfloat16* Yh, __nv_bfloat16* Yl, float* Yf, const float* bias, size_t sY,
    int N, int K, int nkc)
{
    extern __shared__ __align__(1024) char smem[];
    const uint32_t sb = smem_u32(smem);
    const int tid = threadIdx.x;
    const int lane = tid & 31, w = tid >> 5;
    const int b  = blockIdx.z;
    const int m0 = blockIdx.y * 128;
    const int n0 = blockIdx.x * 64;

    const __nv_bfloat16* Ahb = Ah + (size_t)b * sA;
    const __nv_bfloat16* Alb = Al + (size_t)b * sA;
    const __nv_bfloat16* Bhb = Bh + (size_t)b * sB;
    const __nv_bfloat16* Blb = Bl + (size_t)b * sB;

    // swizzled ldmatrix lane offsets (identical mapping to attn kernel)
    const int g = lane >> 3;
    const int rowB = ((g & 2) ? 8 : 0) + (lane & 7);
    const int bytB = (g & 1) * 16;
    const int rowA = lane & 15;
    const int bytA = (lane >> 4) * 16;
    uint32_t swzB[4], swzA[4];
    #pragma unroll
    for (int kk = 0; kk < 4; kk++) {
        swzB[kk] = SWZ((uint32_t)(rowB * 128 + bytB + kk * 32));
        swzA[kk] = SWZ((uint32_t)(rowA * 128 + bytA + kk * 32));
    }

    // buffer regions: AH 0 | AL 16K | BH 32K | BL 40K ; BUF stride 48K
    auto issue = [&](int kc) {
        const uint32_t base = sb + (uint32_t)(kc & 1) * 49152u;
        const int koff = kc * 64;
        #pragma unroll
        for (int e = 0; e < 4; e++) {
            int wi = tid + e * 256;          // 0..1023
            int row = wi >> 3, c = wi & 7;
            uint32_t sw = SWZ((uint32_t)(row * 128 + c * 16));
            const __nv_bfloat16* s0 = Ahb + (size_t)(m0 + row) * K + koff + c * 8;
            const __nv_bfloat16* s1 = Alb + (size_t)(m0 + row) * K + koff + c * 8;
            asm volatile("cp.async.cg.shared.global [%0], [%1], 16;" :: "r"(base + sw), "l"(s0));
            asm volatile("cp.async.cg.shared.global [%0], [%1], 16;" :: "r"(base + 16384u + sw), "l"(s1));
        }
        #pragma unroll
        for (int e = 0; e < 2; e++) {
            int wi = tid + e * 256;          // 0..511
            int row = wi >> 3, c = wi & 7;
            uint32_t sw = SWZ((uint32_t)(row * 128 + c * 16));
            const __nv_bfloat16* s0 = Bhb + (size_t)(n0 + row) * K + koff + c * 8;
            const __nv_bfloat16* s1 = Blb + (size_t)(n0 + row) * K + koff + c * 8;
            asm volatile("cp.async.cg.shared.global [%0], [%1], 16;" :: "r"(base + 32768u + sw), "l"(s0));
            asm volatile("cp.async.cg.shared.global [%0], [%1], 16;" :: "r"(base + 40960u + sw), "l"(s1));
        }
        asm volatile("cp.async.commit_group;" ::: "memory");
    };

    issue(0);

    float s[8][4] = {};

    for (int kc = 0; kc < nkc; kc++) {
        asm volatile("cp.async.wait_group 0;" ::: "memory");
        __syncthreads();
        if (kc + 1 < nkc) issue(kc + 1);

        const uint32_t base = sb + (uint32_t)(kc & 1) * 49152u;
        const uint32_t ab = base + ((uint32_t)w << 11);

        #pragma unroll
        for (int kk = 0; kk < 4; kk++) {
            uint32_t ah[4], al[4];
            ldsm4(ah[0], ah[1], ah[2], ah[3], ab + swzA[kk]);
            ldsm4(al[0], al[1], al[2], al[3], ab + 16384u + swzA[kk]);
            #pragma unroll
            for (int np = 0; np < 4; np++) {
                uint32_t b0, b1, b2, b3, c0, c1, c2, c3;
                ldsm4(b0, b1, b2, b3, base + 32768u + ((uint32_t)np << 11) + swzB[kk]);
                ldsm4(c0, c1, c2, c3, base + 40960u + ((uint32_t)np << 11) + swzB[kk]);
                mma16816(s[2 * np],     ah, b0, b1);
                mma16816(s[2 * np],     al, b0, b1);
                mma16816(s[2 * np],     ah, c0, c1);
                mma16816(s[2 * np + 1], ah, b2, b3);
                mma16816(s[2 * np + 1], al, b2, b3);
                mma16816(s[2 * np + 1], ah, c2, c3);
            }
        }
        __syncthreads();
    }

    // ---- epilogue ----
    const int mr = m0 + w * 16 + (lane >> 2);
    const int nc = n0 + 2 * (lane & 3);
    if (MODE == 0) {
        __nv_bfloat16* Yhb = Yh + (size_t)b * sY;
        __nv_bfloat16* Ylb = Yl + (size_t)b * sY;
        #pragma unroll
        for (int tt = 0; tt < 8; tt++) {
            uint32_t h0, l0, h1, l1;
            pack_pair(s[tt][0], s[tt][1], h0, l0);
            pack_pair(s[tt][2], s[tt][3], h1, l1);
            size_t o0 = (size_t)mr * N + nc + 8 * tt;
            size_t o1 = (size_t)(mr + 8) * N + nc + 8 * tt;
            *(uint32_t*)&Yhb[o0] = h0; *(uint32_t*)&Ylb[o0] = l0;
            *(uint32_t*)&Yhb[o1] = h1; *(uint32_t*)&Ylb[o1] = l1;
        }
    } else {
        float* Yfb = Yf + (size_t)b * sY;
        const float bv0 = bias[mr], bv1 = bias[mr + 8];
        #pragma unroll
        for (int tt = 0; tt < 8; tt++) {
            float2 v0, v1;
            v0.x = s[tt][0] + bv0; v0.y = s[tt][1] + bv0;
            v1.x = s[tt][2] + bv1; v1.y = s[tt][3] + bv1;
            *(float2*)(Yfb + (size_t)mr * N + nc + 8 * tt)       = v0;
            *(float2*)(Yfb + (size_t)(mr + 8) * N + nc + 8 * tt) = v1;
        }
    }
}

// ---------------------------------------------------------------------------
// Flash attention on mma.sync (bf16 3-pass). CTA = one (b,h) x 128 queries,
// 8 warps x 16 rows; 64-key tiles, cp.async double-buffered K/V. Output
// written as bf16 hi/lo for the downstream MMA out-projection.
// ---------------------------------------------------------------------------
__global__ void __launch_bounds__(256, 1) attn_kernel()
{
    extern __shared__ __align__(1024) char smem[];
    const uint32_t sb = smem_u32(smem);
    const int tid = threadIdx.x;
    const int lane = tid & 31, w = tid >> 5;
    const int bh = blockIdx.y;
    const int b = bh >> 3, h = bh & 7;
    const int i0 = blockIdx.x * 128;

    const __nv_bfloat16* qh = g_qk_hi + ((size_t)b * LL + i0) * QKS + h * DD;
    const __nv_bfloat16* ql = g_qk_lo + ((size_t)b * LL + i0) * QKS + h * DD;
    const __nv_bfloat16* kh = g_qk_hi + (size_t)b * LL * QKS + 512 + h * DD;
    const __nv_bfloat16* kl = g_qk_lo + (size_t)b * LL * QKS + 512 + h * DD;
    const __nv_bfloat16* vh = g_v_hi + ((size_t)b * HID + h * DD) * LL;
    const __nv_bfloat16* vl = g_v_lo + ((size_t)b * HID + h * DD) * LL;

    const int g = lane >> 3;
    const int rowB = ((g & 2) ? 8 : 0) + (lane & 7);
    const int bytB = (g & 1) * 16;
    const int rowA = lane & 15;
    const int bytA = (lane >> 4) * 16;
    uint32_t swzB[4], swzA[4];
    #pragma unroll
    for (int kk = 0; kk < 4; kk++) {
        swzB[kk] = SWZ((uint32_t)(rowB * 128 + bytB + kk * 32));
        swzA[kk] = SWZ((uint32_t)(rowA * 128 + bytA + kk * 32));
    }

    auto issue_tile = [&](int jt) {
        const int j0 = jt * 64;
        const uint32_t base = sb + ((jt & 1) ? 32768u : 0u);
        #pragma unroll
        for (int e = 0; e < 8; e++) {
            const int bufsel = e >> 1;
            const int wi = tid + (e & 1) * 256;
            const int row = wi >> 3, c = wi & 7;
            const uint32_t dst = base + bufsel * 8192 + SWZ((uint32_t)(row * 128 + c * 16));
            const __nv_bfloat16* src;
            if (bufsel == 0)      src = kh + (size_t)(j0 + row) * QKS + c * 8;
            else if (bufsel == 1) src = kl + (size_t)(j0 + row) * QKS + c * 8;
            else if (bufsel == 2) src = vh + (size_t)row * LL + j0 + c * 8;
            else                  src = vl + (size_t)row * LL + j0 + c * 8;
            asm volatile("cp.async.cg.shared.global [%0], [%1], 16;"
                         :: "r"(dst), "l"(src));
        }
        asm volatile("cp.async.commit_group;" ::: "memory");
    };

    issue_tile(0);

    // stage Q (hi @32K, lo @48K)
    #pragma unroll
    for (int e = 0; e < 4; e++) {
        int idx = tid + e * 256;
        int row = idx >> 3, c = idx & 7;
        uint32_t sw = SWZ((uint32_t)(row * 128 + c * 16));
        *(uint4*)(smem + 32768 + sw) = *(const uint4*)(qh + (size_t)row * QKS + c * 8);
        *(uint4*)(smem + 49152 + sw) = *(const uint4*)(ql + (size_t)row * QKS + c * 8);
    }
    __syncthreads();
    uint32_t qfh[4][4], qfl[4][4];
    #pragma unroll
    for (int kk = 0; kk < 4; kk++) {
        ldsm4(qfh[kk][0], qfh[kk][1], qfh[kk][2], qfh[kk][3],
              sb + 32768u + ((uint32_t)w << 11) + swzA[kk]);
        ldsm4(qfl[kk][0], qfl[kk][1], qfl[kk][2], qfl[kk][3],
              sb + 49152u + ((uint32_t)w << 11) + swzA[kk]);
    }
    __syncthreads();

    const float LOG2E = 1.4426950408889634f;
    float m0 = -INFINITY, m1 = -INFINITY, l0 = 0.f, l1 = 0.f;
    float O[8][4] = {};

    for (int t = 0; t < 32; t++) {
        asm volatile("cp.async.wait_group 0;" ::: "memory");
        __syncthreads();
        if (t + 1 < 32) issue_tile(t + 1);

        const uint32_t base = sb + ((t & 1) ? 32768u : 0u);
        const uint32_t kbh = base, kbl = base + 8192u;
        const uint32_t vbh = base + 16384u, vbl = base + 24576u;

        float s[8][4] = {};
        #pragma unroll
        for (int kk = 0; kk < 4; kk++) {
            #pragma unroll
            for (int jnp = 0; jnp < 4; jnp++) {
                uint32_t b0, b1, b2, b3, c0, c1, c2, c3;
                ldsm4(b0, b1, b2, b3, kbh + ((uint32_t)jnp << 11) + swzB[kk]);
                ldsm4(c0, c1, c2, c3, kbl + ((uint32_t)jnp << 11) + swzB[kk]);
                mma16816(s[2 * jnp],     qfh[kk], b0, b1);
                mma16816(s[2 * jnp],     qfl[kk], b0, b1);
                mma16816(s[2 * jnp],     qfh[kk], c0, c1);
                mma16816(s[2 * jnp + 1], qfh[kk], b2, b3);
                mma16816(s[2 * jnp + 1], qfl[kk], b2, b3);
                mma16816(s[2 * jnp + 1], qfh[kk], c2, c3);
            }
        }

        float mx0 = -INFINITY, mx1 = -INFINITY;
        #pragma unroll
        for (int tt = 0; tt < 8; tt++) {
            mx0 = fmaxf(mx0, fmaxf(s[tt][0], s[tt][1]));
            mx1 = fmaxf(mx1, fmaxf(s[tt][2], s[tt][3]));
        }
        mx0 = fmaxf(mx0, __shfl_xor_sync(0xffffffffu, mx0, 1));
        mx0 = fmaxf(mx0, __shfl_xor_sync(0xffffffffu, mx0, 2));
        mx1 = fmaxf(mx1, __shfl_xor_sync(0xffffffffu, mx1, 1));
        mx1 = fmaxf(mx1, __shfl_xor_sync(0xffffffffu, mx1, 2));

        float mn0 = fmaxf(m0, mx0), mn1 = fmaxf(m1, mx1);
        float a0 = exp2f((m0 - mn0) * LOG2E), a1 = exp2f((m1 - mn1) * LOG2E);
        float rs0 = 0.f, rs1 = 0.f;
        #pragma unroll
        for (int tt = 0; tt < 8; tt++) {
            s[tt][0] = exp2f((s[tt][0] - mn0) * LOG2E);
            s[tt][1] = exp2f((s[tt][1] - mn0) * LOG2E);
            s[tt][2] = exp2f((s[tt][2] - mn1) * LOG2E);
            s[tt][3] = exp2f((s[tt][3] - mn1) * LOG2E);
            rs0 += s[tt][0] + s[tt][1];
            rs1 += s[tt][2] + s[tt][3];
        }
        rs0 += __shfl_xor_sync(0xffffffffu, rs0, 1);
        rs0 += __shfl_xor_sync(0xffffffffu, rs0, 2);
        rs1 += __shfl_xor_sync(0xffffffffu, rs1, 1);
        rs1 += __shfl_xor_sync(0xffffffffu, rs1, 2);
        l0 = l0 * a0 + rs0; l1 = l1 * a1 + rs1;
        m0 = mn0; m1 = mn1;
        #pragma unroll
        for (int tt = 0; tt < 8; tt++) {
            O[tt][0] *= a0; O[tt][1] *= a0;
            O[tt][2] *= a1; O[tt][3] *= a1;
        }

        uint32_t ph[4][4], pl[4][4];
        #pragma unroll
        for (int kk = 0; kk < 4; kk++) {
            pack_pair(s[2 * kk][0],     s[2 * kk][1],     ph[kk][0], pl[kk][0]);
            pack_pair(s[2 * kk][2],     s[2 * kk][3],     ph[kk][1], pl[kk][1]);
            pack_pair(s[2 * kk + 1][0], s[2 * kk + 1][1], ph[kk][2], pl[kk][2]);
            pack_pair(s[2 * kk + 1][2], s[2 * kk + 1][3], ph[kk][3], pl[kk][3]);
        }

        #pragma unroll
        for (int kk = 0; kk < 4; kk++) {
            #pragma unroll
            for (int dnp = 0; dnp < 4; dnp++) {
                uint32_t b0, b1, b2, b3, c0, c1, c2, c3;
                ldsm4(b0, b1, b2, b3, vbh + ((uint32_t)dnp << 11) + swzB[kk]);
                ldsm4(c0, c1, c2, c3, vbl + ((uint32_t)dnp << 11) + swzB[kk]);
                mma16816(O[2 * dnp],     ph[kk], b0, b1);
                mma16816(O[2 * dnp],     pl[kk], b0, b1);
                mma16816(O[2 * dnp],     ph[kk], c0, c1);
                mma16816(O[2 * dnp + 1], ph[kk], b2, b3);
                mma16816(O[2 * dnp + 1], pl[kk], b2, b3);
                mma16816(O[2 * dnp + 1], ph[kk], c2, c3);
            }
        }
    }

    // normalize + write bf16 hi/lo att [b][l][512]
    const float inv0 = 1.0f / l0, inv1 = 1.0f / l1;
    const int r0 = i0 + 16 * w + (lane >> 2);
    size_t o0 = ((size_t)b * LL + r0) * HID + h * DD + 2 * (lane & 3);
    size_t o1 = o0 + (size_t)8 * HID;
    #pragma unroll
    for (int tt = 0; tt < 8; tt++) {
        uint32_t h0, lo0, h1, lo1;
        pack_pair(O[tt][0] * inv0, O[tt][1] * inv0, h0, lo0);
        pack_pair(O[tt][2] * inv1, O[tt][3] * inv1, h1, lo1);
        *(uint32_t*)&g_att_hi[o0 + 8 * tt] = h0;
        *(uint32_t*)&g_att_lo[o0 + 8 * tt] = lo0;
        *(uint32_t*)&g_att_hi[o1 + 8 * tt] = h1;
        *(uint32_t*)&g_att_lo[o1 + 8 * tt] = lo1;
    }
}

// ---------------------------------------------------------------------------
extern "C" void kernel_launch(void* const* d_in, const int* in_sizes, int n_in,
                              void* d_out, int out_size)
{
    const float* x     = (const float*)d_in[0];
    const float* w_qkv = (const float*)d_in[1];
    const float* w_out = (const float*)d_in[2];
    const float* b_out = (const float*)d_in[3];
    float* out = (float*)d_out;

    __nv_bfloat16 *wq_h, *wq_l, *wo_h, *wo_l, *xt_h, *xt_l;
    __nv_bfloat16 *qk_h, *qk_l, *v_h, *v_l, *at_h, *at_l;
    cudaGetSymbolAddress((void**)&wq_h, g_wq_hi);
    cudaGetSymbolAddress((void**)&wq_l, g_wq_lo);
    cudaGetSymbolAddress((void**)&wo_h, g_wo_hi);
    cudaGetSymbolAddress((void**)&wo_l, g_wo_lo);
    cudaGetSymbolAddress((void**)&xt_h, g_xT_hi);
    cudaGetSymbolAddress((void**)&xt_l, g_xT_lo);
    cudaGetSymbolAddress((void**)&qk_h, g_qk_hi);
    cudaGetSymbolAddress((void**)&qk_l, g_qk_lo);
    cudaGetSymbolAddress((void**)&v_h,  g_v_hi);
    cudaGetSymbolAddress((void**)&v_l,  g_v_lo);
    cudaGetSymbolAddress((void**)&at_h, g_att_hi);
    cudaGetSymbolAddress((void**)&at_l, g_att_lo);

    const int GEMM_SMEM = 98304;
    const int ATTN_SMEM = 65536;
    cudaFuncSetAttribute(mma_gemm<0>, cudaFuncAttributeMaxDynamicSharedMemorySize, GEMM_SMEM);
    cudaFuncSetAttribute(mma_gemm<1>, cudaFuncAttributeMaxDynamicSharedMemorySize, GEMM_SMEM);
    cudaFuncSetAttribute(attn_kernel, cudaFuncAttributeMaxDynamicSharedMemorySize, ATTN_SMEM);

    conv_w<<<(MQKV * CC + CC * HID) / 256, 256>>>(w_qkv, w_out);
    conv_x<<<dim3(LL / 32, CC / 32, BB), dim3(32, 8)>>>(x);

    // L1: C[l][qk_ch] = xT * wq(rows 0..1023)^T  -> g_qk
    mma_gemm<0><<<dim3(QKS / 64, LL / 128, BB), 256, GEMM_SMEM>>>(
        xt_h, xt_l, (size_t)LL * CC, wq_h, wq_l, 0,
        qk_h, qk_l, nullptr, nullptr, (size_t)LL * QKS, QKS, CC, CC / 64);

    // L2: C[v_ch][l] = wq(rows 1024..1535) * xT^T -> g_v
    mma_gemm<0><<<dim3(LL / 64, HID / 128, BB), 256, GEMM_SMEM>>>(
        wq_h + 1024 * CC, wq_l + 1024 * CC, 0, xt_h, xt_l, (size_t)LL * CC,
        v_h, v_l, nullptr, nullptr, (size_t)HID * LL, LL, CC, CC / 64);

    attn_kernel<<<dim3(LL / 128, BB * HH), 256, ATTN_SMEM>>>();

    // L3: out[ch][l] = w_out * att^T + bias
    mma_gemm<1><<<dim3(LL / 64, CC / 128, BB), 256, GEMM_SMEM>>>(
        wo_h, wo_l, 0, at_h, at_l, (size_t)LL * HID,
        nullptr, nullptr, out, b_out, (size_t)CC * LL, LL, HID, HID / 64);
}

// round 6
// speedup vs baseline: 3.7599x; 1.0233x over previous
#include <cuda_runtime.h>
#include <cuda_bf16.h>
#include <math.h>
#include <stdint.h>

#define BB   4
#define CC   256
#define LL   2048
#define HH   8
#define DD   64
#define HID  512
#define MQKV 1536
#define QKS  1024   // fused q|k channel stride

// ---------------- scratch (allocation-free rule: __device__ globals) -------
__device__ __align__(16) __nv_bfloat16 g_wq_hi[MQKV * CC];
__device__ __align__(16) __nv_bfloat16 g_wq_lo[MQKV * CC];
__device__ __align__(16) __nv_bfloat16 g_wo_hi[CC * HID];
__device__ __align__(16) __nv_bfloat16 g_wo_lo[CC * HID];
__device__ __align__(16) __nv_bfloat16 g_xT_hi[(size_t)BB * LL * CC];
__device__ __align__(16) __nv_bfloat16 g_xT_lo[(size_t)BB * LL * CC];
__device__ __align__(16) __nv_bfloat16 g_qk_hi[(size_t)BB * LL * QKS];
__device__ __align__(16) __nv_bfloat16 g_qk_lo[(size_t)BB * LL * QKS];
__device__ __align__(16) __nv_bfloat16 g_v_hi[(size_t)BB * HID * LL];
__device__ __align__(16) __nv_bfloat16 g_v_lo[(size_t)BB * HID * LL];
__device__ __align__(16) __nv_bfloat16 g_att_hi[(size_t)BB * LL * HID];
__device__ __align__(16) __nv_bfloat16 g_att_lo[(size_t)BB * LL * HID];

#define SWZ(x) ((x) ^ (((x) >> 3) & 0x70))

// ---------------- warp-MMA helpers -----------------------------------------
__device__ __forceinline__ uint32_t smem_u32(const void* p) {
    uint32_t a;
    asm("{ .reg .u64 t; cvta.to.shared.u64 t, %1; cvt.u32.u64 %0, t; }"
        : "=r"(a) : "l"(p));
    return a;
}
__device__ __forceinline__ void ldsm4(uint32_t& r0, uint32_t& r1, uint32_t& r2,
                                      uint32_t& r3, uint32_t a) {
    asm volatile("ldmatrix.sync.aligned.m8n8.x4.shared.b16 {%0,%1,%2,%3}, [%4];"
                 : "=r"(r0), "=r"(r1), "=r"(r2), "=r"(r3) : "r"(a));
}
__device__ __forceinline__ void mma16816(float* c, const uint32_t* a,
                                         uint32_t b0, uint32_t b1) {
    asm volatile("mma.sync.aligned.m16n8k16.row.col.f32.bf16.bf16.f32 "
                 "{%0,%1,%2,%3}, {%4,%5,%6,%7}, {%8,%9}, {%0,%1,%2,%3};"
                 : "+f"(c[0]), "+f"(c[1]), "+f"(c[2]), "+f"(c[3])
                 : "r"(a[0]), "r"(a[1]), "r"(a[2]), "r"(a[3]), "r"(b0), "r"(b1));
}
__device__ __forceinline__ uint32_t cvt2bf(float p0, float p1) {
    uint32_t r;
    asm("cvt.rn.bf16x2.f32 %0, %1, %2;" : "=r"(r) : "f"(p1), "f"(p0));
    return r;
}
__device__ __forceinline__ void pack_pair(float p0, float p1,
                                          uint32_t& hi, uint32_t& lo) {
    hi = cvt2bf(p0, p1);
    float f0 = __uint_as_float(hi << 16);
    float f1 = __uint_as_float(hi & 0xffff0000u);
    lo = cvt2bf(p0 - f0, p1 - f1);
}
__device__ __forceinline__ void split_bf16(float x, __nv_bfloat16& h, __nv_bfloat16& l) {
    h = __float2bfloat16(x);
    l = __float2bfloat16(x - __bfloat162float(h));
}

// ---------------------------------------------------------------------------
// conv_w / conv_x (unchanged from R5)
// ---------------------------------------------------------------------------
__global__ void conv_w(const float* __restrict__ wq, const float* __restrict__ wo)
{
    const int NQ = MQKV * CC;
    int idx = blockIdx.x * 256 + threadIdx.x;
    if (idx < NQ) {
        float v = wq[idx];
        if (idx < 512 * CC) v *= 0.125f;
        __nv_bfloat16 h, l;
        split_bf16(v, h, l);
        g_wq_hi[idx] = h; g_wq_lo[idx] = l;
    } else {
        int j = idx - NQ;
        if (j < CC * HID) {
            __nv_bfloat16 h, l;
            split_bf16(wo[j], h, l);
            g_wo_hi[j] = h; g_wo_lo[j] = l;
        }
    }
}

__global__ void conv_x(const float* __restrict__ x)
{
    __shared__ float t[32][33];
    const int b = blockIdx.z;
    const int c0 = blockIdx.y * 32, l0 = blockIdx.x * 32;
    const int tx = threadIdx.x, ty = threadIdx.y;
    const float* xb = x + ((size_t)b * CC + c0) * LL + l0;
    #pragma unroll
    for (int i = 0; i < 4; i++)
        t[ty + 8 * i][tx] = xb[(size_t)(ty + 8 * i) * LL + tx];
    __syncthreads();
    #pragma unroll
    for (int i = 0; i < 4; i++) {
        int row = ty + 8 * i;
        float v = t[tx][row];
        __nv_bfloat16 h, l2;
        split_bf16(v, h, l2);
        size_t o = ((size_t)b * LL + l0 + row) * CC + c0 + tx;
        g_xT_hi[o] = h; g_xT_lo[o] = l2;
    }
}

// ---------------------------------------------------------------------------
// Generic bf16-split MMA GEMM (unchanged from R5): C[m][n] = sum_k A[m][k]*B[n][k]
// ---------------------------------------------------------------------------
template<int MODE>
__global__ void __launch_bounds__(256, 1) mma_gemm(
    const __nv_bfloat16* __restrict__ Ah, const __nv_bfloat16* __restrict__ Al, size_t sA,
    const __nv_bfloat16* __restrict__ Bh, const __nv_bfloat16* __restrict__ Bl, size_t sB,
    __nv_bfloat16* Yh, __nv_bfloat16* Yl, float* Yf, const float* bias, size_t sY,
    int N, int K, int nkc)
{
    extern __shared__ __align__(1024) char smem[];
    const uint32_t sb = smem_u32(smem);
    const int tid = threadIdx.x;
    const int lane = tid & 31, w = tid >> 5;
    const int b  = blockIdx.z;
    const int m0 = blockIdx.y * 128;
    const int n0 = blockIdx.x * 64;

    const __nv_bfloat16* Ahb = Ah + (size_t)b * sA;
    const __nv_bfloat16* Alb = Al + (size_t)b * sA;
    const __nv_bfloat16* Bhb = Bh + (size_t)b * sB;
    const __nv_bfloat16* Blb = Bl + (size_t)b * sB;

    const int g = lane >> 3;
    const int rowB = ((g & 2) ? 8 : 0) + (lane & 7);
    const int bytB = (g & 1) * 16;
    const int rowA = lane & 15;
    const int bytA = (lane >> 4) * 16;
    uint32_t swzB[4], swzA[4];
    #pragma unroll
    for (int kk = 0; kk < 4; kk++) {
        swzB[kk] = SWZ((uint32_t)(rowB * 128 + bytB + kk * 32));
        swzA[kk] = SWZ((uint32_t)(rowA * 128 + bytA + kk * 32));
    }

    auto issue = [&](int kc) {
        const uint32_t base = sb + (uint32_t)(kc & 1) * 49152u;
        const int koff = kc * 64;
        #pragma unroll
        for (int e = 0; e < 4; e++) {
            int wi = tid + e * 256;
            int row = wi >> 3, c = wi & 7;
            uint32_t sw = SWZ((uint32_t)(row * 128 + c * 16));
            const __nv_bfloat16* s0 = Ahb + (size_t)(m0 + row) * K + koff + c * 8;
            const __nv_bfloat16* s1 = Alb + (size_t)(m0 + row) * K + koff + c * 8;
            asm volatile("cp.async.cg.shared.global [%0], [%1], 16;" :: "r"(base + sw), "l"(s0));
            asm volatile("cp.async.cg.shared.global [%0], [%1], 16;" :: "r"(base + 16384u + sw), "l"(s1));
        }
        #pragma unroll
        for (int e = 0; e < 2; e++) {
            int wi = tid + e * 256;
            int row = wi >> 3, c = wi & 7;
            uint32_t sw = SWZ((uint32_t)(row * 128 + c * 16));
            const __nv_bfloat16* s0 = Bhb + (size_t)(n0 + row) * K + koff + c * 8;
            const __nv_bfloat16* s1 = Blb + (size_t)(n0 + row) * K + koff + c * 8;
            asm volatile("cp.async.cg.shared.global [%0], [%1], 16;" :: "r"(base + 32768u + sw), "l"(s0));
            asm volatile("cp.async.cg.shared.global [%0], [%1], 16;" :: "r"(base + 40960u + sw), "l"(s1));
        }
        asm volatile("cp.async.commit_group;" ::: "memory");
    };

    issue(0);

    float s[8][4] = {};

    for (int kc = 0; kc < nkc; kc++) {
        asm volatile("cp.async.wait_group 0;" ::: "memory");
        __syncthreads();
        if (kc + 1 < nkc) issue(kc + 1);

        const uint32_t base = sb + (uint32_t)(kc & 1) * 49152u;
        const uint32_t ab = base + ((uint32_t)w << 11);

        #pragma unroll
        for (int kk = 0; kk < 4; kk++) {
            uint32_t ah[4], al[4];
            ldsm4(ah[0], ah[1], ah[2], ah[3], ab + swzA[kk]);
            ldsm4(al[0], al[1], al[2], al[3], ab + 16384u + swzA[kk]);
            #pragma unroll
            for (int np = 0; np < 4; np++) {
                uint32_t b0, b1, b2, b3, c0, c1, c2, c3;
                ldsm4(b0, b1, b2, b3, base + 32768u + ((uint32_t)np << 11) + swzB[kk]);
                ldsm4(c0, c1, c2, c3, base + 40960u + ((uint32_t)np << 11) + swzB[kk]);
                mma16816(s[2 * np],     ah, b0, b1);
                mma16816(s[2 * np],     al, b0, b1);
                mma16816(s[2 * np],     ah, c0, c1);
                mma16816(s[2 * np + 1], ah, b2, b3);
                mma16816(s[2 * np + 1], al, b2, b3);
                mma16816(s[2 * np + 1], ah, c2, c3);
            }
        }
        __syncthreads();
    }

    const int mr = m0 + w * 16 + (lane >> 2);
    const int nc = n0 + 2 * (lane & 3);
    if (MODE == 0) {
        __nv_bfloat16* Yhb = Yh + (size_t)b * sY;
        __nv_bfloat16* Ylb = Yl + (size_t)b * sY;
        #pragma unroll
        for (int tt = 0; tt < 8; tt++) {
            uint32_t h0, l0, h1, l1;
            pack_pair(s[tt][0], s[tt][1], h0, l0);
            pack_pair(s[tt][2], s[tt][3], h1, l1);
            size_t o0 = (size_t)mr * N + nc + 8 * tt;
            size_t o1 = (size_t)(mr + 8) * N + nc + 8 * tt;
            *(uint32_t*)&Yhb[o0] = h0; *(uint32_t*)&Ylb[o0] = l0;
            *(uint32_t*)&Yhb[o1] = h1; *(uint32_t*)&Ylb[o1] = l1;
        }
    } else {
        float* Yfb = Yf + (size_t)b * sY;
        const float bv0 = bias[mr], bv1 = bias[mr + 8];
        #pragma unroll
        for (int tt = 0; tt < 8; tt++) {
            float2 v0, v1;
            v0.x = s[tt][0] + bv0; v0.y = s[tt][1] + bv0;
            v1.x = s[tt][2] + bv1; v1.y = s[tt][3] + bv1;
            *(float2*)(Yfb + (size_t)mr * N + nc + 8 * tt)       = v0;
            *(float2*)(Yfb + (size_t)(mr + 8) * N + nc + 8 * tt) = v1;
        }
    }
}

// ---------------------------------------------------------------------------
// Flash attention, m32n64 warp tiles. CTA = 4 warps x 32 query rows = 128
// queries, 2 CTAs/SM. B fragments (K,V hi/lo) reused across both 16-row
// halves of each warp tile (MMA:LDSM = 6:1).
// ---------------------------------------------------------------------------
__global__ void __launch_bounds__(128, 2) attn_kernel()
{
    extern __shared__ __align__(1024) char smem[];
    const uint32_t sb = smem_u32(smem);
    const int tid = threadIdx.x;
    const int lane = tid & 31, w = tid >> 5;
    const int bh = blockIdx.y;
    const int b = bh >> 3, h = bh & 7;
    const int i0 = blockIdx.x * 128;

    const __nv_bfloat16* qh = g_qk_hi + ((size_t)b * LL + i0) * QKS + h * DD;
    const __nv_bfloat16* ql = g_qk_lo + ((size_t)b * LL + i0) * QKS + h * DD;
    const __nv_bfloat16* kh = g_qk_hi + (size_t)b * LL * QKS + 512 + h * DD;
    const __nv_bfloat16* kl = g_qk_lo + (size_t)b * LL * QKS + 512 + h * DD;
    const __nv_bfloat16* vh = g_v_hi + ((size_t)b * HID + h * DD) * LL;
    const __nv_bfloat16* vl = g_v_lo + ((size_t)b * HID + h * DD) * LL;

    const int g = lane >> 3;
    const int rowB = ((g & 2) ? 8 : 0) + (lane & 7);
    const int bytB = (g & 1) * 16;
    const int rowA = lane & 15;
    const int bytA = (lane >> 4) * 16;
    uint32_t swzB[4], swzA[4];
    #pragma unroll
    for (int kk = 0; kk < 4; kk++) {
        swzB[kk] = SWZ((uint32_t)(rowB * 128 + bytB + kk * 32));
        swzA[kk] = SWZ((uint32_t)(rowA * 128 + bytA + kk * 32));
    }

    // K/V tile staging: 4 x 8KB per buffer, 128 threads -> 16 chunks each
    auto issue_tile = [&](int jt) {
        const int j0 = jt * 64;
        const uint32_t base = sb + ((jt & 1) ? 32768u : 0u);
        #pragma unroll
        for (int e = 0; e < 16; e++) {
            const int bufsel = e >> 2;
            const int wi = tid + (e & 3) * 128;      // 0..511
            const int row = wi >> 3, c = wi & 7;
            const uint32_t dst = base + bufsel * 8192 + SWZ((uint32_t)(row * 128 + c * 16));
            const __nv_bfloat16* src;
            if (bufsel == 0)      src = kh + (size_t)(j0 + row) * QKS + c * 8;
            else if (bufsel == 1) src = kl + (size_t)(j0 + row) * QKS + c * 8;
            else if (bufsel == 2) src = vh + (size_t)row * LL + j0 + c * 8;
            else                  src = vl + (size_t)row * LL + j0 + c * 8;
            asm volatile("cp.async.cg.shared.global [%0], [%1], 16;"
                         :: "r"(dst), "l"(src));
        }
        asm volatile("cp.async.commit_group;" ::: "memory");
    };

    issue_tile(0);

    // ---- stage Q (hi @32K, lo @48K), 128 rows x 128B each ----
    #pragma unroll
    for (int e = 0; e < 8; e++) {
        int idx = tid + e * 128;                     // 0..1023
        int row = idx >> 3, c = idx & 7;
        uint32_t sw = SWZ((uint32_t)(row * 128 + c * 16));
        *(uint4*)(smem + 32768 + sw) = *(const uint4*)(qh + (size_t)row * QKS + c * 8);
        *(uint4*)(smem + 49152 + sw) = *(const uint4*)(ql + (size_t)row * QKS + c * 8);
    }
    __syncthreads();

    // Q fragments: warp rows w*32 + half*16 + (0..15)
    uint32_t qfh[4][2][4], qfl[4][2][4];
    #pragma unroll
    for (int kk = 0; kk < 4; kk++) {
        #pragma unroll
        for (int half = 0; half < 2; half++) {
            uint32_t ab = sb + ((uint32_t)w << 12) + ((uint32_t)half << 11);
            ldsm4(qfh[kk][half][0], qfh[kk][half][1], qfh[kk][half][2], qfh[kk][half][3],
                  ab + 32768u + swzA[kk]);
            ldsm4(qfl[kk][half][0], qfl[kk][half][1], qfl[kk][half][2], qfl[kk][half][3],
                  ab + 49152u + swzA[kk]);
        }
    }
    __syncthreads();

    const float LOG2E = 1.4426950408889634f;
    float mrow[2][2], lrow[2][2];
    #pragma unroll
    for (int half = 0; half < 2; half++) {
        mrow[half][0] = -INFINITY; mrow[half][1] = -INFINITY;
        lrow[half][0] = 0.f; lrow[half][1] = 0.f;
    }
    float O[2][8][4] = {};

    for (int t = 0; t < 32; t++) {
        asm volatile("cp.async.wait_group 0;" ::: "memory");
        __syncthreads();
        if (t + 1 < 32) issue_tile(t + 1);

        const uint32_t base = sb + ((t & 1) ? 32768u : 0u);
        const uint32_t kbh = base, kbl = base + 8192u;
        const uint32_t vbh = base + 16384u, vbl = base + 24576u;

        // ---- S = Q K^T : m32 x n64, 3-pass; B frags reused across halves --
        float s[2][8][4] = {};
        #pragma unroll
        for (int kk = 0; kk < 4; kk++) {
            #pragma unroll
            for (int np = 0; np < 4; np++) {
                uint32_t b0, b1, b2, b3, c0, c1, c2, c3;
                ldsm4(b0, b1, b2, b3, kbh + ((uint32_t)np << 11) + swzB[kk]);
                ldsm4(c0, c1, c2, c3, kbl + ((uint32_t)np << 11) + swzB[kk]);
                #pragma unroll
                for (int half = 0; half < 2; half++) {
                    mma16816(s[half][2 * np],     qfh[kk][half], b0, b1);
                    mma16816(s[half][2 * np],     qfl[kk][half], b0, b1);
                    mma16816(s[half][2 * np],     qfh[kk][half], c0, c1);
                    mma16816(s[half][2 * np + 1], qfh[kk][half], b2, b3);
                    mma16816(s[half][2 * np + 1], qfl[kk][half], b2, b3);
                    mma16816(s[half][2 * np + 1], qfh[kk][half], c2, c3);
                }
            }
        }

        // ---- online softmax: 4 row-states (2 halves x 2 sub-rows) ----
        #pragma unroll
        for (int half = 0; half < 2; half++) {
            float mx0 = -INFINITY, mx1 = -INFINITY;
            #pragma unroll
            for (int tt = 0; tt < 8; tt++) {
                mx0 = fmaxf(mx0, fmaxf(s[half][tt][0], s[half][tt][1]));
                mx1 = fmaxf(mx1, fmaxf(s[half][tt][2], s[half][tt][3]));
            }
            mx0 = fmaxf(mx0, __shfl_xor_sync(0xffffffffu, mx0, 1));
            mx0 = fmaxf(mx0, __shfl_xor_sync(0xffffffffu, mx0, 2));
            mx1 = fmaxf(mx1, __shfl_xor_sync(0xffffffffu, mx1, 1));
            mx1 = fmaxf(mx1, __shfl_xor_sync(0xffffffffu, mx1, 2));

            float mn0 = fmaxf(mrow[half][0], mx0), mn1 = fmaxf(mrow[half][1], mx1);
            float a0 = exp2f((mrow[half][0] - mn0) * LOG2E);
            float a1 = exp2f((mrow[half][1] - mn1) * LOG2E);
            float rs0 = 0.f, rs1 = 0.f;
            #pragma unroll
            for (int tt = 0; tt < 8; tt++) {
                s[half][tt][0] = exp2f((s[half][tt][0] - mn0) * LOG2E);
                s[half][tt][1] = exp2f((s[half][tt][1] - mn0) * LOG2E);
                s[half][tt][2] = exp2f((s[half][tt][2] - mn1) * LOG2E);
                s[half][tt][3] = exp2f((s[half][tt][3] - mn1) * LOG2E);
                rs0 += s[half][tt][0] + s[half][tt][1];
                rs1 += s[half][tt][2] + s[half][tt][3];
            }
            rs0 += __shfl_xor_sync(0xffffffffu, rs0, 1);
            rs0 += __shfl_xor_sync(0xffffffffu, rs0, 2);
            rs1 += __shfl_xor_sync(0xffffffffu, rs1, 1);
            rs1 += __shfl_xor_sync(0xffffffffu, rs1, 2);
            lrow[half][0] = lrow[half][0] * a0 + rs0;
            lrow[half][1] = lrow[half][1] * a1 + rs1;
            mrow[half][0] = mn0; mrow[half][1] = mn1;
            #pragma unroll
            for (int tt = 0; tt < 8; tt++) {
                O[half][tt][0] *= a0; O[half][tt][1] *= a0;
                O[half][tt][2] *= a1; O[half][tt][3] *= a1;
            }
        }

        // ---- P -> A-frags hi/lo (registers) ----
        uint32_t ph[4][2][4], pl[4][2][4];
        #pragma unroll
        for (int kk = 0; kk < 4; kk++) {
            #pragma unroll
            for (int half = 0; half < 2; half++) {
                pack_pair(s[half][2 * kk][0],     s[half][2 * kk][1],     ph[kk][half][0], pl[kk][half][0]);
                pack_pair(s[half][2 * kk][2],     s[half][2 * kk][3],     ph[kk][half][1], pl[kk][half][1]);
                pack_pair(s[half][2 * kk + 1][0], s[half][2 * kk + 1][1], ph[kk][half][2], pl[kk][half][2]);
                pack_pair(s[half][2 * kk + 1][2], s[half][2 * kk + 1][3], ph[kk][half][3], pl[kk][half][3]);
            }
        }

        // ---- O += P V^T : V frags reused across halves ----
        #pragma unroll
        for (int kk = 0; kk < 4; kk++) {
            #pragma unroll
            for (int dnp = 0; dnp < 4; dnp++) {
                uint32_t b0, b1, b2, b3, c0, c1, c2, c3;
                ldsm4(b0, b1, b2, b3, vbh + ((uint32_t)dnp << 11) + swzB[kk]);
                ldsm4(c0, c1, c2, c3, vbl + ((uint32_t)dnp << 11) + swzB[kk]);
                #pragma unroll
                for (int half = 0; half < 2; half++) {
                    mma16816(O[half][2 * dnp],     ph[kk][half], b0, b1);
                    mma16816(O[half][2 * dnp],     pl[kk][half], b0, b1);
                    mma16816(O[half][2 * dnp],     ph[kk][half], c0, c1);
                    mma16816(O[half][2 * dnp + 1], ph[kk][half], b2, b3);
                    mma16816(O[half][2 * dnp + 1], pl[kk][half], b2, b3);
                    mma16816(O[half][2 * dnp + 1], ph[kk][half], c2, c3);
                }
            }
        }
    }

    // ---- normalize + write bf16 hi/lo att [b][l][512] ----
    #pragma unroll
    for (int half = 0; half < 2; half++) {
        const float inv0 = 1.0f / lrow[half][0], inv1 = 1.0f / lrow[half][1];
        const int r0 = i0 + 32 * w + 16 * half + (lane >> 2);
        size_t o0 = ((size_t)b * LL + r0) * HID + h * DD + 2 * (lane & 3);
        size_t o1 = o0 + (size_t)8 * HID;
        #pragma unroll
        for (int tt = 0; tt < 8; tt++) {
            uint32_t h0, lo0, h1, lo1;
            pack_pair(O[half][tt][0] * inv0, O[half][tt][1] * inv0, h0, lo0);
            pack_pair(O[half][tt][2] * inv1, O[half][tt][3] * inv1, h1, lo1);
            *(uint32_t*)&g_att_hi[o0 + 8 * tt] = h0;
            *(uint32_t*)&g_att_lo[o0 + 8 * tt] = lo0;
            *(uint32_t*)&g_att_hi[o1 + 8 * tt] = h1;
            *(uint32_t*)&g_att_lo[o1 + 8 * tt] = lo1;
        }
    }
}

// ---------------------------------------------------------------------------
extern "C" void kernel_launch(void* const* d_in, const int* in_sizes, int n_in,
                              void* d_out, int out_size)
{
    const float* x     = (const float*)d_in[0];
    const float* w_qkv = (const float*)d_in[1];
    const float* w_out = (const float*)d_in[2];
    const float* b_out = (const float*)d_in[3];
    float* out = (float*)d_out;

    __nv_bfloat16 *wq_h, *wq_l, *wo_h, *wo_l, *xt_h, *xt_l;
    __nv_bfloat16 *qk_h, *qk_l, *v_h, *v_l, *at_h, *at_l;
    cudaGetSymbolAddress((void**)&wq_h, g_wq_hi);
    cudaGetSymbolAddress((void**)&wq_l, g_wq_lo);
    cudaGetSymbolAddress((void**)&wo_h, g_wo_hi);
    cudaGetSymbolAddress((void**)&wo_l, g_wo_lo);
    cudaGetSymbolAddress((void**)&xt_h, g_xT_hi);
    cudaGetSymbolAddress((void**)&xt_l, g_xT_lo);
    cudaGetSymbolAddress((void**)&qk_h, g_qk_hi);
    cudaGetSymbolAddress((void**)&qk_l, g_qk_lo);
    cudaGetSymbolAddress((void**)&v_h,  g_v_hi);
    cudaGetSymbolAddress((void**)&v_l,  g_v_lo);
    cudaGetSymbolAddress((void**)&at_h, g_att_hi);
    cudaGetSymbolAddress((void**)&at_l, g_att_lo);

    const int GEMM_SMEM = 98304;
    const int ATTN_SMEM = 65536;
    cudaFuncSetAttribute(mma_gemm<0>, cudaFuncAttributeMaxDynamicSharedMemorySize, GEMM_SMEM);
    cudaFuncSetAttribute(mma_gemm<1>, cudaFuncAttributeMaxDynamicSharedMemorySize, GEMM_SMEM);
    cudaFuncSetAttribute(attn_kernel, cudaFuncAttributeMaxDynamicSharedMemorySize, ATTN_SMEM);

    conv_w<<<(MQKV * CC + CC * HID) / 256, 256>>>(w_qkv, w_out);
    conv_x<<<dim3(LL / 32, CC / 32, BB), dim3(32, 8)>>>(x);

    // L1: C[l][qk_ch] = xT * wq(rows 0..1023)^T  -> g_qk
    mma_gemm<0><<<dim3(QKS / 64, LL / 128, BB), 256, GEMM_SMEM>>>(
        xt_h, xt_l, (size_t)LL * CC, wq_h, wq_l, 0,
        qk_h, qk_l, nullptr, nullptr, (size_t)LL * QKS, QKS, CC, CC / 64);

    // L2: C[v_ch][l] = wq(rows 1024..1535) * xT^T -> g_v
    mma_gemm<0><<<dim3(LL / 64, HID / 128, BB), 256, GEMM_SMEM>>>(
        wq_h + 1024 * CC, wq_l + 1024 * CC, 0, xt_h, xt_l, (size_t)LL * CC,
        v_h, v_l, nullptr, nullptr, (size_t)HID * LL, LL, CC, CC / 64);

    attn_kernel<<<dim3(LL / 128, BB * HH), 128, ATTN_SMEM>>>();

    // L3: out[ch][l] = w_out * att^T + bias
    mma_gemm<1><<<dim3(LL / 64, CC / 128, BB), 256, GEMM_SMEM>>>(
        wo_h, wo_l, 0, at_h, at_l, (size_t)LL * HID,
        nullptr, nullptr, out, b_out, (size_t)CC * LL, LL, HID, HID / 64);
}

// round 7
// speedup vs baseline: 4.1216x; 1.0962x over previous
#include <cuda_runtime.h>
#include <cuda_bf16.h>
#include <math.h>
#include <stdint.h>

#define BB   4
#define CC   256
#define LL   2048
#define HH   8
#define DD   64
#define HID  512
#define MQKV 1536
#define QKS  1024   // fused q|k channel stride

// ---------------- scratch (allocation-free rule: __device__ globals) -------
__device__ __align__(16) __nv_bfloat16 g_wq_hi[MQKV * CC];
__device__ __align__(16) __nv_bfloat16 g_wq_lo[MQKV * CC];
__device__ __align__(16) __nv_bfloat16 g_wo_hi[CC * HID];
__device__ __align__(16) __nv_bfloat16 g_wo_lo[CC * HID];
__device__ __align__(16) __nv_bfloat16 g_xT_hi[(size_t)BB * LL * CC];
__device__ __align__(16) __nv_bfloat16 g_xT_lo[(size_t)BB * LL * CC];
__device__ __align__(16) __nv_bfloat16 g_qk_hi[(size_t)BB * LL * QKS];
__device__ __align__(16) __nv_bfloat16 g_qk_lo[(size_t)BB * LL * QKS];
__device__ __align__(16) __nv_bfloat16 g_v_hi[(size_t)BB * HID * LL];
__device__ __align__(16) __nv_bfloat16 g_v_lo[(size_t)BB * HID * LL];
__device__ __align__(16) __nv_bfloat16 g_att_hi[(size_t)BB * LL * HID];
__device__ __align__(16) __nv_bfloat16 g_att_lo[(size_t)BB * LL * HID];

#define SWZ(x) ((x) ^ (((x) >> 3) & 0x70))

// ---------------- warp-MMA helpers -----------------------------------------
__device__ __forceinline__ uint32_t smem_u32(const void* p) {
    uint32_t a;
    asm("{ .reg .u64 t; cvta.to.shared.u64 t, %1; cvt.u32.u64 %0, t; }"
        : "=r"(a) : "l"(p));
    return a;
}
__device__ __forceinline__ void ldsm4(uint32_t& r0, uint32_t& r1, uint32_t& r2,
                                      uint32_t& r3, uint32_t a) {
    asm volatile("ldmatrix.sync.aligned.m8n8.x4.shared.b16 {%0,%1,%2,%3}, [%4];"
                 : "=r"(r0), "=r"(r1), "=r"(r2), "=r"(r3) : "r"(a));
}
__device__ __forceinline__ void mma16816(float* c, const uint32_t* a,
                                         uint32_t b0, uint32_t b1) {
    asm volatile("mma.sync.aligned.m16n8k16.row.col.f32.bf16.bf16.f32 "
                 "{%0,%1,%2,%3}, {%4,%5,%6,%7}, {%8,%9}, {%0,%1,%2,%3};"
                 : "+f"(c[0]), "+f"(c[1]), "+f"(c[2]), "+f"(c[3])
                 : "r"(a[0]), "r"(a[1]), "r"(a[2]), "r"(a[3]), "r"(b0), "r"(b1));
}
__device__ __forceinline__ uint32_t cvt2bf(float p0, float p1) {
    uint32_t r;
    asm("cvt.rn.bf16x2.f32 %0, %1, %2;" : "=r"(r) : "f"(p1), "f"(p0));
    return r;
}
__device__ __forceinline__ void pack_pair(float p0, float p1,
                                          uint32_t& hi, uint32_t& lo) {
    hi = cvt2bf(p0, p1);
    float f0 = __uint_as_float(hi << 16);
    float f1 = __uint_as_float(hi & 0xffff0000u);
    lo = cvt2bf(p0 - f0, p1 - f1);
}
__device__ __forceinline__ void split_bf16(float x, __nv_bfloat16& h, __nv_bfloat16& l) {
    h = __float2bfloat16(x);
    l = __float2bfloat16(x - __bfloat162float(h));
}
__device__ __forceinline__ float ex2(float x) {
    float y;
    asm("ex2.approx.ftz.f32 %0, %1;" : "=f"(y) : "f"(x));
    return y;
}

// ---------------------------------------------------------------------------
// conv_w / conv_x (unchanged)
// ---------------------------------------------------------------------------
__global__ void conv_w(const float* __restrict__ wq, const float* __restrict__ wo)
{
    const int NQ = MQKV * CC;
    int idx = blockIdx.x * 256 + threadIdx.x;
    if (idx < NQ) {
        float v = wq[idx];
        if (idx < 512 * CC) v *= 0.125f;
        __nv_bfloat16 h, l;
        split_bf16(v, h, l);
        g_wq_hi[idx] = h; g_wq_lo[idx] = l;
    } else {
        int j = idx - NQ;
        if (j < CC * HID) {
            __nv_bfloat16 h, l;
            split_bf16(wo[j], h, l);
            g_wo_hi[j] = h; g_wo_lo[j] = l;
        }
    }
}

__global__ void conv_x(const float* __restrict__ x)
{
    __shared__ float t[32][33];
    const int b = blockIdx.z;
    const int c0 = blockIdx.y * 32, l0 = blockIdx.x * 32;
    const int tx = threadIdx.x, ty = threadIdx.y;
    const float* xb = x + ((size_t)b * CC + c0) * LL + l0;
    #pragma unroll
    for (int i = 0; i < 4; i++)
        t[ty + 8 * i][tx] = xb[(size_t)(ty + 8 * i) * LL + tx];
    __syncthreads();
    #pragma unroll
    for (int i = 0; i < 4; i++) {
        int row = ty + 8 * i;
        float v = t[tx][row];
        __nv_bfloat16 h, l2;
        split_bf16(v, h, l2);
        size_t o = ((size_t)b * LL + l0 + row) * CC + c0 + tx;
        g_xT_hi[o] = h; g_xT_lo[o] = l2;
    }
}

// ---------------------------------------------------------------------------
// Generic bf16-split MMA GEMM (unchanged from R5/R6)
// ---------------------------------------------------------------------------
template<int MODE>
__global__ void __launch_bounds__(256, 1) mma_gemm(
    const __nv_bfloat16* __restrict__ Ah, const __nv_bfloat16* __restrict__ Al, size_t sA,
    const __nv_bfloat16* __restrict__ Bh, const __nv_bfloat16* __restrict__ Bl, size_t sB,
    __nv_bfloat16* Yh, __nv_bfloat16* Yl, float* Yf, const float* bias, size_t sY,
    int N, int K, int nkc)
{
    extern __shared__ __align__(1024) char smem[];
    const uint32_t sb = smem_u32(smem);
    const int tid = threadIdx.x;
    const int lane = tid & 31, w = tid >> 5;
    const int b  = blockIdx.z;
    const int m0 = blockIdx.y * 128;
    const int n0 = blockIdx.x * 64;

    const __nv_bfloat16* Ahb = Ah + (size_t)b * sA;
    const __nv_bfloat16* Alb = Al + (size_t)b * sA;
    const __nv_bfloat16* Bhb = Bh + (size_t)b * sB;
    const __nv_bfloat16* Blb = Bl + (size_t)b * sB;

    const int g = lane >> 3;
    const int rowB = ((g & 2) ? 8 : 0) + (lane & 7);
    const int bytB = (g & 1) * 16;
    const int rowA = lane & 15;
    const int bytA = (lane >> 4) * 16;
    uint32_t swzB[4], swzA[4];
    #pragma unroll
    for (int kk = 0; kk < 4; kk++) {
        swzB[kk] = SWZ((uint32_t)(rowB * 128 + bytB + kk * 32));
        swzA[kk] = SWZ((uint32_t)(rowA * 128 + bytA + kk * 32));
    }

    auto issue = [&](int kc) {
        const uint32_t base = sb + (uint32_t)(kc & 1) * 49152u;
        const int koff = kc * 64;
        #pragma unroll
        for (int e = 0; e < 4; e++) {
            int wi = tid + e * 256;
            int row = wi >> 3, c = wi & 7;
            uint32_t sw = SWZ((uint32_t)(row * 128 + c * 16));
            const __nv_bfloat16* s0 = Ahb + (size_t)(m0 + row) * K + koff + c * 8;
            const __nv_bfloat16* s1 = Alb + (size_t)(m0 + row) * K + koff + c * 8;
            asm volatile("cp.async.cg.shared.global [%0], [%1], 16;" :: "r"(base + sw), "l"(s0));
            asm volatile("cp.async.cg.shared.global [%0], [%1], 16;" :: "r"(base + 16384u + sw), "l"(s1));
        }
        #pragma unroll
        for (int e = 0; e < 2; e++) {
            int wi = tid + e * 256;
            int row = wi >> 3, c = wi & 7;
            uint32_t sw = SWZ((uint32_t)(row * 128 + c * 16));
            const __nv_bfloat16* s0 = Bhb + (size_t)(n0 + row) * K + koff + c * 8;
            const __nv_bfloat16* s1 = Blb + (size_t)(n0 + row) * K + koff + c * 8;
            asm volatile("cp.async.cg.shared.global [%0], [%1], 16;" :: "r"(base + 32768u + sw), "l"(s0));
            asm volatile("cp.async.cg.shared.global [%0], [%1], 16;" :: "r"(base + 40960u + sw), "l"(s1));
        }
        asm volatile("cp.async.commit_group;" ::: "memory");
    };

    issue(0);

    float s[8][4] = {};

    for (int kc = 0; kc < nkc; kc++) {
        asm volatile("cp.async.wait_group 0;" ::: "memory");
        __syncthreads();
        if (kc + 1 < nkc) issue(kc + 1);

        const uint32_t base = sb + (uint32_t)(kc & 1) * 49152u;
        const uint32_t ab = base + ((uint32_t)w << 11);

        #pragma unroll
        for (int kk = 0; kk < 4; kk++) {
            uint32_t ah[4], al[4];
            ldsm4(ah[0], ah[1], ah[2], ah[3], ab + swzA[kk]);
            ldsm4(al[0], al[1], al[2], al[3], ab + 16384u + swzA[kk]);
            #pragma unroll
            for (int np = 0; np < 4; np++) {
                uint32_t b0, b1, b2, b3, c0, c1, c2, c3;
                ldsm4(b0, b1, b2, b3, base + 32768u + ((uint32_t)np << 11) + swzB[kk]);
                ldsm4(c0, c1, c2, c3, base + 40960u + ((uint32_t)np << 11) + swzB[kk]);
                mma16816(s[2 * np],     ah, b0, b1);
                mma16816(s[2 * np],     al, b0, b1);
                mma16816(s[2 * np],     ah, c0, c1);
                mma16816(s[2 * np + 1], ah, b2, b3);
                mma16816(s[2 * np + 1], al, b2, b3);
                mma16816(s[2 * np + 1], ah, c2, c3);
            }
        }
        __syncthreads();
    }

    const int mr = m0 + w * 16 + (lane >> 2);
    const int nc = n0 + 2 * (lane & 3);
    if (MODE == 0) {
        __nv_bfloat16* Yhb = Yh + (size_t)b * sY;
        __nv_bfloat16* Ylb = Yl + (size_t)b * sY;
        #pragma unroll
        for (int tt = 0; tt < 8; tt++) {
            uint32_t h0, l0, h1, l1;
            pack_pair(s[tt][0], s[tt][1], h0, l0);
            pack_pair(s[tt][2], s[tt][3], h1, l1);
            size_t o0 = (size_t)mr * N + nc + 8 * tt;
            size_t o1 = (size_t)(mr + 8) * N + nc + 8 * tt;
            *(uint32_t*)&Yhb[o0] = h0; *(uint32_t*)&Ylb[o0] = l0;
            *(uint32_t*)&Yhb[o1] = h1; *(uint32_t*)&Ylb[o1] = l1;
        }
    } else {
        float* Yfb = Yf + (size_t)b * sY;
        const float bv0 = bias[mr], bv1 = bias[mr + 8];
        #pragma unroll
        for (int tt = 0; tt < 8; tt++) {
            float2 v0, v1;
            v0.x = s[tt][0] + bv0; v0.y = s[tt][1] + bv0;
            v1.x = s[tt][2] + bv1; v1.y = s[tt][3] + bv1;
            *(float2*)(Yfb + (size_t)mr * N + nc + 8 * tt)       = v0;
            *(float2*)(Yfb + (size_t)(mr + 8) * N + nc + 8 * tt) = v1;
        }
    }
}

// ---------------------------------------------------------------------------
// Flash attention, software-pipelined: softmax(t) || S(t+1) || PV(t).
// CTA = 8 warps x m16n64 = 128 queries. 3-stage K/V smem ring (prefetch
// distance 2) + persistent Q. PV is 2-pass (P_hi only). Smem = 128 KB.
// smem map: QH 0 | QL 16K | buf_i @ 32K+i*32K : {KH 0|KL 8K|VH 16K|VL 24K}
// ---------------------------------------------------------------------------
__global__ void __launch_bounds__(256, 1) attn_kernel()
{
    extern __shared__ __align__(1024) char smem[];
    const uint32_t sb = smem_u32(smem);
    const int tid = threadIdx.x;
    const int lane = tid & 31, w = tid >> 5;
    const int bh = blockIdx.y;
    const int b = bh >> 3, h = bh & 7;
    const int i0 = blockIdx.x * 128;

    const __nv_bfloat16* qh = g_qk_hi + ((size_t)b * LL + i0) * QKS + h * DD;
    const __nv_bfloat16* ql = g_qk_lo + ((size_t)b * LL + i0) * QKS + h * DD;
    const __nv_bfloat16* kh = g_qk_hi + (size_t)b * LL * QKS + 512 + h * DD;
    const __nv_bfloat16* kl = g_qk_lo + (size_t)b * LL * QKS + 512 + h * DD;
    const __nv_bfloat16* vh = g_v_hi + ((size_t)b * HID + h * DD) * LL;
    const __nv_bfloat16* vl = g_v_lo + ((size_t)b * HID + h * DD) * LL;

    const int g = lane >> 3;
    const int rowB = ((g & 2) ? 8 : 0) + (lane & 7);
    const int bytB = (g & 1) * 16;
    const int rowA = lane & 15;
    const int bytA = (lane >> 4) * 16;
    uint32_t swzB[4], swzA[4];
    #pragma unroll
    for (int kk = 0; kk < 4; kk++) {
        swzB[kk] = SWZ((uint32_t)(rowB * 128 + bytB + kk * 32));
        swzA[kk] = SWZ((uint32_t)(rowA * 128 + bytA + kk * 32));
    }

    // ring buffer base for tile jt
    auto bufbase = [&](int jt) -> uint32_t {
        int sel = jt % 3;
        return sb + 32768u + (uint32_t)sel * 32768u;
    };

    // cp.async one 64-key K/V tile (hi+lo, 32KB) into ring slot
    auto issue_tile = [&](int jt) {
        const int j0 = jt * 64;
        const uint32_t base = bufbase(jt);
        #pragma unroll
        for (int e = 0; e < 8; e++) {
            const int bufsel = e >> 1;
            const int wi = tid + (e & 1) * 256;      // 0..511
            const int row = wi >> 3, c = wi & 7;
            const uint32_t dst = base + bufsel * 8192 + SWZ((uint32_t)(row * 128 + c * 16));
            const __nv_bfloat16* src;
            if (bufsel == 0)      src = kh + (size_t)(j0 + row) * QKS + c * 8;
            else if (bufsel == 1) src = kl + (size_t)(j0 + row) * QKS + c * 8;
            else if (bufsel == 2) src = vh + (size_t)row * LL + j0 + c * 8;
            else                  src = vl + (size_t)row * LL + j0 + c * 8;
            asm volatile("cp.async.cg.shared.global [%0], [%1], 16;"
                         :: "r"(dst), "l"(src));
        }
        asm volatile("cp.async.commit_group;" ::: "memory");
    };

    issue_tile(0);
    issue_tile(1);

    // ---- stage Q (persistent: hi @0, lo @16K) ----
    #pragma unroll
    for (int e = 0; e < 4; e++) {
        int idx = tid + e * 256;                     // 0..1023
        int row = idx >> 3, c = idx & 7;
        uint32_t sw = SWZ((uint32_t)(row * 128 + c * 16));
        *(uint4*)(smem + sw)         = *(const uint4*)(qh + (size_t)row * QKS + c * 8);
        *(uint4*)(smem + 16384 + sw) = *(const uint4*)(ql + (size_t)row * QKS + c * 8);
    }
    __syncthreads();
    uint32_t qfh[4][4], qfl[4][4];
    #pragma unroll
    for (int kk = 0; kk < 4; kk++) {
        ldsm4(qfh[kk][0], qfh[kk][1], qfh[kk][2], qfh[kk][3],
              sb + ((uint32_t)w << 11) + swzA[kk]);
        ldsm4(qfl[kk][0], qfl[kk][1], qfl[kk][2], qfl[kk][3],
              sb + 16384u + ((uint32_t)w << 11) + swzA[kk]);
    }

    const float LOG2E = 1.4426950408889634f;
    float m0 = -INFINITY, m1 = -INFINITY, l0 = 0.f, l1 = 0.f;
    float O[8][4] = {};
    float sA[8][4], sB[8][4];

    // S MMAs for one tile into the given accumulator set
    auto do_S = [&](uint32_t base, float (&s)[8][4]) {
        #pragma unroll
        for (int tt = 0; tt < 8; tt++) {
            s[tt][0] = 0.f; s[tt][1] = 0.f; s[tt][2] = 0.f; s[tt][3] = 0.f;
        }
        #pragma unroll
        for (int kk = 0; kk < 4; kk++) {
            #pragma unroll
            for (int np = 0; np < 4; np++) {
                uint32_t b0, b1, b2, b3, c0, c1, c2, c3;
                ldsm4(b0, b1, b2, b3, base + ((uint32_t)np << 11) + swzB[kk]);
                ldsm4(c0, c1, c2, c3, base + 8192u + ((uint32_t)np << 11) + swzB[kk]);
                mma16816(s[2 * np],     qfh[kk], b0, b1);
                mma16816(s[2 * np],     qfl[kk], b0, b1);
                mma16816(s[2 * np],     qfh[kk], c0, c1);
                mma16816(s[2 * np + 1], qfh[kk], b2, b3);
                mma16816(s[2 * np + 1], qfl[kk], b2, b3);
                mma16816(s[2 * np + 1], qfh[kk], c2, c3);
            }
        }
    };

    // one pipelined iteration: softmax(t) on sCur, S(t+1) into sNxt, PV(t)
    auto body = [&](int t, float (&sCur)[8][4], float (&sNxt)[8][4]) {
        __syncthreads();                       // all warps done with buf[(t+2)%3] reads
        if (t + 2 < 32) {
            issue_tile(t + 2);
            asm volatile("cp.async.wait_group 1;" ::: "memory");  // tile t+1 landed
        } else {
            asm volatile("cp.async.wait_group 0;" ::: "memory");
        }
        __syncthreads();                       // tile t+1 visible to all warps

        // ---- softmax on sCur ----
        float mx0 = -INFINITY, mx1 = -INFINITY;
        #pragma unroll
        for (int tt = 0; tt < 8; tt++) {
            mx0 = fmaxf(mx0, fmaxf(sCur[tt][0], sCur[tt][1]));
            mx1 = fmaxf(mx1, fmaxf(sCur[tt][2], sCur[tt][3]));
        }
        mx0 = fmaxf(mx0, __shfl_xor_sync(0xffffffffu, mx0, 1));
        mx0 = fmaxf(mx0, __shfl_xor_sync(0xffffffffu, mx0, 2));
        mx1 = fmaxf(mx1, __shfl_xor_sync(0xffffffffu, mx1, 1));
        mx1 = fmaxf(mx1, __shfl_xor_sync(0xffffffffu, mx1, 2));

        float mn0 = fmaxf(m0, mx0), mn1 = fmaxf(m1, mx1);
        float a0 = ex2((m0 - mn0) * LOG2E), a1 = ex2((m1 - mn1) * LOG2E);
        float rs0 = 0.f, rs1 = 0.f;
        #pragma unroll
        for (int tt = 0; tt < 8; tt++) {
            sCur[tt][0] = ex2((sCur[tt][0] - mn0) * LOG2E);
            sCur[tt][1] = ex2((sCur[tt][1] - mn0) * LOG2E);
            sCur[tt][2] = ex2((sCur[tt][2] - mn1) * LOG2E);
            sCur[tt][3] = ex2((sCur[tt][3] - mn1) * LOG2E);
            rs0 += sCur[tt][0] + sCur[tt][1];
            rs1 += sCur[tt][2] + sCur[tt][3];
        }
        rs0 += __shfl_xor_sync(0xffffffffu, rs0, 1);
        rs0 += __shfl_xor_sync(0xffffffffu, rs0, 2);
        rs1 += __shfl_xor_sync(0xffffffffu, rs1, 1);
        rs1 += __shfl_xor_sync(0xffffffffu, rs1, 2);
        l0 = l0 * a0 + rs0; l1 = l1 * a1 + rs1;
        m0 = mn0; m1 = mn1;
        #pragma unroll
        for (int tt = 0; tt < 8; tt++) {
            O[tt][0] *= a0; O[tt][1] *= a0;
            O[tt][2] *= a1; O[tt][3] *= a1;
        }

        // ---- P (hi only) A-frags ----
        uint32_t p[4][4];
        #pragma unroll
        for (int kk = 0; kk < 4; kk++) {
            p[kk][0] = cvt2bf(sCur[2 * kk][0],     sCur[2 * kk][1]);
            p[kk][1] = cvt2bf(sCur[2 * kk][2],     sCur[2 * kk][3]);
            p[kk][2] = cvt2bf(sCur[2 * kk + 1][0], sCur[2 * kk + 1][1]);
            p[kk][3] = cvt2bf(sCur[2 * kk + 1][2], sCur[2 * kk + 1][3]);
        }

        // ---- S(t+1): independent MMA stream that overlaps the softmax chain
        if (t + 1 < 32) do_S(bufbase(t + 1), sNxt);

        // ---- PV(t): 2-pass (P_hi x V_hi + P_hi x V_lo) ----
        const uint32_t vb = bufbase(t) + 16384u;
        #pragma unroll
        for (int kk = 0; kk < 4; kk++) {
            #pragma unroll
            for (int dnp = 0; dnp < 4; dnp++) {
                uint32_t b0, b1, b2, b3, c0, c1, c2, c3;
                ldsm4(b0, b1, b2, b3, vb + ((uint32_t)dnp << 11) + swzB[kk]);
                ldsm4(c0, c1, c2, c3, vb + 8192u + ((uint32_t)dnp << 11) + swzB[kk]);
                mma16816(O[2 * dnp],     p[kk], b0, b1);
                mma16816(O[2 * dnp],     p[kk], c0, c1);
                mma16816(O[2 * dnp + 1], p[kk], b2, b3);
                mma16816(O[2 * dnp + 1], p[kk], c2, c3);
            }
        }
    };

    // ---- prologue: wait tile0, compute S(0) ----
    asm volatile("cp.async.wait_group 1;" ::: "memory");  // tile0 done (tile1 pending)
    __syncthreads();
    do_S(bufbase(0), sA);

    // ---- main loop, unrolled by 2 to keep sA/sB in registers ----
    for (int tt = 0; tt < 16; tt++) {
        body(2 * tt,     sA, sB);
        body(2 * tt + 1, sB, sA);
    }

    // ---- normalize + write bf16 hi/lo att [b][l][512] ----
    const float inv0 = 1.0f / l0, inv1 = 1.0f / l1;
    const int r0 = i0 + 16 * w + (lane >> 2);
    size_t o0 = ((size_t)b * LL + r0) * HID + h * DD + 2 * (lane & 3);
    size_t o1 = o0 + (size_t)8 * HID;
    #pragma unroll
    for (int tt = 0; tt < 8; tt++) {
        uint32_t h0, lo0, h1, lo1;
        pack_pair(O[tt][0] * inv0, O[tt][1] * inv0, h0, lo0);
        pack_pair(O[tt][2] * inv1, O[tt][3] * inv1, h1, lo1);
        *(uint32_t*)&g_att_hi[o0 + 8 * tt] = h0;
        *(uint32_t*)&g_att_lo[o0 + 8 * tt] = lo0;
        *(uint32_t*)&g_att_hi[o1 + 8 * tt] = h1;
        *(uint32_t*)&g_att_lo[o1 + 8 * tt] = lo1;
    }
}

// ---------------------------------------------------------------------------
extern "C" void kernel_launch(void* const* d_in, const int* in_sizes, int n_in,
                              void* d_out, int out_size)
{
    const float* x     = (const float*)d_in[0];
    const float* w_qkv = (const float*)d_in[1];
    const float* w_out = (const float*)d_in[2];
    const float* b_out = (const float*)d_in[3];
    float* out = (float*)d_out;

    __nv_bfloat16 *wq_h, *wq_l, *wo_h, *wo_l, *xt_h, *xt_l;
    __nv_bfloat16 *qk_h, *qk_l, *v_h, *v_l, *at_h, *at_l;
    cudaGetSymbolAddress((void**)&wq_h, g_wq_hi);
    cudaGetSymbolAddress((void**)&wq_l, g_wq_lo);
    cudaGetSymbolAddress((void**)&wo_h, g_wo_hi);
    cudaGetSymbolAddress((void**)&wo_l, g_wo_lo);
    cudaGetSymbolAddress((void**)&xt_h, g_xT_hi);
    cudaGetSymbolAddress((void**)&xt_l, g_xT_lo);
    cudaGetSymbolAddress((void**)&qk_h, g_qk_hi);
    cudaGetSymbolAddress((void**)&qk_l, g_qk_lo);
    cudaGetSymbolAddress((void**)&v_h,  g_v_hi);
    cudaGetSymbolAddress((void**)&v_l,  g_v_lo);
    cudaGetSymbolAddress((void**)&at_h, g_att_hi);
    cudaGetSymbolAddress((void**)&at_l, g_att_lo);

    const int GEMM_SMEM = 98304;
    const int ATTN_SMEM = 131072;   // Q 32K + 3 ring buffers x 32K
    cudaFuncSetAttribute(mma_gemm<0>, cudaFuncAttributeMaxDynamicSharedMemorySize, GEMM_SMEM);
    cudaFuncSetAttribute(mma_gemm<1>, cudaFuncAttributeMaxDynamicSharedMemorySize, GEMM_SMEM);
    cudaFuncSetAttribute(attn_kernel, cudaFuncAttributeMaxDynamicSharedMemorySize, ATTN_SMEM);

    conv_w<<<(MQKV * CC + CC * HID) / 256, 256>>>(w_qkv, w_out);
    conv_x<<<dim3(LL / 32, CC / 32, BB), dim3(32, 8)>>>(x);

    // L1: C[l][qk_ch] = xT * wq(rows 0..1023)^T  -> g_qk
    mma_gemm<0><<<dim3(QKS / 64, LL / 128, BB), 256, GEMM_SMEM>>>(
        xt_h, xt_l, (size_t)LL * CC, wq_h, wq_l, 0,
        qk_h, qk_l, nullptr, nullptr, (size_t)LL * QKS, QKS, CC, CC / 64);

    // L2: C[v_ch][l] = wq(rows 1024..1535) * xT^T -> g_v
    mma_gemm<0><<<dim3(LL / 64, HID / 128, BB), 256, GEMM_SMEM>>>(
        wq_h + 1024 * CC, wq_l + 1024 * CC, 0, xt_h, xt_l, (size_t)LL * CC,
        v_h, v_l, nullptr, nullptr, (size_t)HID * LL, LL, CC, CC / 64);

    attn_kernel<<<dim3(LL / 128, BB * HH), 256, ATTN_SMEM>>>();

    // L3: out[ch][l] = w_out * att^T + bias
    mma_gemm<1><<<dim3(LL / 64, CC / 128, BB), 256, GEMM_SMEM>>>(
        wo_h, wo_l, 0, at_h, at_l, (size_t)LL * HID,
        nullptr, nullptr, out, b_out, (size_t)CC * LL, LL, HID, HID / 64);
}

// round 8
// speedup vs baseline: 4.3116x; 1.0461x over previous
#include <cuda_runtime.h>
#include <cuda_bf16.h>
#include <cuda_fp16.h>
#include <math.h>
#include <stdint.h>

#define BB   4
#define CC   256
#define LL   2048
#define HH   8
#define DD   64
#define HID  512
#define MQKV 1536
#define QKS  1024   // fused q|k channel stride

// ---------------- scratch (allocation-free rule: __device__ globals) -------
__device__ __align__(16) __nv_bfloat16 g_wq_hi[MQKV * CC];
__device__ __align__(16) __nv_bfloat16 g_wq_lo[MQKV * CC];
__device__ __align__(16) __nv_bfloat16 g_wo_hi[CC * HID];
__device__ __align__(16) __nv_bfloat16 g_wo_lo[CC * HID];
__device__ __align__(16) __nv_bfloat16 g_xT_hi[(size_t)BB * LL * CC];
__device__ __align__(16) __nv_bfloat16 g_xT_lo[(size_t)BB * LL * CC];
__device__ __align__(16) __nv_bfloat16 g_qk_hi[(size_t)BB * LL * QKS];
__device__ __align__(16) __nv_bfloat16 g_qk_lo[(size_t)BB * LL * QKS];
__device__ __align__(16) __half        g_v_hi[(size_t)BB * HID * LL];   // fp16!
__device__ __align__(16) __half        g_v_lo[(size_t)BB * HID * LL];
__device__ __align__(16) __nv_bfloat16 g_att_hi[(size_t)BB * LL * HID];
__device__ __align__(16) __nv_bfloat16 g_att_lo[(size_t)BB * LL * HID];

#define SWZ(x) ((x) ^ (((x) >> 3) & 0x70))

// ---------------- warp-MMA helpers -----------------------------------------
__device__ __forceinline__ uint32_t smem_u32(const void* p) {
    uint32_t a;
    asm("{ .reg .u64 t; cvta.to.shared.u64 t, %1; cvt.u32.u64 %0, t; }"
        : "=r"(a) : "l"(p));
    return a;
}
__device__ __forceinline__ void ldsm4(uint32_t& r0, uint32_t& r1, uint32_t& r2,
                                      uint32_t& r3, uint32_t a) {
    asm volatile("ldmatrix.sync.aligned.m8n8.x4.shared.b16 {%0,%1,%2,%3}, [%4];"
                 : "=r"(r0), "=r"(r1), "=r"(r2), "=r"(r3) : "r"(a));
}
__device__ __forceinline__ void mma16816(float* c, const uint32_t* a,
                                         uint32_t b0, uint32_t b1) {
    asm volatile("mma.sync.aligned.m16n8k16.row.col.f32.bf16.bf16.f32 "
                 "{%0,%1,%2,%3}, {%4,%5,%6,%7}, {%8,%9}, {%0,%1,%2,%3};"
                 : "+f"(c[0]), "+f"(c[1]), "+f"(c[2]), "+f"(c[3])
                 : "r"(a[0]), "r"(a[1]), "r"(a[2]), "r"(a[3]), "r"(b0), "r"(b1));
}
__device__ __forceinline__ void mma16816h(float* c, const uint32_t* a,
                                          uint32_t b0, uint32_t b1) {
    asm volatile("mma.sync.aligned.m16n8k16.row.col.f32.f16.f16.f32 "
                 "{%0,%1,%2,%3}, {%4,%5,%6,%7}, {%8,%9}, {%0,%1,%2,%3};"
                 : "+f"(c[0]), "+f"(c[1]), "+f"(c[2]), "+f"(c[3])
                 : "r"(a[0]), "r"(a[1]), "r"(a[2]), "r"(a[3]), "r"(b0), "r"(b1));
}
__device__ __forceinline__ uint32_t cvt2bf(float p0, float p1) {
    uint32_t r;
    asm("cvt.rn.bf16x2.f32 %0, %1, %2;" : "=r"(r) : "f"(p1), "f"(p0));
    return r;
}
__device__ __forceinline__ uint32_t cvt2f16(float p0, float p1) {
    uint32_t r;
    asm("cvt.rn.f16x2.f32 %0, %1, %2;" : "=r"(r) : "f"(p1), "f"(p0));
    return r;
}
__device__ __forceinline__ void pack_pair(float p0, float p1,
                                          uint32_t& hi, uint32_t& lo) {
    hi = cvt2bf(p0, p1);
    float f0 = __uint_as_float(hi << 16);
    float f1 = __uint_as_float(hi & 0xffff0000u);
    lo = cvt2bf(p0 - f0, p1 - f1);
}
__device__ __forceinline__ void pack_pair_f16(float p0, float p1,
                                              uint32_t& hi, uint32_t& lo) {
    hi = cvt2f16(p0, p1);
    __half2 h2 = *reinterpret_cast<__half2*>(&hi);
    float f0 = __half2float(h2.x);   // low  = p0
    float f1 = __half2float(h2.y);   // high = p1
    lo = cvt2f16(p0 - f0, p1 - f1);
}
__device__ __forceinline__ void split_bf16(float x, __nv_bfloat16& h, __nv_bfloat16& l) {
    h = __float2bfloat16(x);
    l = __float2bfloat16(x - __bfloat162float(h));
}
__device__ __forceinline__ float ex2(float x) {
    float y;
    asm("ex2.approx.ftz.f32 %0, %1;" : "=f"(y) : "f"(x));
    return y;
}

// ---------------------------------------------------------------------------
// conv_w / conv_x (unchanged)
// ---------------------------------------------------------------------------
__global__ void conv_w(const float* __restrict__ wq, const float* __restrict__ wo)
{
    const int NQ = MQKV * CC;
    int idx = blockIdx.x * 256 + threadIdx.x;
    if (idx < NQ) {
        float v = wq[idx];
        if (idx < 512 * CC) v *= 0.125f;
        __nv_bfloat16 h, l;
        split_bf16(v, h, l);
        g_wq_hi[idx] = h; g_wq_lo[idx] = l;
    } else {
        int j = idx - NQ;
        if (j < CC * HID) {
            __nv_bfloat16 h, l;
            split_bf16(wo[j], h, l);
            g_wo_hi[j] = h; g_wo_lo[j] = l;
        }
    }
}

__global__ void conv_x(const float* __restrict__ x)
{
    __shared__ float t[32][33];
    const int b = blockIdx.z;
    const int c0 = blockIdx.y * 32, l0 = blockIdx.x * 32;
    const int tx = threadIdx.x, ty = threadIdx.y;
    const float* xb = x + ((size_t)b * CC + c0) * LL + l0;
    #pragma unroll
    for (int i = 0; i < 4; i++)
        t[ty + 8 * i][tx] = xb[(size_t)(ty + 8 * i) * LL + tx];
    __syncthreads();
    #pragma unroll
    for (int i = 0; i < 4; i++) {
        int row = ty + 8 * i;
        float v = t[tx][row];
        __nv_bfloat16 h, l2;
        split_bf16(v, h, l2);
        size_t o = ((size_t)b * LL + l0 + row) * CC + c0 + tx;
        g_xT_hi[o] = h; g_xT_lo[o] = l2;
    }
}

// ---------------------------------------------------------------------------
// Generic bf16-split MMA GEMM. MODE 0: bf16 hi/lo out. MODE 1: fp32+bias.
// MODE 2: fp16 hi/lo out (Yh/Yl reinterpreted as __half*).
// ---------------------------------------------------------------------------
template<int MODE>
__global__ void __launch_bounds__(256, 1) mma_gemm(
    const __nv_bfloat16* __restrict__ Ah, const __nv_bfloat16* __restrict__ Al, size_t sA,
    const __nv_bfloat16* __restrict__ Bh, const __nv_bfloat16* __restrict__ Bl, size_t sB,
    __nv_bfloat16* Yh, __nv_bfloat16* Yl, float* Yf, const float* bias, size_t sY,
    int N, int K, int nkc)
{
    extern __shared__ __align__(1024) char smem[];
    const uint32_t sb = smem_u32(smem);
    const int tid = threadIdx.x;
    const int lane = tid & 31, w = tid >> 5;
    const int b  = blockIdx.z;
    const int m0 = blockIdx.y * 128;
    const int n0 = blockIdx.x * 64;

    const __nv_bfloat16* Ahb = Ah + (size_t)b * sA;
    const __nv_bfloat16* Alb = Al + (size_t)b * sA;
    const __nv_bfloat16* Bhb = Bh + (size_t)b * sB;
    const __nv_bfloat16* Blb = Bl + (size_t)b * sB;

    const int g = lane >> 3;
    const int rowB = ((g & 2) ? 8 : 0) + (lane & 7);
    const int bytB = (g & 1) * 16;
    const int rowA = lane & 15;
    const int bytA = (lane >> 4) * 16;
    uint32_t swzB[4], swzA[4];
    #pragma unroll
    for (int kk = 0; kk < 4; kk++) {
        swzB[kk] = SWZ((uint32_t)(rowB * 128 + bytB + kk * 32));
        swzA[kk] = SWZ((uint32_t)(rowA * 128 + bytA + kk * 32));
    }

    auto issue = [&](int kc) {
        const uint32_t base = sb + (uint32_t)(kc & 1) * 49152u;
        const int koff = kc * 64;
        #pragma unroll
        for (int e = 0; e < 4; e++) {
            int wi = tid + e * 256;
            int row = wi >> 3, c = wi & 7;
            uint32_t sw = SWZ((uint32_t)(row * 128 + c * 16));
            const __nv_bfloat16* s0 = Ahb + (size_t)(m0 + row) * K + koff + c * 8;
            const __nv_bfloat16* s1 = Alb + (size_t)(m0 + row) * K + koff + c * 8;
            asm volatile("cp.async.cg.shared.global [%0], [%1], 16;" :: "r"(base + sw), "l"(s0));
            asm volatile("cp.async.cg.shared.global [%0], [%1], 16;" :: "r"(base + 16384u + sw), "l"(s1));
        }
        #pragma unroll
        for (int e = 0; e < 2; e++) {
            int wi = tid + e * 256;
            int row = wi >> 3, c = wi & 7;
            uint32_t sw = SWZ((uint32_t)(row * 128 + c * 16));
            const __nv_bfloat16* s0 = Bhb + (size_t)(n0 + row) * K + koff + c * 8;
            const __nv_bfloat16* s1 = Blb + (size_t)(n0 + row) * K + koff + c * 8;
            asm volatile("cp.async.cg.shared.global [%0], [%1], 16;" :: "r"(base + 32768u + sw), "l"(s0));
            asm volatile("cp.async.cg.shared.global [%0], [%1], 16;" :: "r"(base + 40960u + sw), "l"(s1));
        }
        asm volatile("cp.async.commit_group;" ::: "memory");
    };

    issue(0);

    float s[8][4] = {};

    for (int kc = 0; kc < nkc; kc++) {
        asm volatile("cp.async.wait_group 0;" ::: "memory");
        __syncthreads();
        if (kc + 1 < nkc) issue(kc + 1);

        const uint32_t base = sb + (uint32_t)(kc & 1) * 49152u;
        const uint32_t ab = base + ((uint32_t)w << 11);

        #pragma unroll
        for (int kk = 0; kk < 4; kk++) {
            uint32_t ah[4], al[4];
            ldsm4(ah[0], ah[1], ah[2], ah[3], ab + swzA[kk]);
            ldsm4(al[0], al[1], al[2], al[3], ab + 16384u + swzA[kk]);
            #pragma unroll
            for (int np = 0; np < 4; np++) {
                uint32_t b0, b1, b2, b3, c0, c1, c2, c3;
                ldsm4(b0, b1, b2, b3, base + 32768u + ((uint32_t)np << 11) + swzB[kk]);
                ldsm4(c0, c1, c2, c3, base + 40960u + ((uint32_t)np << 11) + swzB[kk]);
                mma16816(s[2 * np],     ah, b0, b1);
                mma16816(s[2 * np],     al, b0, b1);
                mma16816(s[2 * np],     ah, c0, c1);
                mma16816(s[2 * np + 1], ah, b2, b3);
                mma16816(s[2 * np + 1], al, b2, b3);
                mma16816(s[2 * np + 1], ah, c2, c3);
            }
        }
        __syncthreads();
    }

    const int mr = m0 + w * 16 + (lane >> 2);
    const int nc = n0 + 2 * (lane & 3);
    if (MODE == 0 || MODE == 2) {
        __nv_bfloat16* Yhb = Yh + (size_t)b * sY;
        __nv_bfloat16* Ylb = Yl + (size_t)b * sY;
        #pragma unroll
        for (int tt = 0; tt < 8; tt++) {
            uint32_t h0, l0, h1, l1;
            if (MODE == 0) {
                pack_pair(s[tt][0], s[tt][1], h0, l0);
                pack_pair(s[tt][2], s[tt][3], h1, l1);
            } else {
                pack_pair_f16(s[tt][0], s[tt][1], h0, l0);
                pack_pair_f16(s[tt][2], s[tt][3], h1, l1);
            }
            size_t o0 = (size_t)mr * N + nc + 8 * tt;
            size_t o1 = (size_t)(mr + 8) * N + nc + 8 * tt;
            *(uint32_t*)&Yhb[o0] = h0; *(uint32_t*)&Ylb[o0] = l0;
            *(uint32_t*)&Yhb[o1] = h1; *(uint32_t*)&Ylb[o1] = l1;
        }
    } else {
        float* Yfb = Yf + (size_t)b * sY;
        const float bv0 = bias[mr], bv1 = bias[mr + 8];
        #pragma unroll
        for (int tt = 0; tt < 8; tt++) {
            float2 v0, v1;
            v0.x = s[tt][0] + bv0; v0.y = s[tt][1] + bv0;
            v1.x = s[tt][2] + bv1; v1.y = s[tt][3] + bv1;
            *(float2*)(Yfb + (size_t)mr * N + nc + 8 * tt)       = v0;
            *(float2*)(Yfb + (size_t)(mr + 8) * N + nc + 8 * tt) = v1;
        }
    }
}

// ---------------------------------------------------------------------------
// Flash attention, 128-key tiles (16 tiles). CTA = 8 warps x m16 x 128
// queries. 2-stage 64KB K/V ring + persistent 32KB Q = 160KB smem.
// S: bf16 3-pass. PV: fp16, P single (11-bit mantissa) x V hi/lo 2-pass.
// buffer layout: KH 0 |KL 16K| VH 32K (two 8K subtiles) | VL 48K
// ---------------------------------------------------------------------------
__global__ void __launch_bounds__(256, 1) attn_kernel()
{
    extern __shared__ __align__(1024) char smem[];
    const uint32_t sb = smem_u32(smem);
    const int tid = threadIdx.x;
    const int lane = tid & 31, w = tid >> 5;
    const int bh = blockIdx.y;
    const int b = bh >> 3, h = bh & 7;
    const int i0 = blockIdx.x * 128;

    const __nv_bfloat16* qh = g_qk_hi + ((size_t)b * LL + i0) * QKS + h * DD;
    const __nv_bfloat16* ql = g_qk_lo + ((size_t)b * LL + i0) * QKS + h * DD;
    const __nv_bfloat16* kh = g_qk_hi + (size_t)b * LL * QKS + 512 + h * DD;
    const __nv_bfloat16* kl = g_qk_lo + (size_t)b * LL * QKS + 512 + h * DD;
    const __half* vh = g_v_hi + ((size_t)b * HID + h * DD) * LL;
    const __half* vl = g_v_lo + ((size_t)b * HID + h * DD) * LL;

    const int g = lane >> 3;
    const int rowB = ((g & 2) ? 8 : 0) + (lane & 7);
    const int bytB = (g & 1) * 16;
    const int rowA = lane & 15;
    const int bytA = (lane >> 4) * 16;
    uint32_t swzB[4], swzA[4];
    #pragma unroll
    for (int kk = 0; kk < 4; kk++) {
        swzB[kk] = SWZ((uint32_t)(rowB * 128 + bytB + kk * 32));
        swzA[kk] = SWZ((uint32_t)(rowA * 128 + bytA + kk * 32));
    }

    auto bufbase = [&](int jt) -> uint32_t {
        return sb + 32768u + (uint32_t)(jt & 1) * 65536u;
    };

    // one 128-key tile: K 128 rows x 128B (hi+lo), V as 2 subtiles of
    // 64 d-rows x 128B (hi+lo). 64 KB total, 16 cp.async per thread.
    auto issue_tile = [&](int jt) {
        const int j0 = jt * 128;
        const uint32_t base = bufbase(jt);
        #pragma unroll
        for (int e = 0; e < 16; e++) {
            const int arr = e >> 2;                 // 0 KH 1 KL 2 VH 3 VL
            const int wi = tid + (e & 3) * 256;     // 0..1023
            const int row = wi >> 3, c = wi & 7;
            if (arr < 2) {
                const uint32_t dst = base + arr * 16384 + SWZ((uint32_t)(row * 128 + c * 16));
                const __nv_bfloat16* src = (arr == 0 ? kh : kl) + (size_t)(j0 + row) * QKS + c * 8;
                asm volatile("cp.async.cg.shared.global [%0], [%1], 16;" :: "r"(dst), "l"(src));
            } else {
                const int sub = row >> 6, d = row & 63;
                const uint32_t dst = base + arr * 16384 + sub * 8192 + SWZ((uint32_t)(d * 128 + c * 16));
                const __half* src = (arr == 2 ? vh : vl) + (size_t)d * LL + j0 + sub * 64 + c * 8;
                asm volatile("cp.async.cg.shared.global [%0], [%1], 16;" :: "r"(dst), "l"(src));
            }
        }
        asm volatile("cp.async.commit_group;" ::: "memory");
    };

    issue_tile(0);
    issue_tile(1);

    // ---- stage Q (persistent: hi @0, lo @16K) ----
    #pragma unroll
    for (int e = 0; e < 4; e++) {
        int idx = tid + e * 256;
        int row = idx >> 3, c = idx & 7;
        uint32_t sw = SWZ((uint32_t)(row * 128 + c * 16));
        *(uint4*)(smem + sw)         = *(const uint4*)(qh + (size_t)row * QKS + c * 8);
        *(uint4*)(smem + 16384 + sw) = *(const uint4*)(ql + (size_t)row * QKS + c * 8);
    }
    __syncthreads();
    uint32_t qfh[4][4], qfl[4][4];
    #pragma unroll
    for (int kk = 0; kk < 4; kk++) {
        ldsm4(qfh[kk][0], qfh[kk][1], qfh[kk][2], qfh[kk][3],
              sb + ((uint32_t)w << 11) + swzA[kk]);
        ldsm4(qfl[kk][0], qfl[kk][1], qfl[kk][2], qfl[kk][3],
              sb + 16384u + ((uint32_t)w << 11) + swzA[kk]);
    }

    const float LOG2E = 1.4426950408889634f;
    float m0 = -INFINITY, m1 = -INFINITY, l0 = 0.f, l1 = 0.f;
    float O[8][4] = {};

    for (int t = 0; t < 16; t++) {
        asm volatile("cp.async.wait_group 1;" ::: "memory");  // tile t landed
        __syncthreads();
        const uint32_t base = bufbase(t);

        // ---- S = Q K^T (m16 x n128, bf16 3-pass) ----
        float s[16][4];
        #pragma unroll
        for (int tt = 0; tt < 16; tt++) {
            s[tt][0] = 0.f; s[tt][1] = 0.f; s[tt][2] = 0.f; s[tt][3] = 0.f;
        }
        #pragma unroll
        for (int kk = 0; kk < 4; kk++) {
            #pragma unroll
            for (int np = 0; np < 8; np++) {
                uint32_t b0, b1, b2, b3, c0, c1, c2, c3;
                ldsm4(b0, b1, b2, b3, base + ((uint32_t)np << 11) + swzB[kk]);
                ldsm4(c0, c1, c2, c3, base + 16384u + ((uint32_t)np << 11) + swzB[kk]);
                mma16816(s[2 * np],     qfh[kk], b0, b1);
                mma16816(s[2 * np],     qfl[kk], b0, b1);
                mma16816(s[2 * np],     qfh[kk], c0, c1);
                mma16816(s[2 * np + 1], qfh[kk], b2, b3);
                mma16816(s[2 * np + 1], qfl[kk], b2, b3);
                mma16816(s[2 * np + 1], qfh[kk], c2, c3);
            }
        }

        // ---- online softmax (2 rows per thread) ----
        float mx0 = -INFINITY, mx1 = -INFINITY;
        #pragma unroll
        for (int tt = 0; tt < 16; tt++) {
            mx0 = fmaxf(mx0, fmaxf(s[tt][0], s[tt][1]));
            mx1 = fmaxf(mx1, fmaxf(s[tt][2], s[tt][3]));
        }
        mx0 = fmaxf(mx0, __shfl_xor_sync(0xffffffffu, mx0, 1));
        mx0 = fmaxf(mx0, __shfl_xor_sync(0xffffffffu, mx0, 2));
        mx1 = fmaxf(mx1, __shfl_xor_sync(0xffffffffu, mx1, 1));
        mx1 = fmaxf(mx1, __shfl_xor_sync(0xffffffffu, mx1, 2));

        float mn0 = fmaxf(m0, mx0), mn1 = fmaxf(m1, mx1);
        float a0 = ex2((m0 - mn0) * LOG2E), a1 = ex2((m1 - mn1) * LOG2E);
        float rs0 = 0.f, rs1 = 0.f;
        #pragma unroll
        for (int tt = 0; tt < 16; tt++) {
            s[tt][0] = ex2((s[tt][0] - mn0) * LOG2E);
            s[tt][1] = ex2((s[tt][1] - mn0) * LOG2E);
            s[tt][2] = ex2((s[tt][2] - mn1) * LOG2E);
            s[tt][3] = ex2((s[tt][3] - mn1) * LOG2E);
            rs0 += s[tt][0] + s[tt][1];
            rs1 += s[tt][2] + s[tt][3];
        }
        rs0 += __shfl_xor_sync(0xffffffffu, rs0, 1);
        rs0 += __shfl_xor_sync(0xffffffffu, rs0, 2);
        rs1 += __shfl_xor_sync(0xffffffffu, rs1, 1);
        rs1 += __shfl_xor_sync(0xffffffffu, rs1, 2);
        l0 = l0 * a0 + rs0; l1 = l1 * a1 + rs1;
        m0 = mn0; m1 = mn1;
        #pragma unroll
        for (int tt = 0; tt < 8; tt++) {
            O[tt][0] *= a0; O[tt][1] *= a0;
            O[tt][2] *= a1; O[tt][3] *= a1;
        }

        // ---- P -> fp16 A-frags (single pass; 11-bit mantissa) ----
        uint32_t p[8][4];
        #pragma unroll
        for (int kg = 0; kg < 8; kg++) {
            p[kg][0] = cvt2f16(s[2 * kg][0],     s[2 * kg][1]);
            p[kg][1] = cvt2f16(s[2 * kg][2],     s[2 * kg][3]);
            p[kg][2] = cvt2f16(s[2 * kg + 1][0], s[2 * kg + 1][1]);
            p[kg][3] = cvt2f16(s[2 * kg + 1][2], s[2 * kg + 1][3]);
        }

        // ---- O += P V^T (fp16: P x V_hi + P x V_lo) ----
        const uint32_t vb = base + 32768u;
        #pragma unroll
        for (int kg = 0; kg < 8; kg++) {
            const uint32_t sub = (uint32_t)(kg >> 2) * 8192u;
            const int kkin = kg & 3;
            #pragma unroll
            for (int dnp = 0; dnp < 4; dnp++) {
                uint32_t b0, b1, b2, b3, c0, c1, c2, c3;
                ldsm4(b0, b1, b2, b3, vb + sub + ((uint32_t)dnp << 11) + swzB[kkin]);
                ldsm4(c0, c1, c2, c3, vb + 16384u + sub + ((uint32_t)dnp << 11) + swzB[kkin]);
                mma16816h(O[2 * dnp],     p[kg], b0, b1);
                mma16816h(O[2 * dnp],     p[kg], c0, c1);
                mma16816h(O[2 * dnp + 1], p[kg], b2, b3);
                mma16816h(O[2 * dnp + 1], p[kg], c2, c3);
            }
        }

        __syncthreads();                 // all warps done with buf(t&1)
        if (t + 2 < 16) issue_tile(t + 2);
    }

    // ---- normalize + write bf16 hi/lo att [b][l][512] ----
    const float inv0 = 1.0f / l0, inv1 = 1.0f / l1;
    const int r0 = i0 + 16 * w + (lane >> 2);
    size_t o0 = ((size_t)b * LL + r0) * HID + h * DD + 2 * (lane & 3);
    size_t o1 = o0 + (size_t)8 * HID;
    #pragma unroll
    for (int tt = 0; tt < 8; tt++) {
        uint32_t h0, lo0, h1, lo1;
        pack_pair(O[tt][0] * inv0, O[tt][1] * inv0, h0, lo0);
        pack_pair(O[tt][2] * inv1, O[tt][3] * inv1, h1, lo1);
        *(uint32_t*)&g_att_hi[o0 + 8 * tt] = h0;
        *(uint32_t*)&g_att_lo[o0 + 8 * tt] = lo0;
        *(uint32_t*)&g_att_hi[o1 + 8 * tt] = h1;
        *(uint32_t*)&g_att_lo[o1 + 8 * tt] = lo1;
    }
}

// ---------------------------------------------------------------------------
extern "C" void kernel_launch(void* const* d_in, const int* in_sizes, int n_in,
                              void* d_out, int out_size)
{
    const float* x     = (const float*)d_in[0];
    const float* w_qkv = (const float*)d_in[1];
    const float* w_out = (const float*)d_in[2];
    const float* b_out = (const float*)d_in[3];
    float* out = (float*)d_out;

    __nv_bfloat16 *wq_h, *wq_l, *wo_h, *wo_l, *xt_h, *xt_l;
    __nv_bfloat16 *qk_h, *qk_l, *at_h, *at_l;
    __half *v_h, *v_l;
    cudaGetSymbolAddress((void**)&wq_h, g_wq_hi);
    cudaGetSymbolAddress((void**)&wq_l, g_wq_lo);
    cudaGetSymbolAddress((void**)&wo_h, g_wo_hi);
    cudaGetSymbolAddress((void**)&wo_l, g_wo_lo);
    cudaGetSymbolAddress((void**)&xt_h, g_xT_hi);
    cudaGetSymbolAddress((void**)&xt_l, g_xT_lo);
    cudaGetSymbolAddress((void**)&qk_h, g_qk_hi);
    cudaGetSymbolAddress((void**)&qk_l, g_qk_lo);
    cudaGetSymbolAddress((void**)&v_h,  g_v_hi);
    cudaGetSymbolAddress((void**)&v_l,  g_v_lo);
    cudaGetSymbolAddress((void**)&at_h, g_att_hi);
    cudaGetSymbolAddress((void**)&at_l, g_att_lo);

    const int GEMM_SMEM = 98304;
    const int ATTN_SMEM = 163840;   // Q 32K + 2 ring buffers x 64K
    cudaFuncSetAttribute(mma_gemm<0>, cudaFuncAttributeMaxDynamicSharedMemorySize, GEMM_SMEM);
    cudaFuncSetAttribute(mma_gemm<1>, cudaFuncAttributeMaxDynamicSharedMemorySize, GEMM_SMEM);
    cudaFuncSetAttribute(mma_gemm<2>, cudaFuncAttributeMaxDynamicSharedMemorySize, GEMM_SMEM);
    cudaFuncSetAttribute(attn_kernel, cudaFuncAttributeMaxDynamicSharedMemorySize, ATTN_SMEM);

    conv_w<<<(MQKV * CC + CC * HID) / 256, 256>>>(w_qkv, w_out);
    conv_x<<<dim3(LL / 32, CC / 32, BB), dim3(32, 8)>>>(x);

    // L1: C[l][qk_ch] = xT * wq(rows 0..1023)^T  -> g_qk (bf16 hi/lo)
    mma_gemm<0><<<dim3(QKS / 64, LL / 128, BB), 256, GEMM_SMEM>>>(
        xt_h, xt_l, (size_t)LL * CC, wq_h, wq_l, 0,
        qk_h, qk_l, nullptr, nullptr, (size_t)LL * QKS, QKS, CC, CC / 64);

    // L2: C[v_ch][l] = wq(rows 1024..1535) * xT^T -> g_v (fp16 hi/lo)
    mma_gemm<2><<<dim3(LL / 64, HID / 128, BB), 256, GEMM_SMEM>>>(
        wq_h + 1024 * CC, wq_l + 1024 * CC, 0, xt_h, xt_l, (size_t)LL * CC,
        (__nv_bfloat16*)v_h, (__nv_bfloat16*)v_l, nullptr, nullptr,
        (size_t)HID * LL, LL, CC, CC / 64);

    attn_kernel<<<dim3(LL / 128, BB * HH), 256, ATTN_SMEM>>>();

    // L3: out[ch][l] = w_out * att^T + bias
    mma_gemm<1><<<dim3(LL / 64, CC / 128, BB), 256, GEMM_SMEM>>>(
        wo_h, wo_l, 0, at_h, at_l, (size_t)LL * HID,
        nullptr, nullptr, out, b_out, (size_t)CC * LL, LL, HID, HID / 64);
}

// round 9
// speedup vs baseline: 4.8671x; 1.1288x over previous
#include <cuda_runtime.h>
#include <cuda_bf16.h>
#include <cuda_fp16.h>
#include <math.h>
#include <stdint.h>

#define BB   4
#define CC   256
#define LL   2048
#define HH   8
#define DD   64
#define HID  512
#define MQKV 1536
#define QKS  1024   // fused q|k channel stride

// ---------------- scratch (allocation-free rule: __device__ globals) -------
__device__ __align__(16) __nv_bfloat16 g_wq_hi[MQKV * CC];
__device__ __align__(16) __nv_bfloat16 g_wq_lo[MQKV * CC];
__device__ __align__(16) __nv_bfloat16 g_wo_hi[CC * HID];
__device__ __align__(16) __nv_bfloat16 g_wo_lo[CC * HID];
__device__ __align__(16) __nv_bfloat16 g_xT_hi[(size_t)BB * LL * CC];
__device__ __align__(16) __nv_bfloat16 g_xT_lo[(size_t)BB * LL * CC];
__device__ __align__(16) __half        g_qk_hi[(size_t)BB * LL * QKS];  // fp16 now
__device__ __align__(16) __half        g_qk_lo[(size_t)BB * LL * QKS];
__device__ __align__(16) __half        g_v_hi[(size_t)BB * HID * LL];
__device__ __align__(16) __half        g_v_lo[(size_t)BB * HID * LL];
__device__ __align__(16) __nv_bfloat16 g_att_hi[(size_t)BB * LL * HID];
__device__ __align__(16) __nv_bfloat16 g_att_lo[(size_t)BB * LL * HID];

#define SWZ(x) ((x) ^ (((x) >> 3) & 0x70))

// ---------------- warp-MMA helpers -----------------------------------------
__device__ __forceinline__ uint32_t smem_u32(const void* p) {
    uint32_t a;
    asm("{ .reg .u64 t; cvta.to.shared.u64 t, %1; cvt.u32.u64 %0, t; }"
        : "=r"(a) : "l"(p));
    return a;
}
__device__ __forceinline__ void ldsm4(uint32_t& r0, uint32_t& r1, uint32_t& r2,
                                      uint32_t& r3, uint32_t a) {
    asm volatile("ldmatrix.sync.aligned.m8n8.x4.shared.b16 {%0,%1,%2,%3}, [%4];"
                 : "=r"(r0), "=r"(r1), "=r"(r2), "=r"(r3) : "r"(a));
}
__device__ __forceinline__ void mma16816(float* c, const uint32_t* a,
                                         uint32_t b0, uint32_t b1) {
    asm volatile("mma.sync.aligned.m16n8k16.row.col.f32.bf16.bf16.f32 "
                 "{%0,%1,%2,%3}, {%4,%5,%6,%7}, {%8,%9}, {%0,%1,%2,%3};"
                 : "+f"(c[0]), "+f"(c[1]), "+f"(c[2]), "+f"(c[3])
                 : "r"(a[0]), "r"(a[1]), "r"(a[2]), "r"(a[3]), "r"(b0), "r"(b1));
}
__device__ __forceinline__ void mma16816h(float* c, const uint32_t* a,
                                          uint32_t b0, uint32_t b1) {
    asm volatile("mma.sync.aligned.m16n8k16.row.col.f32.f16.f16.f32 "
                 "{%0,%1,%2,%3}, {%4,%5,%6,%7}, {%8,%9}, {%0,%1,%2,%3};"
                 : "+f"(c[0]), "+f"(c[1]), "+f"(c[2]), "+f"(c[3])
                 : "r"(a[0]), "r"(a[1]), "r"(a[2]), "r"(a[3]), "r"(b0), "r"(b1));
}
__device__ __forceinline__ uint32_t cvt2bf(float p0, float p1) {
    uint32_t r;
    asm("cvt.rn.bf16x2.f32 %0, %1, %2;" : "=r"(r) : "f"(p1), "f"(p0));
    return r;
}
__device__ __forceinline__ uint32_t cvt2f16(float p0, float p1) {
    uint32_t r;
    asm("cvt.rn.f16x2.f32 %0, %1, %2;" : "=r"(r) : "f"(p1), "f"(p0));
    return r;
}
__device__ __forceinline__ void pack_pair(float p0, float p1,
                                          uint32_t& hi, uint32_t& lo) {
    hi = cvt2bf(p0, p1);
    float f0 = __uint_as_float(hi << 16);
    float f1 = __uint_as_float(hi & 0xffff0000u);
    lo = cvt2bf(p0 - f0, p1 - f1);
}
__device__ __forceinline__ void pack_pair_f16(float p0, float p1,
                                              uint32_t& hi, uint32_t& lo) {
    hi = cvt2f16(p0, p1);
    __half2 h2 = *reinterpret_cast<__half2*>(&hi);
    float f0 = __half2float(h2.x);
    float f1 = __half2float(h2.y);
    lo = cvt2f16(p0 - f0, p1 - f1);
}
__device__ __forceinline__ void split_bf16(float x, __nv_bfloat16& h, __nv_bfloat16& l) {
    h = __float2bfloat16(x);
    l = __float2bfloat16(x - __bfloat162float(h));
}
__device__ __forceinline__ float ex2(float x) {
    float y;
    asm("ex2.approx.ftz.f32 %0, %1;" : "=f"(y) : "f"(x));
    return y;
}

// ---------------------------------------------------------------------------
// conv_w / conv_x (unchanged)
// ---------------------------------------------------------------------------
__global__ void conv_w(const float* __restrict__ wq, const float* __restrict__ wo)
{
    const int NQ = MQKV * CC;
    int idx = blockIdx.x * 256 + threadIdx.x;
    if (idx < NQ) {
        float v = wq[idx];
        if (idx < 512 * CC) v *= 0.125f;
        __nv_bfloat16 h, l;
        split_bf16(v, h, l);
        g_wq_hi[idx] = h; g_wq_lo[idx] = l;
    } else {
        int j = idx - NQ;
        if (j < CC * HID) {
            __nv_bfloat16 h, l;
            split_bf16(wo[j], h, l);
            g_wo_hi[j] = h; g_wo_lo[j] = l;
        }
    }
}

__global__ void conv_x(const float* __restrict__ x)
{
    __shared__ float t[32][33];
    const int b = blockIdx.z;
    const int c0 = blockIdx.y * 32, l0 = blockIdx.x * 32;
    const int tx = threadIdx.x, ty = threadIdx.y;
    const float* xb = x + ((size_t)b * CC + c0) * LL + l0;
    #pragma unroll
    for (int i = 0; i < 4; i++)
        t[ty + 8 * i][tx] = xb[(size_t)(ty + 8 * i) * LL + tx];
    __syncthreads();
    #pragma unroll
    for (int i = 0; i < 4; i++) {
        int row = ty + 8 * i;
        float v = t[tx][row];
        __nv_bfloat16 h, l2;
        split_bf16(v, h, l2);
        size_t o = ((size_t)b * LL + l0 + row) * CC + c0 + tx;
        g_xT_hi[o] = h; g_xT_lo[o] = l2;
    }
}

// ---------------------------------------------------------------------------
// Generic bf16-split MMA GEMM. MODE 0: bf16 hi/lo out. MODE 1: fp32+bias.
// MODE 2: fp16 hi/lo out (Yh/Yl reinterpreted as __half*).
// ---------------------------------------------------------------------------
template<int MODE>
__global__ void __launch_bounds__(256, 1) mma_gemm(
    const __nv_bfloat16* __restrict__ Ah, const __nv_bfloat16* __restrict__ Al, size_t sA,
    const __nv_bfloat16* __restrict__ Bh, const __nv_bfloat16* __restrict__ Bl, size_t sB,
    __nv_bfloat16* Yh, __nv_bfloat16* Yl, float* Yf, const float* bias, size_t sY,
    int N, int K, int nkc)
{
    extern __shared__ __align__(1024) char smem[];
    const uint32_t sb = smem_u32(smem);
    const int tid = threadIdx.x;
    const int lane = tid & 31, w = tid >> 5;
    const int b  = blockIdx.z;
    const int m0 = blockIdx.y * 128;
    const int n0 = blockIdx.x * 64;

    const __nv_bfloat16* Ahb = Ah + (size_t)b * sA;
    const __nv_bfloat16* Alb = Al + (size_t)b * sA;
    const __nv_bfloat16* Bhb = Bh + (size_t)b * sB;
    const __nv_bfloat16* Blb = Bl + (size_t)b * sB;

    const int g = lane >> 3;
    const int rowB = ((g & 2) ? 8 : 0) + (lane & 7);
    const int bytB = (g & 1) * 16;
    const int rowA = lane & 15;
    const int bytA = (lane >> 4) * 16;
    uint32_t swzB[4], swzA[4];
    #pragma unroll
    for (int kk = 0; kk < 4; kk++) {
        swzB[kk] = SWZ((uint32_t)(rowB * 128 + bytB + kk * 32));
        swzA[kk] = SWZ((uint32_t)(rowA * 128 + bytA + kk * 32));
    }

    auto issue = [&](int kc) {
        const uint32_t base = sb + (uint32_t)(kc & 1) * 49152u;
        const int koff = kc * 64;
        #pragma unroll
        for (int e = 0; e < 4; e++) {
            int wi = tid + e * 256;
            int row = wi >> 3, c = wi & 7;
            uint32_t sw = SWZ((uint32_t)(row * 128 + c * 16));
            const __nv_bfloat16* s0 = Ahb + (size_t)(m0 + row) * K + koff + c * 8;
            const __nv_bfloat16* s1 = Alb + (size_t)(m0 + row) * K + koff + c * 8;
            asm volatile("cp.async.cg.shared.global [%0], [%1], 16;" :: "r"(base + sw), "l"(s0));
            asm volatile("cp.async.cg.shared.global [%0], [%1], 16;" :: "r"(base + 16384u + sw), "l"(s1));
        }
        #pragma unroll
        for (int e = 0; e < 2; e++) {
            int wi = tid + e * 256;
            int row = wi >> 3, c = wi & 7;
            uint32_t sw = SWZ((uint32_t)(row * 128 + c * 16));
            const __nv_bfloat16* s0 = Bhb + (size_t)(n0 + row) * K + koff + c * 8;
            const __nv_bfloat16* s1 = Blb + (size_t)(n0 + row) * K + koff + c * 8;
            asm volatile("cp.async.cg.shared.global [%0], [%1], 16;" :: "r"(base + 32768u + sw), "l"(s0));
            asm volatile("cp.async.cg.shared.global [%0], [%1], 16;" :: "r"(base + 40960u + sw), "l"(s1));
        }
        asm volatile("cp.async.commit_group;" ::: "memory");
    };

    issue(0);

    float s[8][4] = {};

    for (int kc = 0; kc < nkc; kc++) {
        asm volatile("cp.async.wait_group 0;" ::: "memory");
        __syncthreads();
        if (kc + 1 < nkc) issue(kc + 1);

        const uint32_t base = sb + (uint32_t)(kc & 1) * 49152u;
        const uint32_t ab = base + ((uint32_t)w << 11);

        #pragma unroll
        for (int kk = 0; kk < 4; kk++) {
            uint32_t ah[4], al[4];
            ldsm4(ah[0], ah[1], ah[2], ah[3], ab + swzA[kk]);
            ldsm4(al[0], al[1], al[2], al[3], ab + 16384u + swzA[kk]);
            #pragma unroll
            for (int np = 0; np < 4; np++) {
                uint32_t b0, b1, b2, b3, c0, c1, c2, c3;
                ldsm4(b0, b1, b2, b3, base + 32768u + ((uint32_t)np << 11) + swzB[kk]);
                ldsm4(c0, c1, c2, c3, base + 40960u + ((uint32_t)np << 11) + swzB[kk]);
                mma16816(s[2 * np],     ah, b0, b1);
                mma16816(s[2 * np],     al, b0, b1);
                mma16816(s[2 * np],     ah, c0, c1);
                mma16816(s[2 * np + 1], ah, b2, b3);
                mma16816(s[2 * np + 1], al, b2, b3);
                mma16816(s[2 * np + 1], ah, c2, c3);
            }
        }
        __syncthreads();
    }

    const int mr = m0 + w * 16 + (lane >> 2);
    const int nc = n0 + 2 * (lane & 3);
    if (MODE == 0 || MODE == 2) {
        __nv_bfloat16* Yhb = Yh + (size_t)b * sY;
        __nv_bfloat16* Ylb = Yl + (size_t)b * sY;
        #pragma unroll
        for (int tt = 0; tt < 8; tt++) {
            uint32_t h0, l0, h1, l1;
            if (MODE == 0) {
                pack_pair(s[tt][0], s[tt][1], h0, l0);
                pack_pair(s[tt][2], s[tt][3], h1, l1);
            } else {
                pack_pair_f16(s[tt][0], s[tt][1], h0, l0);
                pack_pair_f16(s[tt][2], s[tt][3], h1, l1);
            }
            size_t o0 = (size_t)mr * N + nc + 8 * tt;
            size_t o1 = (size_t)(mr + 8) * N + nc + 8 * tt;
            *(uint32_t*)&Yhb[o0] = h0; *(uint32_t*)&Ylb[o0] = l0;
            *(uint32_t*)&Yhb[o1] = h1; *(uint32_t*)&Ylb[o1] = l1;
        }
    } else {
        float* Yfb = Yf + (size_t)b * sY;
        const float bv0 = bias[mr], bv1 = bias[mr + 8];
        #pragma unroll
        for (int tt = 0; tt < 8; tt++) {
            float2 v0, v1;
            v0.x = s[tt][0] + bv0; v0.y = s[tt][1] + bv0;
            v1.x = s[tt][2] + bv1; v1.y = s[tt][3] + bv1;
            *(float2*)(Yfb + (size_t)mr * N + nc + 8 * tt)       = v0;
            *(float2*)(Yfb + (size_t)(mr + 8) * N + nc + 8 * tt) = v1;
        }
    }
}

// ---------------------------------------------------------------------------
// Flash attention: all-fp16 MMA path. S = q_hi*k_hi + q_lo*k_hi (2-pass,
// drops q*k_lo ~1e-4 abs). PV = p_f16 x (V_hi + V_lo). 128-key tiles,
// 3-stage 48KB ring + persistent 32KB Q = 176 KB smem.
// stage layout: K 0..16K | VH 16..32K (2x8K subtiles) | VL 32..48K
// ---------------------------------------------------------------------------
__global__ void __launch_bounds__(256, 1) attn_kernel()
{
    extern __shared__ __align__(1024) char smem[];
    const uint32_t sb = smem_u32(smem);
    const int tid = threadIdx.x;
    const int lane = tid & 31, w = tid >> 5;
    const int bh = blockIdx.y;
    const int b = bh >> 3, h = bh & 7;
    const int i0 = blockIdx.x * 128;

    const __half* qh = g_qk_hi + ((size_t)b * LL + i0) * QKS + h * DD;
    const __half* ql = g_qk_lo + ((size_t)b * LL + i0) * QKS + h * DD;
    const __half* kh = g_qk_hi + (size_t)b * LL * QKS + 512 + h * DD;
    const __half* vh = g_v_hi + ((size_t)b * HID + h * DD) * LL;
    const __half* vl = g_v_lo + ((size_t)b * HID + h * DD) * LL;

    const int g = lane >> 3;
    const int rowB = ((g & 2) ? 8 : 0) + (lane & 7);
    const int bytB = (g & 1) * 16;
    const int rowA = lane & 15;
    const int bytA = (lane >> 4) * 16;
    uint32_t swzB[4], swzA[4];
    #pragma unroll
    for (int kk = 0; kk < 4; kk++) {
        swzB[kk] = SWZ((uint32_t)(rowB * 128 + bytB + kk * 32));
        swzA[kk] = SWZ((uint32_t)(rowA * 128 + bytA + kk * 32));
    }

    auto bufbase = [&](int jt) -> uint32_t {
        return sb + 32768u + (uint32_t)(jt % 3) * 49152u;
    };

    // one 128-key tile: K 128x128B + VH/VL (2x 64x128B subtiles each) = 48KB
    auto issue_tile = [&](int jt) {
        const int j0 = jt * 128;
        const uint32_t base = bufbase(jt);
        #pragma unroll
        for (int e = 0; e < 4; e++) {
            int wi = tid + e * 256;
            int row = wi >> 3, c = wi & 7;
            uint32_t dst = base + SWZ((uint32_t)(row * 128 + c * 16));
            const __half* src = kh + (size_t)(j0 + row) * QKS + c * 8;
            asm volatile("cp.async.cg.shared.global [%0], [%1], 16;" :: "r"(dst), "l"(src));
        }
        #pragma unroll
        for (int e = 0; e < 8; e++) {
            int arr = e >> 2;                 // 0 VH, 1 VL
            int wi = tid + (e & 3) * 256;     // 0..1023
            int row = wi >> 3, c = wi & 7;
            int sub = row >> 6, d = row & 63;
            uint32_t dst = base + 16384u + (uint32_t)arr * 16384u + sub * 8192u
                           + SWZ((uint32_t)(d * 128 + c * 16));
            const __half* src = (arr == 0 ? vh : vl) + (size_t)d * LL + j0 + sub * 64 + c * 8;
            asm volatile("cp.async.cg.shared.global [%0], [%1], 16;" :: "r"(dst), "l"(src));
        }
        asm volatile("cp.async.commit_group;" ::: "memory");
    };

    issue_tile(0);
    issue_tile(1);
    issue_tile(2);

    // ---- stage Q (persistent: hi @0, lo @16K) ----
    #pragma unroll
    for (int e = 0; e < 4; e++) {
        int idx = tid + e * 256;
        int row = idx >> 3, c = idx & 7;
        uint32_t sw = SWZ((uint32_t)(row * 128 + c * 16));
        *(uint4*)(smem + sw)         = *(const uint4*)(qh + (size_t)row * QKS + c * 8);
        *(uint4*)(smem + 16384 + sw) = *(const uint4*)(ql + (size_t)row * QKS + c * 8);
    }
    __syncthreads();
    uint32_t qfh[4][4], qfl[4][4];
    #pragma unroll
    for (int kk = 0; kk < 4; kk++) {
        ldsm4(qfh[kk][0], qfh[kk][1], qfh[kk][2], qfh[kk][3],
              sb + ((uint32_t)w << 11) + swzA[kk]);
        ldsm4(qfl[kk][0], qfl[kk][1], qfl[kk][2], qfl[kk][3],
              sb + 16384u + ((uint32_t)w << 11) + swzA[kk]);
    }

    const float LOG2E = 1.4426950408889634f;
    float m0 = -INFINITY, m1 = -INFINITY, l0 = 0.f, l1 = 0.f;
    float O[8][4] = {};

    for (int t = 0; t < 16; t++) {
        if (t < 14)      asm volatile("cp.async.wait_group 2;" ::: "memory");
        else if (t == 14) asm volatile("cp.async.wait_group 1;" ::: "memory");
        else              asm volatile("cp.async.wait_group 0;" ::: "memory");
        __syncthreads();
        const uint32_t base = bufbase(t);

        // ---- S = Q K^T (m16 x n128, fp16 2-pass) ----
        float s[16][4];
        #pragma unroll
        for (int tt = 0; tt < 16; tt++) {
            s[tt][0] = 0.f; s[tt][1] = 0.f; s[tt][2] = 0.f; s[tt][3] = 0.f;
        }
        #pragma unroll
        for (int kk = 0; kk < 4; kk++) {
            #pragma unroll
            for (int np = 0; np < 8; np++) {
                uint32_t b0, b1, b2, b3;
                ldsm4(b0, b1, b2, b3, base + ((uint32_t)np << 11) + swzB[kk]);
                mma16816h(s[2 * np],     qfh[kk], b0, b1);
                mma16816h(s[2 * np],     qfl[kk], b0, b1);
                mma16816h(s[2 * np + 1], qfh[kk], b2, b3);
                mma16816h(s[2 * np + 1], qfl[kk], b2, b3);
            }
        }

        // ---- online softmax (2 rows per thread) ----
        float mx0 = -INFINITY, mx1 = -INFINITY;
        #pragma unroll
        for (int tt = 0; tt < 16; tt++) {
            mx0 = fmaxf(mx0, fmaxf(s[tt][0], s[tt][1]));
            mx1 = fmaxf(mx1, fmaxf(s[tt][2], s[tt][3]));
        }
        mx0 = fmaxf(mx0, __shfl_xor_sync(0xffffffffu, mx0, 1));
        mx0 = fmaxf(mx0, __shfl_xor_sync(0xffffffffu, mx0, 2));
        mx1 = fmaxf(mx1, __shfl_xor_sync(0xffffffffu, mx1, 1));
        mx1 = fmaxf(mx1, __shfl_xor_sync(0xffffffffu, mx1, 2));

        float mn0 = fmaxf(m0, mx0), mn1 = fmaxf(m1, mx1);
        float a0 = ex2((m0 - mn0) * LOG2E), a1 = ex2((m1 - mn1) * LOG2E);
        float rs0 = 0.f, rs1 = 0.f;
        #pragma unroll
        for (int tt = 0; tt < 16; tt++) {
            s[tt][0] = ex2((s[tt][0] - mn0) * LOG2E);
            s[tt][1] = ex2((s[tt][1] - mn0) * LOG2E);
            s[tt][2] = ex2((s[tt][2] - mn1) * LOG2E);
            s[tt][3] = ex2((s[tt][3] - mn1) * LOG2E);
            rs0 += s[tt][0] + s[tt][1];
            rs1 += s[tt][2] + s[tt][3];
        }
        rs0 += __shfl_xor_sync(0xffffffffu, rs0, 1);
        rs0 += __shfl_xor_sync(0xffffffffu, rs0, 2);
        rs1 += __shfl_xor_sync(0xffffffffu, rs1, 1);
        rs1 += __shfl_xor_sync(0xffffffffu, rs1, 2);
        l0 = l0 * a0 + rs0; l1 = l1 * a1 + rs1;
        m0 = mn0; m1 = mn1;
        #pragma unroll
        for (int tt = 0; tt < 8; tt++) {
            O[tt][0] *= a0; O[tt][1] *= a0;
            O[tt][2] *= a1; O[tt][3] *= a1;
        }

        // ---- P -> fp16 A-frags ----
        uint32_t p[8][4];
        #pragma unroll
        for (int kg = 0; kg < 8; kg++) {
            p[kg][0] = cvt2f16(s[2 * kg][0],     s[2 * kg][1]);
            p[kg][1] = cvt2f16(s[2 * kg][2],     s[2 * kg][3]);
            p[kg][2] = cvt2f16(s[2 * kg + 1][0], s[2 * kg + 1][1]);
            p[kg][3] = cvt2f16(s[2 * kg + 1][2], s[2 * kg + 1][3]);
        }

        // ---- O += P V^T (fp16: P x V_hi + P x V_lo) ----
        const uint32_t vb = base + 16384u;
        #pragma unroll
        for (int kg = 0; kg < 8; kg++) {
            const uint32_t sub = (uint32_t)(kg >> 2) * 8192u;
            const int kkin = kg & 3;
            #pragma unroll
            for (int dnp = 0; dnp < 4; dnp++) {
                uint32_t b0, b1, b2, b3, c0, c1, c2, c3;
                ldsm4(b0, b1, b2, b3, vb + sub + ((uint32_t)dnp << 11) + swzB[kkin]);
                ldsm4(c0, c1, c2, c3, vb + 16384u + sub + ((uint32_t)dnp << 11) + swzB[kkin]);
                mma16816h(O[2 * dnp],     p[kg], b0, b1);
                mma16816h(O[2 * dnp],     p[kg], c0, c1);
                mma16816h(O[2 * dnp + 1], p[kg], b2, b3);
                mma16816h(O[2 * dnp + 1], p[kg], c2, c3);
            }
        }

        __syncthreads();
        if (t + 3 < 16) issue_tile(t + 3);
    }

    // ---- normalize + write bf16 hi/lo att [b][l][512] ----
    const float inv0 = 1.0f / l0, inv1 = 1.0f / l1;
    const int r0 = i0 + 16 * w + (lane >> 2);
    size_t o0 = ((size_t)b * LL + r0) * HID + h * DD + 2 * (lane & 3);
    size_t o1 = o0 + (size_t)8 * HID;
    #pragma unroll
    for (int tt = 0; tt < 8; tt++) {
        uint32_t h0, lo0, h1, lo1;
        pack_pair(O[tt][0] * inv0, O[tt][1] * inv0, h0, lo0);
        pack_pair(O[tt][2] * inv1, O[tt][3] * inv1, h1, lo1);
        *(uint32_t*)&g_att_hi[o0 + 8 * tt] = h0;
        *(uint32_t*)&g_att_lo[o0 + 8 * tt] = lo0;
        *(uint32_t*)&g_att_hi[o1 + 8 * tt] = h1;
        *(uint32_t*)&g_att_lo[o1 + 8 * tt] = lo1;
    }
}

// ---------------------------------------------------------------------------
extern "C" void kernel_launch(void* const* d_in, const int* in_sizes, int n_in,
                              void* d_out, int out_size)
{
    const float* x     = (const float*)d_in[0];
    const float* w_qkv = (const float*)d_in[1];
    const float* w_out = (const float*)d_in[2];
    const float* b_out = (const float*)d_in[3];
    float* out = (float*)d_out;

    __nv_bfloat16 *wq_h, *wq_l, *wo_h, *wo_l, *xt_h, *xt_l, *at_h, *at_l;
    __half *qk_h, *qk_l, *v_h, *v_l;
    cudaGetSymbolAddress((void**)&wq_h, g_wq_hi);
    cudaGetSymbolAddress((void**)&wq_l, g_wq_lo);
    cudaGetSymbolAddress((void**)&wo_h, g_wo_hi);
    cudaGetSymbolAddress((void**)&wo_l, g_wo_lo);
    cudaGetSymbolAddress((void**)&xt_h, g_xT_hi);
    cudaGetSymbolAddress((void**)&xt_l, g_xT_lo);
    cudaGetSymbolAddress((void**)&qk_h, g_qk_hi);
    cudaGetSymbolAddress((void**)&qk_l, g_qk_lo);
    cudaGetSymbolAddress((void**)&v_h,  g_v_hi);
    cudaGetSymbolAddress((void**)&v_l,  g_v_lo);
    cudaGetSymbolAddress((void**)&at_h, g_att_hi);
    cudaGetSymbolAddress((void**)&at_l, g_att_lo);

    const int GEMM_SMEM = 98304;
    const int ATTN_SMEM = 180224;   // Q 32K + 3 ring stages x 48K
    cudaFuncSetAttribute(mma_gemm<1>, cudaFuncAttributeMaxDynamicSharedMemorySize, GEMM_SMEM);
    cudaFuncSetAttribute(mma_gemm<2>, cudaFuncAttributeMaxDynamicSharedMemorySize, GEMM_SMEM);
    cudaFuncSetAttribute(attn_kernel, cudaFuncAttributeMaxDynamicSharedMemorySize, ATTN_SMEM);

    conv_w<<<(MQKV * CC + CC * HID) / 256, 256>>>(w_qkv, w_out);
    conv_x<<<dim3(LL / 32, CC / 32, BB), dim3(32, 8)>>>(x);

    // L1: C[l][qk_ch] = xT * wq(rows 0..1023)^T  -> g_qk (fp16 hi/lo)
    mma_gemm<2><<<dim3(QKS / 64, LL / 128, BB), 256, GEMM_SMEM>>>(
        xt_h, xt_l, (size_t)LL * CC, wq_h, wq_l, 0,
        (__nv_bfloat16*)qk_h, (__nv_bfloat16*)qk_l, nullptr, nullptr,
        (size_t)LL * QKS, QKS, CC, CC / 64);

    // L2: C[v_ch][l] = wq(rows 1024..1535) * xT^T -> g_v (fp16 hi/lo)
    mma_gemm<2><<<dim3(LL / 64, HID / 128, BB), 256, GEMM_SMEM>>>(
        wq_h + 1024 * CC, wq_l + 1024 * CC, 0, xt_h, xt_l, (size_t)LL * CC,
        (__nv_bfloat16*)v_h, (__nv_bfloat16*)v_l, nullptr, nullptr,
        (size_t)HID * LL, LL, CC, CC / 64);

    attn_kernel<<<dim3(LL / 128, BB * HH), 256, ATTN_SMEM>>>();

    // L3: out[ch][l] = w_out * att^T + bias
    mma_gemm<1><<<dim3(LL / 64, CC / 128, BB), 256, GEMM_SMEM>>>(
        wo_h, wo_l, 0, at_h, at_l, (size_t)LL * HID,
        nullptr, nullptr, out, b_out, (size_t)CC * LL, LL, HID, HID / 64);
}

// round 10
// speedup vs baseline: 5.6331x; 1.1574x over previous
#include <cuda_runtime.h>
#include <cuda_bf16.h>
#include <cuda_fp16.h>
#include <math.h>
#include <stdint.h>

#define BB   4
#define CC   256
#define LL   2048
#define HH   8
#define DD   64
#define HID  512
#define MQKV 1536
#define QKS  1024   // fused q|k channel stride

// ---------------- scratch (allocation-free rule: __device__ globals) -------
__device__ __align__(16) __nv_bfloat16 g_wq_hi[MQKV * CC];
__device__ __align__(16) __nv_bfloat16 g_wq_lo[MQKV * CC];
__device__ __align__(16) __nv_bfloat16 g_wo_hi[CC * HID];
__device__ __align__(16) __nv_bfloat16 g_wo_lo[CC * HID];
__device__ __align__(16) __nv_bfloat16 g_xT_hi[(size_t)BB * LL * CC];
__device__ __align__(16) __nv_bfloat16 g_xT_lo[(size_t)BB * LL * CC];
__device__ __align__(16) __half        g_qk_hi[(size_t)BB * LL * QKS];
__device__ __align__(16) __half        g_qk_lo[(size_t)BB * LL * QKS];
__device__ __align__(16) __half        g_v_hi[(size_t)BB * HID * LL];   // single fp16 V
__device__ __align__(16) __nv_bfloat16 g_att_hi[(size_t)BB * LL * HID];
__device__ __align__(16) __nv_bfloat16 g_att_lo[(size_t)BB * LL * HID];

#define SWZ(x) ((x) ^ (((x) >> 3) & 0x70))

// ---------------- warp-MMA helpers -----------------------------------------
__device__ __forceinline__ uint32_t smem_u32(const void* p) {
    uint32_t a;
    asm("{ .reg .u64 t; cvta.to.shared.u64 t, %1; cvt.u32.u64 %0, t; }"
        : "=r"(a) : "l"(p));
    return a;
}
__device__ __forceinline__ void ldsm4(uint32_t& r0, uint32_t& r1, uint32_t& r2,
                                      uint32_t& r3, uint32_t a) {
    asm volatile("ldmatrix.sync.aligned.m8n8.x4.shared.b16 {%0,%1,%2,%3}, [%4];"
                 : "=r"(r0), "=r"(r1), "=r"(r2), "=r"(r3) : "r"(a));
}
__device__ __forceinline__ void mma16816(float* c, const uint32_t* a,
                                         uint32_t b0, uint32_t b1) {
    asm volatile("mma.sync.aligned.m16n8k16.row.col.f32.bf16.bf16.f32 "
                 "{%0,%1,%2,%3}, {%4,%5,%6,%7}, {%8,%9}, {%0,%1,%2,%3};"
                 : "+f"(c[0]), "+f"(c[1]), "+f"(c[2]), "+f"(c[3])
                 : "r"(a[0]), "r"(a[1]), "r"(a[2]), "r"(a[3]), "r"(b0), "r"(b1));
}
__device__ __forceinline__ void mma16816h(float* c, const uint32_t* a,
                                          uint32_t b0, uint32_t b1) {
    asm volatile("mma.sync.aligned.m16n8k16.row.col.f32.f16.f16.f32 "
                 "{%0,%1,%2,%3}, {%4,%5,%6,%7}, {%8,%9}, {%0,%1,%2,%3};"
                 : "+f"(c[0]), "+f"(c[1]), "+f"(c[2]), "+f"(c[3])
                 : "r"(a[0]), "r"(a[1]), "r"(a[2]), "r"(a[3]), "r"(b0), "r"(b1));
}
__device__ __forceinline__ uint32_t cvt2bf(float p0, float p1) {
    uint32_t r;
    asm("cvt.rn.bf16x2.f32 %0, %1, %2;" : "=r"(r) : "f"(p1), "f"(p0));
    return r;
}
__device__ __forceinline__ uint32_t cvt2f16(float p0, float p1) {
    uint32_t r;
    asm("cvt.rn.f16x2.f32 %0, %1, %2;" : "=r"(r) : "f"(p1), "f"(p0));
    return r;
}
__device__ __forceinline__ void pack_pair(float p0, float p1,
                                          uint32_t& hi, uint32_t& lo) {
    hi = cvt2bf(p0, p1);
    float f0 = __uint_as_float(hi << 16);
    float f1 = __uint_as_float(hi & 0xffff0000u);
    lo = cvt2bf(p0 - f0, p1 - f1);
}
__device__ __forceinline__ void pack_pair_f16(float p0, float p1,
                                              uint32_t& hi, uint32_t& lo) {
    hi = cvt2f16(p0, p1);
    __half2 h2 = *reinterpret_cast<__half2*>(&hi);
    float f0 = __half2float(h2.x);
    float f1 = __half2float(h2.y);
    lo = cvt2f16(p0 - f0, p1 - f1);
}
__device__ __forceinline__ void split_bf16(float x, __nv_bfloat16& h, __nv_bfloat16& l) {
    h = __float2bfloat16(x);
    l = __float2bfloat16(x - __bfloat162float(h));
}
__device__ __forceinline__ float ex2(float x) {
    float y;
    asm("ex2.approx.ftz.f32 %0, %1;" : "=f"(y) : "f"(x));
    return y;
}

// ---------------------------------------------------------------------------
// conv_w / conv_x (unchanged)
// ---------------------------------------------------------------------------
__global__ void conv_w(const float* __restrict__ wq, const float* __restrict__ wo)
{
    const int NQ = MQKV * CC;
    int idx = blockIdx.x * 256 + threadIdx.x;
    if (idx < NQ) {
        float v = wq[idx];
        if (idx < 512 * CC) v *= 0.125f;
        __nv_bfloat16 h, l;
        split_bf16(v, h, l);
        g_wq_hi[idx] = h; g_wq_lo[idx] = l;
    } else {
        int j = idx - NQ;
        if (j < CC * HID) {
            __nv_bfloat16 h, l;
            split_bf16(wo[j], h, l);
            g_wo_hi[j] = h; g_wo_lo[j] = l;
        }
    }
}

__global__ void conv_x(const float* __restrict__ x)
{
    __shared__ float t[32][33];
    const int b = blockIdx.z;
    const int c0 = blockIdx.y * 32, l0 = blockIdx.x * 32;
    const int tx = threadIdx.x, ty = threadIdx.y;
    const float* xb = x + ((size_t)b * CC + c0) * LL + l0;
    #pragma unroll
    for (int i = 0; i < 4; i++)
        t[ty + 8 * i][tx] = xb[(size_t)(ty + 8 * i) * LL + tx];
    __syncthreads();
    #pragma unroll
    for (int i = 0; i < 4; i++) {
        int row = ty + 8 * i;
        float v = t[tx][row];
        __nv_bfloat16 h, l2;
        split_bf16(v, h, l2);
        size_t o = ((size_t)b * LL + l0 + row) * CC + c0 + tx;
        g_xT_hi[o] = h; g_xT_lo[o] = l2;
    }
}

// ---------------------------------------------------------------------------
// Generic bf16-split MMA GEMM. MODE 1: fp32+bias. MODE 2: fp16 hi/lo out.
// MODE 3: fp16 hi-only out.
// ---------------------------------------------------------------------------
template<int MODE>
__global__ void __launch_bounds__(256, 1) mma_gemm(
    const __nv_bfloat16* __restrict__ Ah, const __nv_bfloat16* __restrict__ Al, size_t sA,
    const __nv_bfloat16* __restrict__ Bh, const __nv_bfloat16* __restrict__ Bl, size_t sB,
    __nv_bfloat16* Yh, __nv_bfloat16* Yl, float* Yf, const float* bias, size_t sY,
    int N, int K, int nkc)
{
    extern __shared__ __align__(1024) char smem[];
    const uint32_t sb = smem_u32(smem);
    const int tid = threadIdx.x;
    const int lane = tid & 31, w = tid >> 5;
    const int b  = blockIdx.z;
    const int m0 = blockIdx.y * 128;
    const int n0 = blockIdx.x * 64;

    const __nv_bfloat16* Ahb = Ah + (size_t)b * sA;
    const __nv_bfloat16* Alb = Al + (size_t)b * sA;
    const __nv_bfloat16* Bhb = Bh + (size_t)b * sB;
    const __nv_bfloat16* Blb = Bl + (size_t)b * sB;

    const int g = lane >> 3;
    const int rowB = ((g & 2) ? 8 : 0) + (lane & 7);
    const int bytB = (g & 1) * 16;
    const int rowA = lane & 15;
    const int bytA = (lane >> 4) * 16;
    uint32_t swzB[4], swzA[4];
    #pragma unroll
    for (int kk = 0; kk < 4; kk++) {
        swzB[kk] = SWZ((uint32_t)(rowB * 128 + bytB + kk * 32));
        swzA[kk] = SWZ((uint32_t)(rowA * 128 + bytA + kk * 32));
    }

    auto issue = [&](int kc) {
        const uint32_t base = sb + (uint32_t)(kc & 1) * 49152u;
        const int koff = kc * 64;
        #pragma unroll
        for (int e = 0; e < 4; e++) {
            int wi = tid + e * 256;
            int row = wi >> 3, c = wi & 7;
            uint32_t sw = SWZ((uint32_t)(row * 128 + c * 16));
            const __nv_bfloat16* s0 = Ahb + (size_t)(m0 + row) * K + koff + c * 8;
            const __nv_bfloat16* s1 = Alb + (size_t)(m0 + row) * K + koff + c * 8;
            asm volatile("cp.async.cg.shared.global [%0], [%1], 16;" :: "r"(base + sw), "l"(s0));
            asm volatile("cp.async.cg.shared.global [%0], [%1], 16;" :: "r"(base + 16384u + sw), "l"(s1));
        }
        #pragma unroll
        for (int e = 0; e < 2; e++) {
            int wi = tid + e * 256;
            int row = wi >> 3, c = wi & 7;
            uint32_t sw = SWZ((uint32_t)(row * 128 + c * 16));
            const __nv_bfloat16* s0 = Bhb + (size_t)(n0 + row) * K + koff + c * 8;
            const __nv_bfloat16* s1 = Blb + (size_t)(n0 + row) * K + koff + c * 8;
            asm volatile("cp.async.cg.shared.global [%0], [%1], 16;" :: "r"(base + 32768u + sw), "l"(s0));
            asm volatile("cp.async.cg.shared.global [%0], [%1], 16;" :: "r"(base + 40960u + sw), "l"(s1));
        }
        asm volatile("cp.async.commit_group;" ::: "memory");
    };

    issue(0);

    float s[8][4] = {};

    for (int kc = 0; kc < nkc; kc++) {
        asm volatile("cp.async.wait_group 0;" ::: "memory");
        __syncthreads();
        if (kc + 1 < nkc) issue(kc + 1);

        const uint32_t base = sb + (uint32_t)(kc & 1) * 49152u;
        const uint32_t ab = base + ((uint32_t)w << 11);

        #pragma unroll
        for (int kk = 0; kk < 4; kk++) {
            uint32_t ah[4], al[4];
            ldsm4(ah[0], ah[1], ah[2], ah[3], ab + swzA[kk]);
            ldsm4(al[0], al[1], al[2], al[3], ab + 16384u + swzA[kk]);
            #pragma unroll
            for (int np = 0; np < 4; np++) {
                uint32_t b0, b1, b2, b3, c0, c1, c2, c3;
                ldsm4(b0, b1, b2, b3, base + 32768u + ((uint32_t)np << 11) + swzB[kk]);
                ldsm4(c0, c1, c2, c3, base + 40960u + ((uint32_t)np << 11) + swzB[kk]);
                mma16816(s[2 * np],     ah, b0, b1);
                mma16816(s[2 * np],     al, b0, b1);
                mma16816(s[2 * np],     ah, c0, c1);
                mma16816(s[2 * np + 1], ah, b2, b3);
                mma16816(s[2 * np + 1], al, b2, b3);
                mma16816(s[2 * np + 1], ah, c2, c3);
            }
        }
        __syncthreads();
    }

    const int mr = m0 + w * 16 + (lane >> 2);
    const int nc = n0 + 2 * (lane & 3);
    if (MODE == 2) {
        __nv_bfloat16* Yhb = Yh + (size_t)b * sY;
        __nv_bfloat16* Ylb = Yl + (size_t)b * sY;
        #pragma unroll
        for (int tt = 0; tt < 8; tt++) {
            uint32_t h0, l0, h1, l1;
            pack_pair_f16(s[tt][0], s[tt][1], h0, l0);
            pack_pair_f16(s[tt][2], s[tt][3], h1, l1);
            size_t o0 = (size_t)mr * N + nc + 8 * tt;
            size_t o1 = (size_t)(mr + 8) * N + nc + 8 * tt;
            *(uint32_t*)&Yhb[o0] = h0; *(uint32_t*)&Ylb[o0] = l0;
            *(uint32_t*)&Yhb[o1] = h1; *(uint32_t*)&Ylb[o1] = l1;
        }
    } else if (MODE == 3) {
        __nv_bfloat16* Yhb = Yh + (size_t)b * sY;
        #pragma unroll
        for (int tt = 0; tt < 8; tt++) {
            uint32_t h0 = cvt2f16(s[tt][0], s[tt][1]);
            uint32_t h1 = cvt2f16(s[tt][2], s[tt][3]);
            *(uint32_t*)&Yhb[(size_t)mr * N + nc + 8 * tt]       = h0;
            *(uint32_t*)&Yhb[(size_t)(mr + 8) * N + nc + 8 * tt] = h1;
        }
    } else {
        float* Yfb = Yf + (size_t)b * sY;
        const float bv0 = bias[mr], bv1 = bias[mr + 8];
        #pragma unroll
        for (int tt = 0; tt < 8; tt++) {
            float2 v0, v1;
            v0.x = s[tt][0] + bv0; v0.y = s[tt][1] + bv0;
            v1.x = s[tt][2] + bv1; v1.y = s[tt][3] + bv1;
            *(float2*)(Yfb + (size_t)mr * N + nc + 8 * tt)       = v0;
            *(float2*)(Yfb + (size_t)(mr + 8) * N + nc + 8 * tt) = v1;
        }
    }
}

// ---------------------------------------------------------------------------
// Flash attention: fp16 MMA. S = (q_hi + q_lo)·k_hi (2-pass). PV = p·v
// (single pass, v fp16). 128-key tiles, 3-stage 32KB ring + 32KB Q = 128KB.
// stage layout: K 0..16K | V 16..32K (two 8K subtiles)
// ---------------------------------------------------------------------------
__global__ void __launch_bounds__(256, 1) attn_kernel()
{
    extern __shared__ __align__(1024) char smem[];
    const uint32_t sb = smem_u32(smem);
    const int tid = threadIdx.x;
    const int lane = tid & 31, w = tid >> 5;
    const int bh = blockIdx.y;
    const int b = bh >> 3, h = bh & 7;
    const int i0 = blockIdx.x * 128;

    const __half* qh = g_qk_hi + ((size_t)b * LL + i0) * QKS + h * DD;
    const __half* ql = g_qk_lo + ((size_t)b * LL + i0) * QKS + h * DD;
    const __half* kh = g_qk_hi + (size_t)b * LL * QKS + 512 + h * DD;
    const __half* vh = g_v_hi + ((size_t)b * HID + h * DD) * LL;

    const int g = lane >> 3;
    const int rowB = ((g & 2) ? 8 : 0) + (lane & 7);
    const int bytB = (g & 1) * 16;
    const int rowA = lane & 15;
    const int bytA = (lane >> 4) * 16;
    uint32_t swzB[4], swzA[4];
    #pragma unroll
    for (int kk = 0; kk < 4; kk++) {
        swzB[kk] = SWZ((uint32_t)(rowB * 128 + bytB + kk * 32));
        swzA[kk] = SWZ((uint32_t)(rowA * 128 + bytA + kk * 32));
    }

    auto bufbase = [&](int jt) -> uint32_t {
        return sb + 32768u + (uint32_t)(jt % 3) * 32768u;
    };

    // one 128-key tile: K 128x128B + V (2x 64x128B subtiles) = 32KB
    auto issue_tile = [&](int jt) {
        const int j0 = jt * 128;
        const uint32_t base = bufbase(jt);
        #pragma unroll
        for (int e = 0; e < 4; e++) {
            int wi = tid + e * 256;
            int row = wi >> 3, c = wi & 7;
            uint32_t dst = base + SWZ((uint32_t)(row * 128 + c * 16));
            const __half* src = kh + (size_t)(j0 + row) * QKS + c * 8;
            asm volatile("cp.async.cg.shared.global [%0], [%1], 16;" :: "r"(dst), "l"(src));
        }
        #pragma unroll
        for (int e = 0; e < 4; e++) {
            int wi = tid + e * 256;     // 0..1023
            int row = wi >> 3, c = wi & 7;
            int sub = row >> 6, d = row & 63;
            uint32_t dst = base + 16384u + sub * 8192u + SWZ((uint32_t)(d * 128 + c * 16));
            const __half* src = vh + (size_t)d * LL + j0 + sub * 64 + c * 8;
            asm volatile("cp.async.cg.shared.global [%0], [%1], 16;" :: "r"(dst), "l"(src));
        }
        asm volatile("cp.async.commit_group;" ::: "memory");
    };

    issue_tile(0);
    issue_tile(1);
    issue_tile(2);

    // ---- stage Q (persistent: hi @0, lo @16K) ----
    #pragma unroll
    for (int e = 0; e < 4; e++) {
        int idx = tid + e * 256;
        int row = idx >> 3, c = idx & 7;
        uint32_t sw = SWZ((uint32_t)(row * 128 + c * 16));
        *(uint4*)(smem + sw)         = *(const uint4*)(qh + (size_t)row * QKS + c * 8);
        *(uint4*)(smem + 16384 + sw) = *(const uint4*)(ql + (size_t)row * QKS + c * 8);
    }
    __syncthreads();
    uint32_t qfh[4][4], qfl[4][4];
    #pragma unroll
    for (int kk = 0; kk < 4; kk++) {
        ldsm4(qfh[kk][0], qfh[kk][1], qfh[kk][2], qfh[kk][3],
              sb + ((uint32_t)w << 11) + swzA[kk]);
        ldsm4(qfl[kk][0], qfl[kk][1], qfl[kk][2], qfl[kk][3],
              sb + 16384u + ((uint32_t)w << 11) + swzA[kk]);
    }

    const float LOG2E = 1.4426950408889634f;
    float m0 = -INFINITY, m1 = -INFINITY, l0 = 0.f, l1 = 0.f;
    float O[8][4] = {};

    for (int t = 0; t < 16; t++) {
        if (t < 14)       asm volatile("cp.async.wait_group 2;" ::: "memory");
        else if (t == 14) asm volatile("cp.async.wait_group 1;" ::: "memory");
        else              asm volatile("cp.async.wait_group 0;" ::: "memory");
        __syncthreads();
        const uint32_t base = bufbase(t);

        // ---- S = Q K^T (m16 x n128, fp16 2-pass) ----
        float s[16][4];
        #pragma unroll
        for (int tt = 0; tt < 16; tt++) {
            s[tt][0] = 0.f; s[tt][1] = 0.f; s[tt][2] = 0.f; s[tt][3] = 0.f;
        }
        #pragma unroll
        for (int kk = 0; kk < 4; kk++) {
            #pragma unroll
            for (int np = 0; np < 8; np++) {
                uint32_t b0, b1, b2, b3;
                ldsm4(b0, b1, b2, b3, base + ((uint32_t)np << 11) + swzB[kk]);
                mma16816h(s[2 * np],     qfh[kk], b0, b1);
                mma16816h(s[2 * np],     qfl[kk], b0, b1);
                mma16816h(s[2 * np + 1], qfh[kk], b2, b3);
                mma16816h(s[2 * np + 1], qfl[kk], b2, b3);
            }
        }

        // ---- online softmax (2 rows per thread) ----
        float mx0 = -INFINITY, mx1 = -INFINITY;
        #pragma unroll
        for (int tt = 0; tt < 16; tt++) {
            mx0 = fmaxf(mx0, fmaxf(s[tt][0], s[tt][1]));
            mx1 = fmaxf(mx1, fmaxf(s[tt][2], s[tt][3]));
        }
        mx0 = fmaxf(mx0, __shfl_xor_sync(0xffffffffu, mx0, 1));
        mx0 = fmaxf(mx0, __shfl_xor_sync(0xffffffffu, mx0, 2));
        mx1 = fmaxf(mx1, __shfl_xor_sync(0xffffffffu, mx1, 1));
        mx1 = fmaxf(mx1, __shfl_xor_sync(0xffffffffu, mx1, 2));

        float mn0 = fmaxf(m0, mx0), mn1 = fmaxf(m1, mx1);
        float a0 = ex2((m0 - mn0) * LOG2E), a1 = ex2((m1 - mn1) * LOG2E);
        float rs0 = 0.f, rs1 = 0.f;
        #pragma unroll
        for (int tt = 0; tt < 16; tt++) {
            s[tt][0] = ex2((s[tt][0] - mn0) * LOG2E);
            s[tt][1] = ex2((s[tt][1] - mn0) * LOG2E);
            s[tt][2] = ex2((s[tt][2] - mn1) * LOG2E);
            s[tt][3] = ex2((s[tt][3] - mn1) * LOG2E);
            rs0 += s[tt][0] + s[tt][1];
            rs1 += s[tt][2] + s[tt][3];
        }
        rs0 += __shfl_xor_sync(0xffffffffu, rs0, 1);
        rs0 += __shfl_xor_sync(0xffffffffu, rs0, 2);
        rs1 += __shfl_xor_sync(0xffffffffu, rs1, 1);
        rs1 += __shfl_xor_sync(0xffffffffu, rs1, 2);
        l0 = l0 * a0 + rs0; l1 = l1 * a1 + rs1;
        m0 = mn0; m1 = mn1;
        #pragma unroll
        for (int tt = 0; tt < 8; tt++) {
            O[tt][0] *= a0; O[tt][1] *= a0;
            O[tt][2] *= a1; O[tt][3] *= a1;
        }

        // ---- P -> fp16 A-frags ----
        uint32_t p[8][4];
        #pragma unroll
        for (int kg = 0; kg < 8; kg++) {
            p[kg][0] = cvt2f16(s[2 * kg][0],     s[2 * kg][1]);
            p[kg][1] = cvt2f16(s[2 * kg][2],     s[2 * kg][3]);
            p[kg][2] = cvt2f16(s[2 * kg + 1][0], s[2 * kg + 1][1]);
            p[kg][3] = cvt2f16(s[2 * kg + 1][2], s[2 * kg + 1][3]);
        }

        // ---- O += P V^T (fp16, single pass) ----
        const uint32_t vb = base + 16384u;
        #pragma unroll
        for (int kg = 0; kg < 8; kg++) {
            const uint32_t sub = (uint32_t)(kg >> 2) * 8192u;
            const int kkin = kg & 3;
            #pragma unroll
            for (int dnp = 0; dnp < 4; dnp++) {
                uint32_t b0, b1, b2, b3;
                ldsm4(b0, b1, b2, b3, vb + sub + ((uint32_t)dnp << 11) + swzB[kkin]);
                mma16816h(O[2 * dnp],     p[kg], b0, b1);
                mma16816h(O[2 * dnp + 1], p[kg], b2, b3);
            }
        }

        __syncthreads();
        if (t + 3 < 16) issue_tile(t + 3);
    }

    // ---- normalize + write bf16 hi/lo att [b][l][512] ----
    const float inv0 = 1.0f / l0, inv1 = 1.0f / l1;
    const int r0 = i0 + 16 * w + (lane >> 2);
    size_t o0 = ((size_t)b * LL + r0) * HID + h * DD + 2 * (lane & 3);
    size_t o1 = o0 + (size_t)8 * HID;
    #pragma unroll
    for (int tt = 0; tt < 8; tt++) {
        uint32_t h0, lo0, h1, lo1;
        pack_pair(O[tt][0] * inv0, O[tt][1] * inv0, h0, lo0);
        pack_pair(O[tt][2] * inv1, O[tt][3] * inv1, h1, lo1);
        *(uint32_t*)&g_att_hi[o0 + 8 * tt] = h0;
        *(uint32_t*)&g_att_lo[o0 + 8 * tt] = lo0;
        *(uint32_t*)&g_att_hi[o1 + 8 * tt] = h1;
        *(uint32_t*)&g_att_lo[o1 + 8 * tt] = lo1;
    }
}

// ---------------------------------------------------------------------------
extern "C" void kernel_launch(void* const* d_in, const int* in_sizes, int n_in,
                              void* d_out, int out_size)
{
    const float* x     = (const float*)d_in[0];
    const float* w_qkv = (const float*)d_in[1];
    const float* w_out = (const float*)d_in[2];
    const float* b_out = (const float*)d_in[3];
    float* out = (float*)d_out;

    __nv_bfloat16 *wq_h, *wq_l, *wo_h, *wo_l, *xt_h, *xt_l, *at_h, *at_l;
    __half *qk_h, *qk_l, *v_h;
    cudaGetSymbolAddress((void**)&wq_h, g_wq_hi);
    cudaGetSymbolAddress((void**)&wq_l, g_wq_lo);
    cudaGetSymbolAddress((void**)&wo_h, g_wo_hi);
    cudaGetSymbolAddress((void**)&wo_l, g_wo_lo);
    cudaGetSymbolAddress((void**)&xt_h, g_xT_hi);
    cudaGetSymbolAddress((void**)&xt_l, g_xT_lo);
    cudaGetSymbolAddress((void**)&qk_h, g_qk_hi);
    cudaGetSymbolAddress((void**)&qk_l, g_qk_lo);
    cudaGetSymbolAddress((void**)&v_h,  g_v_hi);
    cudaGetSymbolAddress((void**)&at_h, g_att_hi);
    cudaGetSymbolAddress((void**)&at_l, g_att_lo);

    const int GEMM_SMEM = 98304;
    const int ATTN_SMEM = 131072;   // Q 32K + 3 ring stages x 32K
    cudaFuncSetAttribute(mma_gemm<1>, cudaFuncAttributeMaxDynamicSharedMemorySize, GEMM_SMEM);
    cudaFuncSetAttribute(mma_gemm<2>, cudaFuncAttributeMaxDynamicSharedMemorySize, GEMM_SMEM);
    cudaFuncSetAttribute(mma_gemm<3>, cudaFuncAttributeMaxDynamicSharedMemorySize, GEMM_SMEM);
    cudaFuncSetAttribute(attn_kernel, cudaFuncAttributeMaxDynamicSharedMemorySize, ATTN_SMEM);

    conv_w<<<(MQKV * CC + CC * HID) / 256, 256>>>(w_qkv, w_out);
    conv_x<<<dim3(LL / 32, CC / 32, BB), dim3(32, 8)>>>(x);

    // L1: C[l][qk_ch] = xT * wq(rows 0..1023)^T  -> g_qk (fp16 hi/lo)
    mma_gemm<2><<<dim3(QKS / 64, LL / 128, BB), 256, GEMM_SMEM>>>(
        xt_h, xt_l, (size_t)LL * CC, wq_h, wq_l, 0,
        (__nv_bfloat16*)qk_h, (__nv_bfloat16*)qk_l, nullptr, nullptr,
        (size_t)LL * QKS, QKS, CC, CC / 64);

    // L2: C[v_ch][l] = wq(rows 1024..1535) * xT^T -> g_v (fp16 hi only)
    mma_gemm<3><<<dim3(LL / 64, HID / 128, BB), 256, GEMM_SMEM>>>(
        wq_h + 1024 * CC, wq_l + 1024 * CC, 0, xt_h, xt_l, (size_t)LL * CC,
        (__nv_bfloat16*)v_h, nullptr, nullptr, nullptr,
        (size_t)HID * LL, LL, CC, CC / 64);

    attn_kernel<<<dim3(LL / 128, BB * HH), 256, ATTN_SMEM>>>();

    // L3: out[ch][l] = w_out * att^T + bias
    mma_gemm<1><<<dim3(LL / 64, CC / 128, BB), 256, GEMM_SMEM>>>(
        wo_h, wo_l, 0, at_h, at_l, (size_t)LL * HID,
        nullptr, nullptr, out, b_out, (size_t)CC * LL, LL, HID, HID / 64);
}

// round 11
// speedup vs baseline: 7.3621x; 1.3069x over previous
#include <cuda_runtime.h>
#include <cuda_fp16.h>
#include <math.h>
#include <stdint.h>

#define BB   4
#define CC   256
#define LL   2048
#define HH   8
#define DD   64
#define HID  512
#define MQKV 1536
#define QKS  1024   // fused q|k channel stride

// ---------------- scratch (allocation-free rule: __device__ globals) -------
__device__ __align__(16) __half g_wq_hi[MQKV * CC];
__device__ __align__(16) __half g_wq_lo[MQKV * CC];
__device__ __align__(16) __half g_wo_hi[CC * HID];
__device__ __align__(16) __half g_wo_lo[CC * HID];
__device__ __align__(16) __half g_xT_hi[(size_t)BB * LL * CC];
__device__ __align__(16) __half g_xT_lo[(size_t)BB * LL * CC];
__device__ __align__(16) __half g_qk[(size_t)BB * LL * QKS];   // fp16 single
__device__ __align__(16) __half g_v[(size_t)BB * HID * LL];    // fp16 single
__device__ __align__(16) __half g_att[(size_t)BB * LL * HID];  // fp16 single

#define SWZ(x) ((x) ^ (((x) >> 3) & 0x70))

// ---------------- warp-MMA helpers -----------------------------------------
__device__ __forceinline__ uint32_t smem_u32(const void* p) {
    uint32_t a;
    asm("{ .reg .u64 t; cvta.to.shared.u64 t, %1; cvt.u32.u64 %0, t; }"
        : "=r"(a) : "l"(p));
    return a;
}
__device__ __forceinline__ void ldsm4(uint32_t& r0, uint32_t& r1, uint32_t& r2,
                                      uint32_t& r3, uint32_t a) {
    asm volatile("ldmatrix.sync.aligned.m8n8.x4.shared.b16 {%0,%1,%2,%3}, [%4];"
                 : "=r"(r0), "=r"(r1), "=r"(r2), "=r"(r3) : "r"(a));
}
__device__ __forceinline__ void mma16816h(float* c, const uint32_t* a,
                                          uint32_t b0, uint32_t b1) {
    asm volatile("mma.sync.aligned.m16n8k16.row.col.f32.f16.f16.f32 "
                 "{%0,%1,%2,%3}, {%4,%5,%6,%7}, {%8,%9}, {%0,%1,%2,%3};"
                 : "+f"(c[0]), "+f"(c[1]), "+f"(c[2]), "+f"(c[3])
                 : "r"(a[0]), "r"(a[1]), "r"(a[2]), "r"(a[3]), "r"(b0), "r"(b1));
}
__device__ __forceinline__ uint32_t cvt2f16(float p0, float p1) {
    uint32_t r;
    asm("cvt.rn.f16x2.f32 %0, %1, %2;" : "=r"(r) : "f"(p1), "f"(p0));
    return r;
}
__device__ __forceinline__ void split_f16(float x, __half& h, __half& l) {
    h = __float2half(x);
    l = __float2half(x - __half2float(h));
}
__device__ __forceinline__ float ex2(float x) {
    float y;
    asm("ex2.approx.ftz.f32 %0, %1;" : "=f"(y) : "f"(x));
    return y;
}

// ---------------------------------------------------------------------------
// conv_w: fp16 hi/lo split of both weights; q rows (<512) pre-scaled x0.125.
// ---------------------------------------------------------------------------
__global__ void conv_w(const float* __restrict__ wq, const float* __restrict__ wo)
{
    const int NQ = MQKV * CC;
    int idx = blockIdx.x * 256 + threadIdx.x;
    if (idx < NQ) {
        float v = wq[idx];
        if (idx < 512 * CC) v *= 0.125f;
        __half h, l;
        split_f16(v, h, l);
        g_wq_hi[idx] = h; g_wq_lo[idx] = l;
    } else {
        int j = idx - NQ;
        if (j < CC * HID) {
            __half h, l;
            split_f16(wo[j], h, l);
            g_wo_hi[j] = h; g_wo_lo[j] = l;
        }
    }
}

// ---------------------------------------------------------------------------
// conv_x: transpose + fp16 split x [b][256][2048] -> xT [b][2048][256].
// ---------------------------------------------------------------------------
__global__ void conv_x(const float* __restrict__ x)
{
    __shared__ float t[32][33];
    const int b = blockIdx.z;
    const int c0 = blockIdx.y * 32, l0 = blockIdx.x * 32;
    const int tx = threadIdx.x, ty = threadIdx.y;
    const float* xb = x + ((size_t)b * CC + c0) * LL + l0;
    #pragma unroll
    for (int i = 0; i < 4; i++)
        t[ty + 8 * i][tx] = xb[(size_t)(ty + 8 * i) * LL + tx];
    __syncthreads();
    #pragma unroll
    for (int i = 0; i < 4; i++) {
        int row = ty + 8 * i;
        float v = t[tx][row];
        __half h, l2;
        split_f16(v, h, l2);
        size_t o = ((size_t)b * LL + l0 + row) * CC + c0 + tx;
        g_xT_hi[o] = h; g_xT_lo[o] = l2;
    }
}

// ---------------------------------------------------------------------------
// fp16 2-pass MMA GEMM: C[m][n] = sum_k (A_hi+A_lo)[m][k] * B_hi[n][k].
// CTA 128(M) x 64(N), 8 warps, K-chunks of 64, double-buffered.
// MODE 3: fp16 out. MODE 1: fp32 + bias[m] out.
// smem/stage: AH 0..16K | AL 16..32K | BH 32..40K ; stage stride 40K.
// ---------------------------------------------------------------------------
template<int MODE>
__global__ void __launch_bounds__(256, 1) mma_gemm(
    const __half* __restrict__ Ah, const __half* __restrict__ Al, size_t sA,
    const __half* __restrict__ Bh, size_t sB,
    __half* Yh, float* Yf, const float* bias, size_t sY,
    int N, int K, int nkc)
{
    extern __shared__ __align__(1024) char smem[];
    const uint32_t sb = smem_u32(smem);
    const int tid = threadIdx.x;
    const int lane = tid & 31, w = tid >> 5;
    const int b  = blockIdx.z;
    const int m0 = blockIdx.y * 128;
    const int n0 = blockIdx.x * 64;

    const __half* Ahb = Ah + (size_t)b * sA;
    const __half* Alb = Al + (size_t)b * sA;
    const __half* Bhb = Bh + (size_t)b * sB;

    const int g = lane >> 3;
    const int rowB = ((g & 2) ? 8 : 0) + (lane & 7);
    const int bytB = (g & 1) * 16;
    const int rowA = lane & 15;
    const int bytA = (lane >> 4) * 16;
    uint32_t swzB[4], swzA[4];
    #pragma unroll
    for (int kk = 0; kk < 4; kk++) {
        swzB[kk] = SWZ((uint32_t)(rowB * 128 + bytB + kk * 32));
        swzA[kk] = SWZ((uint32_t)(rowA * 128 + bytA + kk * 32));
    }

    auto issue = [&](int kc) {
        const uint32_t base = sb + (uint32_t)(kc & 1) * 40960u;
        const int koff = kc * 64;
        #pragma unroll
        for (int e = 0; e < 4; e++) {
            int wi = tid + e * 256;          // 0..1023
            int row = wi >> 3, c = wi & 7;
            uint32_t sw = SWZ((uint32_t)(row * 128 + c * 16));
            const __half* s0 = Ahb + (size_t)(m0 + row) * K + koff + c * 8;
            const __half* s1 = Alb + (size_t)(m0 + row) * K + koff + c * 8;
            asm volatile("cp.async.cg.shared.global [%0], [%1], 16;" :: "r"(base + sw), "l"(s0));
            asm volatile("cp.async.cg.shared.global [%0], [%1], 16;" :: "r"(base + 16384u + sw), "l"(s1));
        }
        #pragma unroll
        for (int e = 0; e < 2; e++) {
            int wi = tid + e * 256;          // 0..511
            int row = wi >> 3, c = wi & 7;
            uint32_t sw = SWZ((uint32_t)(row * 128 + c * 16));
            const __half* s0 = Bhb + (size_t)(n0 + row) * K + koff + c * 8;
            asm volatile("cp.async.cg.shared.global [%0], [%1], 16;" :: "r"(base + 32768u + sw), "l"(s0));
        }
        asm volatile("cp.async.commit_group;" ::: "memory");
    };

    issue(0);

    float s[8][4] = {};

    for (int kc = 0; kc < nkc; kc++) {
        asm volatile("cp.async.wait_group 0;" ::: "memory");
        __syncthreads();
        if (kc + 1 < nkc) issue(kc + 1);

        const uint32_t base = sb + (uint32_t)(kc & 1) * 40960u;
        const uint32_t ab = base + ((uint32_t)w << 11);

        #pragma unroll
        for (int kk = 0; kk < 4; kk++) {
            uint32_t ah[4], al[4];
            ldsm4(ah[0], ah[1], ah[2], ah[3], ab + swzA[kk]);
            ldsm4(al[0], al[1], al[2], al[3], ab + 16384u + swzA[kk]);
            #pragma unroll
            for (int np = 0; np < 4; np++) {
                uint32_t b0, b1, b2, b3;
                ldsm4(b0, b1, b2, b3, base + 32768u + ((uint32_t)np << 11) + swzB[kk]);
                mma16816h(s[2 * np],     ah, b0, b1);
                mma16816h(s[2 * np],     al, b0, b1);
                mma16816h(s[2 * np + 1], ah, b2, b3);
                mma16816h(s[2 * np + 1], al, b2, b3);
            }
        }
        __syncthreads();
    }

    const int mr = m0 + w * 16 + (lane >> 2);
    const int nc = n0 + 2 * (lane & 3);
    if (MODE == 3) {
        __half* Yhb = Yh + (size_t)b * sY;
        #pragma unroll
        for (int tt = 0; tt < 8; tt++) {
            *(uint32_t*)&Yhb[(size_t)mr * N + nc + 8 * tt]       = cvt2f16(s[tt][0], s[tt][1]);
            *(uint32_t*)&Yhb[(size_t)(mr + 8) * N + nc + 8 * tt] = cvt2f16(s[tt][2], s[tt][3]);
        }
    } else {
        float* Yfb = Yf + (size_t)b * sY;
        const float bv0 = bias[mr], bv1 = bias[mr + 8];
        #pragma unroll
        for (int tt = 0; tt < 8; tt++) {
            float2 v0, v1;
            v0.x = s[tt][0] + bv0; v0.y = s[tt][1] + bv0;
            v1.x = s[tt][2] + bv1; v1.y = s[tt][3] + bv1;
            *(float2*)(Yfb + (size_t)mr * N + nc + 8 * tt)       = v0;
            *(float2*)(Yfb + (size_t)(mr + 8) * N + nc + 8 * tt) = v1;
        }
    }
}

// ---------------------------------------------------------------------------
// Flash attention, all-fp16 single-pass MMA: S = q·k, O += p·v. 128-key
// tiles, 3-stage 32KB ring + 16KB Q = 112KB smem.
// stage layout: K 0..16K | V 16..32K (two 8K subtiles)
// ---------------------------------------------------------------------------
__global__ void __launch_bounds__(256, 1) attn_kernel()
{
    extern __shared__ __align__(1024) char smem[];
    const uint32_t sb = smem_u32(smem);
    const int tid = threadIdx.x;
    const int lane = tid & 31, w = tid >> 5;
    const int bh = blockIdx.y;
    const int b = bh >> 3, h = bh & 7;
    const int i0 = blockIdx.x * 128;

    const __half* qp = g_qk + ((size_t)b * LL + i0) * QKS + h * DD;
    const __half* kp = g_qk + (size_t)b * LL * QKS + 512 + h * DD;
    const __half* vp = g_v + ((size_t)b * HID + h * DD) * LL;

    const int g = lane >> 3;
    const int rowB = ((g & 2) ? 8 : 0) + (lane & 7);
    const int bytB = (g & 1) * 16;
    const int rowA = lane & 15;
    const int bytA = (lane >> 4) * 16;
    uint32_t swzB[4], swzA[4];
    #pragma unroll
    for (int kk = 0; kk < 4; kk++) {
        swzB[kk] = SWZ((uint32_t)(rowB * 128 + bytB + kk * 32));
        swzA[kk] = SWZ((uint32_t)(rowA * 128 + bytA + kk * 32));
    }

    auto bufbase = [&](int jt) -> uint32_t {
        return sb + 16384u + (uint32_t)(jt % 3) * 32768u;
    };

    // one 128-key tile: K 128x128B + V (2x 64x128B subtiles) = 32KB
    auto issue_tile = [&](int jt) {
        const int j0 = jt * 128;
        const uint32_t base = bufbase(jt);
        #pragma unroll
        for (int e = 0; e < 4; e++) {
            int wi = tid + e * 256;
            int row = wi >> 3, c = wi & 7;
            uint32_t dst = base + SWZ((uint32_t)(row * 128 + c * 16));
            const __half* src = kp + (size_t)(j0 + row) * QKS + c * 8;
            asm volatile("cp.async.cg.shared.global [%0], [%1], 16;" :: "r"(dst), "l"(src));
        }
        #pragma unroll
        for (int e = 0; e < 4; e++) {
            int wi = tid + e * 256;
            int row = wi >> 3, c = wi & 7;
            int sub = row >> 6, d = row & 63;
            uint32_t dst = base + 16384u + sub * 8192u + SWZ((uint32_t)(d * 128 + c * 16));
            const __half* src = vp + (size_t)d * LL + j0 + sub * 64 + c * 8;
            asm volatile("cp.async.cg.shared.global [%0], [%1], 16;" :: "r"(dst), "l"(src));
        }
        asm volatile("cp.async.commit_group;" ::: "memory");
    };

    issue_tile(0);
    issue_tile(1);
    issue_tile(2);

    // ---- stage Q (persistent, 16KB) ----
    #pragma unroll
    for (int e = 0; e < 4; e++) {
        int idx = tid + e * 256;
        int row = idx >> 3, c = idx & 7;
        uint32_t sw = SWZ((uint32_t)(row * 128 + c * 16));
        *(uint4*)(smem + sw) = *(const uint4*)(qp + (size_t)row * QKS + c * 8);
    }
    __syncthreads();
    uint32_t qf[4][4];
    #pragma unroll
    for (int kk = 0; kk < 4; kk++) {
        ldsm4(qf[kk][0], qf[kk][1], qf[kk][2], qf[kk][3],
              sb + ((uint32_t)w << 11) + swzA[kk]);
    }

    const float LOG2E = 1.4426950408889634f;
    float m0 = -INFINITY, m1 = -INFINITY, l0 = 0.f, l1 = 0.f;
    float O[8][4] = {};

    for (int t = 0; t < 16; t++) {
        if (t < 14)       asm volatile("cp.async.wait_group 2;" ::: "memory");
        else if (t == 14) asm volatile("cp.async.wait_group 1;" ::: "memory");
        else              asm volatile("cp.async.wait_group 0;" ::: "memory");
        __syncthreads();
        const uint32_t base = bufbase(t);

        // ---- S = Q K^T (m16 x n128, fp16 single pass) ----
        float s[16][4];
        #pragma unroll
        for (int tt = 0; tt < 16; tt++) {
            s[tt][0] = 0.f; s[tt][1] = 0.f; s[tt][2] = 0.f; s[tt][3] = 0.f;
        }
        #pragma unroll
        for (int kk = 0; kk < 4; kk++) {
            #pragma unroll
            for (int np = 0; np < 8; np++) {
                uint32_t b0, b1, b2, b3;
                ldsm4(b0, b1, b2, b3, base + ((uint32_t)np << 11) + swzB[kk]);
                mma16816h(s[2 * np],     qf[kk], b0, b1);
                mma16816h(s[2 * np + 1], qf[kk], b2, b3);
            }
        }

        // ---- online softmax (2 rows per thread) ----
        float mx0 = -INFINITY, mx1 = -INFINITY;
        #pragma unroll
        for (int tt = 0; tt < 16; tt++) {
            mx0 = fmaxf(mx0, fmaxf(s[tt][0], s[tt][1]));
            mx1 = fmaxf(mx1, fmaxf(s[tt][2], s[tt][3]));
        }
        mx0 = fmaxf(mx0, __shfl_xor_sync(0xffffffffu, mx0, 1));
        mx0 = fmaxf(mx0, __shfl_xor_sync(0xffffffffu, mx0, 2));
        mx1 = fmaxf(mx1, __shfl_xor_sync(0xffffffffu, mx1, 1));
        mx1 = fmaxf(mx1, __shfl_xor_sync(0xffffffffu, mx1, 2));

        float mn0 = fmaxf(m0, mx0), mn1 = fmaxf(m1, mx1);
        float a0 = ex2((m0 - mn0) * LOG2E), a1 = ex2((m1 - mn1) * LOG2E);
        float rs0 = 0.f, rs1 = 0.f;
        #pragma unroll
        for (int tt = 0; tt < 16; tt++) {
            s[tt][0] = ex2((s[tt][0] - mn0) * LOG2E);
            s[tt][1] = ex2((s[tt][1] - mn0) * LOG2E);
            s[tt][2] = ex2((s[tt][2] - mn1) * LOG2E);
            s[tt][3] = ex2((s[tt][3] - mn1) * LOG2E);
            rs0 += s[tt][0] + s[tt][1];
            rs1 += s[tt][2] + s[tt][3];
        }
        rs0 += __shfl_xor_sync(0xffffffffu, rs0, 1);
        rs0 += __shfl_xor_sync(0xffffffffu, rs0, 2);
        rs1 += __shfl_xor_sync(0xffffffffu, rs1, 1);
        rs1 += __shfl_xor_sync(0xffffffffu, rs1, 2);
        l0 = l0 * a0 + rs0; l1 = l1 * a1 + rs1;
        m0 = mn0; m1 = mn1;
        #pragma unroll
        for (int tt = 0; tt < 8; tt++) {
            O[tt][0] *= a0; O[tt][1] *= a0;
            O[tt][2] *= a1; O[tt][3] *= a1;
        }

        // ---- P -> fp16 A-frags ----
        uint32_t p[8][4];
        #pragma unroll
        for (int kg = 0; kg < 8; kg++) {
            p[kg][0] = cvt2f16(s[2 * kg][0],     s[2 * kg][1]);
            p[kg][1] = cvt2f16(s[2 * kg][2],     s[2 * kg][3]);
            p[kg][2] = cvt2f16(s[2 * kg + 1][0], s[2 * kg + 1][1]);
            p[kg][3] = cvt2f16(s[2 * kg + 1][2], s[2 * kg + 1][3]);
        }

        // ---- O += P V^T (fp16, single pass) ----
        const uint32_t vb = base + 16384u;
        #pragma unroll
        for (int kg = 0; kg < 8; kg++) {
            const uint32_t sub = (uint32_t)(kg >> 2) * 8192u;
            const int kkin = kg & 3;
            #pragma unroll
            for (int dnp = 0; dnp < 4; dnp++) {
                uint32_t b0, b1, b2, b3;
                ldsm4(b0, b1, b2, b3, vb + sub + ((uint32_t)dnp << 11) + swzB[kkin]);
                mma16816h(O[2 * dnp],     p[kg], b0, b1);
                mma16816h(O[2 * dnp + 1], p[kg], b2, b3);
            }
        }

        __syncthreads();
        if (t + 3 < 16) issue_tile(t + 3);
    }

    // ---- normalize + write fp16 att [b][l][512] ----
    const float inv0 = 1.0f / l0, inv1 = 1.0f / l1;
    const int r0 = i0 + 16 * w + (lane >> 2);
    size_t o0 = ((size_t)b * LL + r0) * HID + h * DD + 2 * (lane & 3);
    size_t o1 = o0 + (size_t)8 * HID;
    #pragma unroll
    for (int tt = 0; tt < 8; tt++) {
        *(uint32_t*)&g_att[o0 + 8 * tt] = cvt2f16(O[tt][0] * inv0, O[tt][1] * inv0);
        *(uint32_t*)&g_att[o1 + 8 * tt] = cvt2f16(O[tt][2] * inv1, O[tt][3] * inv1);
    }
}

// ---------------------------------------------------------------------------
extern "C" void kernel_launch(void* const* d_in, const int* in_sizes, int n_in,
                              void* d_out, int out_size)
{
    const float* x     = (const float*)d_in[0];
    const float* w_qkv = (const float*)d_in[1];
    const float* w_out = (const float*)d_in[2];
    const float* b_out = (const float*)d_in[3];
    float* out = (float*)d_out;

    __half *wq_h, *wq_l, *wo_h, *wo_l, *xt_h, *xt_l, *qk, *v, *att;
    cudaGetSymbolAddress((void**)&wq_h, g_wq_hi);
    cudaGetSymbolAddress((void**)&wq_l, g_wq_lo);
    cudaGetSymbolAddress((void**)&wo_h, g_wo_hi);
    cudaGetSymbolAddress((void**)&wo_l, g_wo_lo);
    cudaGetSymbolAddress((void**)&xt_h, g_xT_hi);
    cudaGetSymbolAddress((void**)&xt_l, g_xT_lo);
    cudaGetSymbolAddress((void**)&qk,   g_qk);
    cudaGetSymbolAddress((void**)&v,    g_v);
    cudaGetSymbolAddress((void**)&att,  g_att);

    const int GEMM_SMEM = 81920;    // 2 stages x (AH 16K + AL 16K + BH 8K)
    const int ATTN_SMEM = 114688;   // Q 16K + 3 ring stages x 32K
    cudaFuncSetAttribute(mma_gemm<1>, cudaFuncAttributeMaxDynamicSharedMemorySize, GEMM_SMEM);
    cudaFuncSetAttribute(mma_gemm<3>, cudaFuncAttributeMaxDynamicSharedMemorySize, GEMM_SMEM);
    cudaFuncSetAttribute(attn_kernel, cudaFuncAttributeMaxDynamicSharedMemorySize, ATTN_SMEM);

    conv_w<<<(MQKV * CC + CC * HID) / 256, 256>>>(w_qkv, w_out);
    conv_x<<<dim3(LL / 32, CC / 32, BB), dim3(32, 8)>>>(x);

    // L1: C[l][qk_ch] = (xT_hi+xT_lo) * wq_hi(rows 0..1023)^T -> g_qk (fp16)
    mma_gemm<3><<<dim3(QKS / 64, LL / 128, BB), 256, GEMM_SMEM>>>(
        xt_h, xt_l, (size_t)LL * CC, wq_h, 0,
        qk, nullptr, nullptr, (size_t)LL * QKS, QKS, CC, CC / 64);

    // L2: C[v_ch][l] = (wq_hi+wq_lo)(rows 1024..1535) * xT_hi^T -> g_v (fp16)
    mma_gemm<3><<<dim3(LL / 64, HID / 128, BB), 256, GEMM_SMEM>>>(
        wq_h + 1024 * CC, wq_l + 1024 * CC, 0, xt_h, (size_t)LL * CC,
        v, nullptr, nullptr, (size_t)HID * LL, LL, CC, CC / 64);

    attn_kernel<<<dim3(LL / 128, BB * HH), 256, ATTN_SMEM>>>();

    // L3: out[ch][l] = (wo_hi+wo_lo) * att^T + bias (fp32 out)
    mma_gemm<1><<<dim3(LL / 64, CC / 128, BB), 256, GEMM_SMEM>>>(
        wo_h, wo_l, 0, att, (size_t)LL * HID,
        nullptr, out, b_out, (size_t)CC * LL, LL, HID, HID / 64);
}